// round 2
// baseline (speedup 1.0000x reference)
#include <cuda_runtime.h>
#include <math.h>

// Problem constants
#define BB 4
#define TT 1024
#define CC 1024
#define NH 16
#define HD 64
#define KKEEP 391
#define REC 64
#define NONREC (TT - REC)       // 960
// kept set = {960..1023} UNION top-327 of scores over t in [0,960)

// ---------------- scratch (device globals; no allocation allowed) ----------
__device__ float g_qkv[BB * TT * 3 * CC];   // 50.3 MB
__device__ float g_y[BB * TT * CC];         // 16.8 MB
__device__ float g_last[BB * NH * TT];
__device__ int   g_idx[BB * NH * KKEEP];

// ---------------- generic tiled SGEMM: C[M,N] = A[M,K] * B[K,N] ------------
// Row-major. Requires M%128==0, N%128==0, K%16==0 (true for both GEMMs here).
#define GBM 128
#define GBN 128
#define GBK 16
#define GTM 8
#define GTN 8

__global__ __launch_bounds__(256) void sgemm128(
    const float* __restrict__ A, const float* __restrict__ B,
    float* __restrict__ C, int M, int N, int K)
{
    __shared__ float As[GBK][GBM];
    __shared__ float Bs[GBK][GBN];

    const int tid = threadIdx.x;
    const int tx = tid % (GBN / GTN);   // 0..15
    const int ty = tid / (GBN / GTN);   // 0..15
    const int bx = blockIdx.x;          // N tile
    const int by = blockIdx.y;          // M tile

    const float* Ab = A + (size_t)by * GBM * K;
    const float* Bb = B + (size_t)bx * GBN;

    float acc[GTM][GTN];
    #pragma unroll
    for (int i = 0; i < GTM; i++)
        #pragma unroll
        for (int j = 0; j < GTN; j++) acc[i][j] = 0.f;

    for (int k0 = 0; k0 < K; k0 += GBK) {
        // Load A tile 128x16 (512 float4 -> 2 per thread), store transposed
        #pragma unroll
        for (int i = 0; i < 2; i++) {
            int idx = tid + i * 256;
            int r  = idx >> 2;          // 0..127
            int c4 = (idx & 3) * 4;     // 0,4,8,12
            float4 v = *(const float4*)(Ab + (size_t)r * K + k0 + c4);
            As[c4 + 0][r] = v.x; As[c4 + 1][r] = v.y;
            As[c4 + 2][r] = v.z; As[c4 + 3][r] = v.w;
        }
        // Load B tile 16x128 (512 float4 -> 2 per thread)
        #pragma unroll
        for (int i = 0; i < 2; i++) {
            int idx = tid + i * 256;
            int r  = idx >> 5;          // 0..15
            int c4 = (idx & 31) * 4;    // 0..124
            float4 v = *(const float4*)(Bb + (size_t)(k0 + r) * N + c4);
            *(float4*)&Bs[r][c4] = v;
        }
        __syncthreads();

        #pragma unroll
        for (int k = 0; k < GBK; k++) {
            float a[GTM], b[GTN];
            float4 a0 = *(float4*)&As[k][ty * GTM];
            float4 a1 = *(float4*)&As[k][ty * GTM + 4];
            a[0]=a0.x; a[1]=a0.y; a[2]=a0.z; a[3]=a0.w;
            a[4]=a1.x; a[5]=a1.y; a[6]=a1.z; a[7]=a1.w;
            float4 b0 = *(float4*)&Bs[k][tx * GTN];
            float4 b1 = *(float4*)&Bs[k][tx * GTN + 4];
            b[0]=b0.x; b[1]=b0.y; b[2]=b0.z; b[3]=b0.w;
            b[4]=b1.x; b[5]=b1.y; b[6]=b1.z; b[7]=b1.w;
            #pragma unroll
            for (int i = 0; i < GTM; i++)
                #pragma unroll
                for (int j = 0; j < GTN; j++)
                    acc[i][j] += a[i] * b[j];
        }
        __syncthreads();
    }

    float* Cb = C + (size_t)by * GBM * N + (size_t)bx * GBN;
    #pragma unroll
    for (int i = 0; i < GTM; i++) {
        #pragma unroll
        for (int j = 0; j < GTN; j += 4) {
            float4 v = make_float4(acc[i][j], acc[i][j+1], acc[i][j+2], acc[i][j+3]);
            *(float4*)(Cb + (size_t)(ty * GTM + i) * N + tx * GTN + j) = v;
        }
    }
}

// ---------------- last-row scores: last[b,h,t] = q[b,T-1,h,:]·k[b,t,h,:]/8 --
__global__ void last_scores_kernel(const float* __restrict__ qkv,
                                   float* __restrict__ last)
{
    int bh = blockIdx.x;            // 0..63
    int b = bh >> 4, h = bh & 15;
    __shared__ float qv[HD];
    const float* qrow = qkv + ((size_t)b * TT + (TT - 1)) * (3 * CC) + h * HD;
    if (threadIdx.x < HD) qv[threadIdx.x] = qrow[threadIdx.x];
    __syncthreads();
    for (int t = threadIdx.x; t < TT; t += blockDim.x) {
        const float* krow = qkv + ((size_t)b * TT + t) * (3 * CC) + CC + h * HD;
        float s = 0.f;
        #pragma unroll
        for (int d = 0; d < HD; d++) s += qv[d] * krow[d];
        last[bh * TT + t] = s * 0.125f;
    }
}

// ---------------- top-k set selection via bitonic sort ---------------------
// Recent positions (t>=960) keyed +inf -> always selected; set semantics make
// ordering irrelevant, so this matches the reference's recency+topk exactly.
__global__ __launch_bounds__(512) void topk_kernel(const float* __restrict__ last,
                                                   int* __restrict__ idxout)
{
    __shared__ unsigned long long s[TT];
    const int bh = blockIdx.x;
    const int tid = threadIdx.x;   // 512 threads

    for (int t = tid; t < TT; t += 512) {
        unsigned u;
        if (t >= NONREC) {
            u = 0xFFFFFFFFu;       // +inf key
        } else {
            u = __float_as_uint(last[bh * TT + t]);
            u = (u & 0x80000000u) ? ~u : (u | 0x80000000u);  // order-preserving flip
        }
        s[t] = ((unsigned long long)u << 32) | (unsigned)t;
    }
    __syncthreads();

    // bitonic sort, descending
    for (int k = 2; k <= TT; k <<= 1) {
        for (int j = k >> 1; j > 0; j >>= 1) {
            for (int i = tid; i < TT; i += 512) {
                int ix = i ^ j;
                if (ix > i) {
                    bool desc = ((i & k) == 0);
                    unsigned long long a = s[i], b = s[ix];
                    bool sw = desc ? (a < b) : (a > b);
                    if (sw) { s[i] = b; s[ix] = a; }
                }
            }
            __syncthreads();
        }
    }
    for (int i = tid; i < KKEEP; i += 512)
        idxout[bh * KKEEP + i] = (int)(s[i] & 0xFFFFFFFFu);
}

// ---------------- pruned attention ----------------------------------------
// One thread = one query row. K/V chunks of 64 keys staged in smem (gathered
// via idx). No max-subtraction: |score| < ~3 so exp is safe in fp32.
#define KCHUNK 64

__global__ __launch_bounds__(128) void attn_kernel(
    const float* __restrict__ qkv, const int* __restrict__ idx,
    float* __restrict__ y)
{
    const int bh = blockIdx.x;
    const int b = bh >> 4, h = bh & 15;
    const int qt = blockIdx.y * 128 + threadIdx.x;

    __shared__ float Ks[KCHUNK][HD];
    __shared__ float Vs[KCHUNK][HD];

    float q[HD];
    const float* qrow = qkv + ((size_t)b * TT + qt) * (3 * CC) + h * HD;
    #pragma unroll
    for (int d = 0; d < HD; d++) q[d] = qrow[d] * 0.125f;

    float l = 0.f;
    float acc[HD];
    #pragma unroll
    for (int d = 0; d < HD; d++) acc[d] = 0.f;

    for (int c0 = 0; c0 < KKEEP; c0 += KCHUNK) {
        const int cn = min(KCHUNK, KKEEP - c0);
        __syncthreads();
        // gather K and V rows for this chunk
        for (int i = threadIdx.x; i < cn * (HD / 4); i += 128) {
            int r = i >> 4;                  // key within chunk
            int c4 = (i & 15) * 4;           // float4 offset in head dim
            int kt = idx[bh * KKEEP + c0 + r];
            const float* kr = qkv + ((size_t)b * TT + kt) * (3 * CC) + CC + h * HD;
            *(float4*)&Ks[r][c4] = *(const float4*)(kr + c4);
            *(float4*)&Vs[r][c4] = *(const float4*)(kr + CC + c4);
        }
        __syncthreads();

        for (int kk = 0; kk < cn; kk++) {
            float sc = 0.f;
            #pragma unroll
            for (int d = 0; d < HD; d++) sc += q[d] * Ks[kk][d];
            float p = __expf(sc);
            l += p;
            #pragma unroll
            for (int d = 0; d < HD; d++) acc[d] += p * Vs[kk][d];
        }
    }

    float invl = 1.f / l;
    float* yrow = y + ((size_t)b * TT + qt) * CC + h * HD;
    #pragma unroll
    for (int d = 0; d < HD; d++) yrow[d] = acc[d] * invl;
}

// ---------------- launch ----------------------------------------------------
extern "C" void kernel_launch(void* const* d_in, const int* in_sizes, int n_in,
                              void* d_out, int out_size)
{
    const float* x  = (const float*)d_in[0];   // [4,1024,1024]
    const float* Wa = (const float*)d_in[1];   // [1024,3072]
    const float* Wp = (const float*)d_in[2];   // [1024,1024]
    float* out = (float*)d_out;                // [4,1024,1024]

    void* p;
    cudaGetSymbolAddress(&p, g_qkv);  float* qkv  = (float*)p;
    cudaGetSymbolAddress(&p, g_y);    float* y    = (float*)p;
    cudaGetSymbolAddress(&p, g_last); float* last = (float*)p;
    cudaGetSymbolAddress(&p, g_idx);  int*   idx  = (int*)p;

    // 1) qkv = x @ W_attn   [4096,1024]x[1024,3072]
    sgemm128<<<dim3(3 * CC / GBN, BB * TT / GBM), 256>>>(x, Wa, qkv, BB * TT, 3 * CC, CC);

    // 2) last-row scores
    last_scores_kernel<<<BB * NH, 256>>>(qkv, last);

    // 3) kept-index set per (b,h)
    topk_kernel<<<BB * NH, 512>>>(last, idx);

    // 4) pruned attention -> y [B,T,C]
    attn_kernel<<<dim3(BB * NH, TT / 128), 128>>>(qkv, idx, y);

    // 5) out = y @ W_proj   [4096,1024]x[1024,1024]
    sgemm128<<<dim3(CC / GBN, BB * TT / GBM), 256>>>(y, Wp, out, BB * TT, CC, CC);
}

// round 5
// speedup vs baseline: 1.0516x; 1.0516x over previous
#include <cuda_runtime.h>
#include <cuda_bf16.h>
#include <math.h>
#include <stdint.h>

// Problem constants
#define BB 4
#define TT 1024
#define CC 1024
#define NH 16
#define HD 64
#define KKEEP 391
#define REC 64
#define NONREC (TT - REC)       // 960

// ---------------- scratch (device globals; no allocation allowed) ----------
__device__ float g_qkv[BB * TT * 3 * CC];            // 50.3 MB fp32
__device__ float g_y[BB * TT * CC];                  // 16.8 MB fp32
__device__ float g_last[BB * NH * TT];
__device__ int   g_idx[BB * NH * KKEEP];
__device__ float g_qlast[BB * CC];                   // q[b, T-1, :] fp32
__device__ float g_u[BB * CC * NH];                  // u[b][c][h] fp32
__device__ __nv_bfloat16 g_xh[BB * TT * CC];         // x hi/lo
__device__ __nv_bfloat16 g_xl[BB * TT * CC];
__device__ __nv_bfloat16 g_wah[3 * CC * CC];         // W_attn^T hi/lo [3072][1024]
__device__ __nv_bfloat16 g_wal[3 * CC * CC];
__device__ __nv_bfloat16 g_wph[CC * CC];             // W_proj^T hi/lo [1024][1024]
__device__ __nv_bfloat16 g_wpl[CC * CC];
__device__ __nv_bfloat16 g_yh[BB * TT * CC];         // y hi/lo
__device__ __nv_bfloat16 g_yl[BB * TT * CC];

// ---------------- helpers ---------------------------------------------------
__device__ __forceinline__ uint32_t smem_u32(const void* p) {
    uint32_t a;
    asm("{ .reg .u64 t; cvta.to.shared.u64 t, %1; cvt.u32.u64 %0, t; }" : "=r"(a) : "l"(p));
    return a;
}
__device__ __forceinline__ void ldm_x4(uint32_t& r0, uint32_t& r1, uint32_t& r2, uint32_t& r3, uint32_t addr) {
    asm volatile("ldmatrix.sync.aligned.m8n8.x4.shared.b16 {%0,%1,%2,%3}, [%4];"
                 : "=r"(r0), "=r"(r1), "=r"(r2), "=r"(r3) : "r"(addr));
}
__device__ __forceinline__ void ldm_x2(uint32_t& r0, uint32_t& r1, uint32_t addr) {
    asm volatile("ldmatrix.sync.aligned.m8n8.x2.shared.b16 {%0,%1}, [%2];"
                 : "=r"(r0), "=r"(r1) : "r"(addr));
}
__device__ __forceinline__ void mma16816(float* d, const uint32_t* a, const uint32_t* b) {
    asm volatile(
        "mma.sync.aligned.m16n8k16.row.col.f32.bf16.bf16.f32 "
        "{%0,%1,%2,%3},{%4,%5,%6,%7},{%8,%9},{%0,%1,%2,%3};"
        : "+f"(d[0]), "+f"(d[1]), "+f"(d[2]), "+f"(d[3])
        : "r"(a[0]), "r"(a[1]), "r"(a[2]), "r"(a[3]), "r"(b[0]), "r"(b[1]));
}
__device__ __forceinline__ void split_bf16(float a, __nv_bfloat16& h, __nv_bfloat16& l) {
    h = __float2bfloat16(a);
    l = __float2bfloat16(a - __bfloat162float(h));
}

// ---------------- prep: fp32 -> (hi, lo) bf16 -------------------------------
__global__ __launch_bounds__(256) void split_kernel(
    const float* __restrict__ in, __nv_bfloat16* __restrict__ hi,
    __nv_bfloat16* __restrict__ lo, int n4)
{
    int i = blockIdx.x * 256 + threadIdx.x;
    if (i >= n4) return;
    float4 v = ((const float4*)in)[i];
    __nv_bfloat16 h0, h1, h2, h3, l0, l1, l2, l3;
    split_bf16(v.x, h0, l0); split_bf16(v.y, h1, l1);
    split_bf16(v.z, h2, l2); split_bf16(v.w, h3, l3);
    ((__nv_bfloat162*)hi)[i * 2 + 0] = __nv_bfloat162(h0, h1);
    ((__nv_bfloat162*)hi)[i * 2 + 1] = __nv_bfloat162(h2, h3);
    ((__nv_bfloat162*)lo)[i * 2 + 0] = __nv_bfloat162(l0, l1);
    ((__nv_bfloat162*)lo)[i * 2 + 1] = __nv_bfloat162(l2, l3);
}

// ---------------- prep: transpose fp32 [rows][cols] -> bf16 hi/lo [cols][rows]
__global__ __launch_bounds__(256) void transpose_split_kernel(
    const float* __restrict__ in, __nv_bfloat16* __restrict__ outh,
    __nv_bfloat16* __restrict__ outl, int rows, int cols)
{
    __shared__ float t[32][33];
    int bx = blockIdx.x * 32, by = blockIdx.y * 32;
    int x = bx + threadIdx.x;
    #pragma unroll
    for (int j = threadIdx.y; j < 32; j += 8)
        t[j][threadIdx.x] = in[(size_t)(by + j) * cols + x];
    __syncthreads();
    int xo = by + threadIdx.x;
    #pragma unroll
    for (int j = threadIdx.y; j < 32; j += 8) {
        float v = t[threadIdx.x][j];
        __nv_bfloat16 h, l;
        split_bf16(v, h, l);
        outh[(size_t)(bx + j) * rows + xo] = h;
        outl[(size_t)(bx + j) * rows + xo] = l;
    }
}

// ---------------- mma.sync bf16 3-term GEMM ---------------------------------
// C[M,N] = (Ah+Al)[M,K] * (Bh+Bl)[N,K]^T  (dropping Al*Bl)
// CTA 128x128, 8 warps (2m x 4n), warp tile 64x32, BK=32.
#define GK 1024
#define BKC 32
#define PADR 40                    // padded row: 40 bf16 = 80 bytes

__global__ __launch_bounds__(256, 1) void gemm_bf16x3(
    const __nv_bfloat16* __restrict__ Ah, const __nv_bfloat16* __restrict__ Al,
    const __nv_bfloat16* __restrict__ Bh, const __nv_bfloat16* __restrict__ Bl,
    float* __restrict__ C, int N)
{
    __shared__ __nv_bfloat16 sAh[128][PADR];
    __shared__ __nv_bfloat16 sAl[128][PADR];
    __shared__ __nv_bfloat16 sBh[128][PADR];
    __shared__ __nv_bfloat16 sBl[128][PADR];

    const int tid = threadIdx.x;
    const int wid = tid >> 5;
    const int lane = tid & 31;
    const int wm = wid >> 2;        // 0..1  (m)
    const int wn = wid & 3;         // 0..3  (n)

    const int m0 = blockIdx.y * 128;
    const int n0 = blockIdx.x * 128;

    const __nv_bfloat16* Ahb = Ah + (size_t)m0 * GK;
    const __nv_bfloat16* Alb = Al + (size_t)m0 * GK;
    const __nv_bfloat16* Bhb = Bh + (size_t)n0 * GK;
    const __nv_bfloat16* Blb = Bl + (size_t)n0 * GK;

    float acc[4][4][4];
    #pragma unroll
    for (int i = 0; i < 4; i++)
        #pragma unroll
        for (int j = 0; j < 4; j++)
            #pragma unroll
            for (int r = 0; r < 4; r++) acc[i][j][r] = 0.f;

    const uint32_t uAh = smem_u32(&sAh[0][0]);
    const uint32_t uAl = smem_u32(&sAl[0][0]);
    const uint32_t uBh = smem_u32(&sBh[0][0]);
    const uint32_t uBl = smem_u32(&sBl[0][0]);
    const uint32_t aoff = (uint32_t)((wm * 64 + (lane & 15)) * (PADR * 2) + ((lane >> 4) << 4));
    const uint32_t boff = (uint32_t)((wn * 32 + (lane & 7)) * (PADR * 2) + (((lane >> 3) & 1) << 4));

    for (int k0 = 0; k0 < GK; k0 += BKC) {
        #pragma unroll
        for (int it = 0; it < 2; it++) {
            int i = tid + it * 256;
            int r = i >> 2, c = i & 3;            // c: 16B chunk (8 bf16)
            size_t go = (size_t)r * GK + k0 + c * 8;
            *(uint4*)((char*)&sAh[r][0] + c * 16) = *(const uint4*)(Ahb + go);
            *(uint4*)((char*)&sAl[r][0] + c * 16) = *(const uint4*)(Alb + go);
            *(uint4*)((char*)&sBh[r][0] + c * 16) = *(const uint4*)(Bhb + go);
            *(uint4*)((char*)&sBl[r][0] + c * 16) = *(const uint4*)(Blb + go);
        }
        __syncthreads();

        #pragma unroll
        for (int ks = 0; ks < 2; ks++) {
            const uint32_t ksb = ks * 32;          // 16 bf16 = 32 bytes
            uint32_t ah[4][4], al[4][4], bh[4][2], bl[4][2];
            #pragma unroll
            for (int mt = 0; mt < 4; mt++) {
                uint32_t off = aoff + mt * 16 * (PADR * 2) + ksb;
                ldm_x4(ah[mt][0], ah[mt][1], ah[mt][2], ah[mt][3], uAh + off);
                ldm_x4(al[mt][0], al[mt][1], al[mt][2], al[mt][3], uAl + off);
            }
            #pragma unroll
            for (int nt = 0; nt < 4; nt++) {
                uint32_t off = boff + nt * 8 * (PADR * 2) + ksb;
                ldm_x2(bh[nt][0], bh[nt][1], uBh + off);
                ldm_x2(bl[nt][0], bl[nt][1], uBl + off);
            }
            #pragma unroll
            for (int mt = 0; mt < 4; mt++)
                #pragma unroll
                for (int nt = 0; nt < 4; nt++) {
                    mma16816(acc[mt][nt], ah[mt], bh[nt]);
                    mma16816(acc[mt][nt], ah[mt], bl[nt]);
                    mma16816(acc[mt][nt], al[mt], bh[nt]);
                }
        }
        __syncthreads();
    }

    const int mrow = m0 + wm * 64 + (lane >> 2);
    const int ncol = n0 + wn * 32 + (lane & 3) * 2;
    #pragma unroll
    for (int mt = 0; mt < 4; mt++)
        #pragma unroll
        for (int nt = 0; nt < 4; nt++) {
            float* c0 = C + (size_t)(mrow + mt * 16) * N + ncol + nt * 8;
            *(float2*)c0 = make_float2(acc[mt][nt][0], acc[mt][nt][1]);
            float* c1 = c0 + (size_t)8 * N;
            *(float2*)c1 = make_float2(acc[mt][nt][2], acc[mt][nt][3]);
        }
}

// ---------------- fp32 selection-score path ---------------------------------
// q_last[b][h*64+d] = sum_c x[b,T-1,c] * Wa[c][h*64+d]
__global__ __launch_bounds__(64) void qlast_kernel(
    const float* __restrict__ x, const float* __restrict__ Wa,
    float* __restrict__ qlast)
{
    const int b = blockIdx.x >> 4, h = blockIdx.x & 15;
    __shared__ float xs[CC];
    for (int c = threadIdx.x; c < CC; c += 64)
        xs[c] = x[((size_t)b * TT + (TT - 1)) * CC + c];
    __syncthreads();
    const int col = h * HD + threadIdx.x;
    float s = 0.f;
    for (int c = 0; c < CC; c++) s += xs[c] * Wa[(size_t)c * (3 * CC) + col];
    qlast[(b * NH + h) * HD + threadIdx.x] = s;
}

// u[b][c][h] = sum_d Wa[c][CC + h*64+d] * qlast[b][h*64+d]
__global__ __launch_bounds__(256) void uproj_kernel(
    const float* __restrict__ Wa, const float* __restrict__ qlast,
    float* __restrict__ u)
{
    const int b = blockIdx.x;
    const int c = blockIdx.y * 16 + (threadIdx.x >> 4);
    const int h = threadIdx.x & 15;
    __shared__ float qs[CC];
    for (int i = threadIdx.x; i < CC; i += 256) qs[i] = qlast[b * CC + i];
    __syncthreads();
    const float* wrow = Wa + (size_t)c * (3 * CC) + CC + h * HD;
    const float* qh = qs + h * HD;
    float s = 0.f;
    #pragma unroll
    for (int d = 0; d < HD; d++) s += wrow[d] * qh[d];
    u[((size_t)b * CC + c) * NH + h] = s;
}

// last[b,h,t] = 0.125 * sum_c x[b,t,c] * u[b][c][h]
__global__ __launch_bounds__(256) void scores_kernel(
    const float* __restrict__ x, const float* __restrict__ u,
    float* __restrict__ last)
{
    const int b = blockIdx.x;
    const int t = blockIdx.y * 256 + threadIdx.x;
    __shared__ float us[128][NH];
    float acc[NH];
    #pragma unroll
    for (int h = 0; h < NH; h++) acc[h] = 0.f;
    const float* xr = x + ((size_t)b * TT + t) * CC;
    for (int c0 = 0; c0 < CC; c0 += 128) {
        __syncthreads();
        for (int i = threadIdx.x; i < 128 * NH; i += 256)
            ((float*)us)[i] = u[((size_t)b * CC + c0) * NH + i];
        __syncthreads();
        for (int ci = 0; ci < 128; ci++) {
            float xv = xr[c0 + ci];
            #pragma unroll
            for (int h = 0; h < NH; h++) acc[h] += xv * us[ci][h];
        }
    }
    #pragma unroll
    for (int h = 0; h < NH; h++)
        last[(b * NH + h) * TT + t] = acc[h] * 0.125f;
}

// ---------------- top-k set selection via bitonic sort ---------------------
__global__ __launch_bounds__(512) void topk_kernel(const float* __restrict__ last,
                                                   int* __restrict__ idxout)
{
    __shared__ unsigned long long s[TT];
    const int bh = blockIdx.x;
    const int tid = threadIdx.x;

    for (int t = tid; t < TT; t += 512) {
        unsigned u;
        if (t >= NONREC) {
            u = 0xFFFFFFFFu;
        } else {
            u = __float_as_uint(last[bh * TT + t]);
            u = (u & 0x80000000u) ? ~u : (u | 0x80000000u);
        }
        s[t] = ((unsigned long long)u << 32) | (unsigned)t;
    }
    __syncthreads();

    for (int k = 2; k <= TT; k <<= 1) {
        for (int j = k >> 1; j > 0; j >>= 1) {
            for (int i = tid; i < TT; i += 512) {
                int ix = i ^ j;
                if (ix > i) {
                    bool desc = ((i & k) == 0);
                    unsigned long long a = s[i], b = s[ix];
                    bool sw = desc ? (a < b) : (a > b);
                    if (sw) { s[i] = b; s[ix] = a; }
                }
            }
            __syncthreads();
        }
    }
    for (int i = tid; i < KKEEP; i += 512)
        idxout[bh * KKEEP + i] = (int)(s[i] & 0xFFFFFFFFu);
}

// ---------------- pruned attention (float4 smem reads) ----------------------
#define KCHUNK 64

__global__ __launch_bounds__(128) void attn_kernel(
    const float* __restrict__ qkv, const int* __restrict__ idx,
    float* __restrict__ y)
{
    const int bh = blockIdx.x;
    const int b = bh >> 4, h = bh & 15;
    const int qt = blockIdx.y * 128 + threadIdx.x;

    __shared__ float Ks[KCHUNK][HD];
    __shared__ float Vs[KCHUNK][HD];

    float4 q4[HD / 4];
    {
        const float4* qrow = (const float4*)(qkv + ((size_t)b * TT + qt) * (3 * CC) + h * HD);
        #pragma unroll
        for (int d = 0; d < HD / 4; d++) {
            float4 v = qrow[d];
            q4[d] = make_float4(v.x * 0.125f, v.y * 0.125f, v.z * 0.125f, v.w * 0.125f);
        }
    }

    float l = 0.f;
    float4 a4[HD / 4];
    #pragma unroll
    for (int d = 0; d < HD / 4; d++) a4[d] = make_float4(0.f, 0.f, 0.f, 0.f);

    for (int c0 = 0; c0 < KKEEP; c0 += KCHUNK) {
        const int cn = min(KCHUNK, KKEEP - c0);
        __syncthreads();
        for (int i = threadIdx.x; i < cn * (HD / 4); i += 128) {
            int r = i >> 4;
            int c4 = (i & 15) * 4;
            int kt = idx[bh * KKEEP + c0 + r];
            const float* kr = qkv + ((size_t)b * TT + kt) * (3 * CC) + CC + h * HD;
            *(float4*)&Ks[r][c4] = *(const float4*)(kr + c4);
            *(float4*)&Vs[r][c4] = *(const float4*)(kr + CC + c4);
        }
        __syncthreads();

        for (int kk = 0; kk < cn; kk++) {
            const float4* kr = (const float4*)&Ks[kk][0];
            float sc = 0.f;
            #pragma unroll
            for (int d = 0; d < HD / 4; d++) {
                float4 kv = kr[d];
                sc += q4[d].x * kv.x + q4[d].y * kv.y + q4[d].z * kv.z + q4[d].w * kv.w;
            }
            float p = __expf(sc);
            l += p;
            const float4* vr = (const float4*)&Vs[kk][0];
            #pragma unroll
            for (int d = 0; d < HD / 4; d++) {
                float4 vv = vr[d];
                a4[d].x += p * vv.x; a4[d].y += p * vv.y;
                a4[d].z += p * vv.z; a4[d].w += p * vv.w;
            }
        }
    }

    float invl = 1.f / l;
    float4* yrow = (float4*)(y + ((size_t)b * TT + qt) * CC + h * HD);
    #pragma unroll
    for (int d = 0; d < HD / 4; d++)
        yrow[d] = make_float4(a4[d].x * invl, a4[d].y * invl, a4[d].z * invl, a4[d].w * invl);
}

// ---------------- launch ----------------------------------------------------
extern "C" void kernel_launch(void* const* d_in, const int* in_sizes, int n_in,
                              void* d_out, int out_size)
{
    const float* x  = (const float*)d_in[0];   // [4,1024,1024]
    const float* Wa = (const float*)d_in[1];   // [1024,3072]
    const float* Wp = (const float*)d_in[2];   // [1024,1024]
    float* out = (float*)d_out;                // [4,1024,1024]

    void* p;
    cudaGetSymbolAddress(&p, g_qkv);   float* qkv   = (float*)p;
    cudaGetSymbolAddress(&p, g_y);     float* y     = (float*)p;
    cudaGetSymbolAddress(&p, g_last);  float* last  = (float*)p;
    cudaGetSymbolAddress(&p, g_idx);   int*   idx   = (int*)p;
    cudaGetSymbolAddress(&p, g_qlast); float* qlast = (float*)p;
    cudaGetSymbolAddress(&p, g_u);     float* u     = (float*)p;
    cudaGetSymbolAddress(&p, g_xh);   __nv_bfloat16* xh  = (__nv_bfloat16*)p;
    cudaGetSymbolAddress(&p, g_xl);   __nv_bfloat16* xl  = (__nv_bfloat16*)p;
    cudaGetSymbolAddress(&p, g_wah);  __nv_bfloat16* wah = (__nv_bfloat16*)p;
    cudaGetSymbolAddress(&p, g_wal);  __nv_bfloat16* wal = (__nv_bfloat16*)p;
    cudaGetSymbolAddress(&p, g_wph);  __nv_bfloat16* wph = (__nv_bfloat16*)p;
    cudaGetSymbolAddress(&p, g_wpl);  __nv_bfloat16* wpl = (__nv_bfloat16*)p;
    cudaGetSymbolAddress(&p, g_yh);   __nv_bfloat16* yh  = (__nv_bfloat16*)p;
    cudaGetSymbolAddress(&p, g_yl);   __nv_bfloat16* yl  = (__nv_bfloat16*)p;

    // 0) fp32 selection scores (independent of bf16 GEMM precision)
    qlast_kernel<<<BB * NH, 64>>>(x, Wa, qlast);
    uproj_kernel<<<dim3(BB, CC / 16), 256>>>(Wa, qlast, u);
    scores_kernel<<<dim3(BB, TT / 256), 256>>>(x, u, last);
    topk_kernel<<<BB * NH, 512>>>(last, idx);

    // 1) prep: split x; transpose+split weights
    split_kernel<<<(BB * TT * CC / 4 + 255) / 256, 256>>>(x, xh, xl, BB * TT * CC / 4);
    transpose_split_kernel<<<dim3(3 * CC / 32, CC / 32), dim3(32, 8)>>>(Wa, wah, wal, CC, 3 * CC);
    transpose_split_kernel<<<dim3(CC / 32, CC / 32), dim3(32, 8)>>>(Wp, wph, wpl, CC, CC);

    // 2) qkv = x @ W_attn   (mma.sync bf16 3-term)
    gemm_bf16x3<<<dim3(3 * CC / 128, BB * TT / 128), 256>>>(xh, xl, wah, wal, qkv, 3 * CC);

    // 3) pruned attention -> y
    attn_kernel<<<dim3(BB * NH, TT / 128), 128>>>(qkv, idx, y);

    // 4) split y; out = y @ W_proj
    split_kernel<<<(BB * TT * CC / 4 + 255) / 256, 256>>>(y, yh, yl, BB * TT * CC / 4);
    gemm_bf16x3<<<dim3(CC / 128, BB * TT / 128), 256>>>(yh, yl, wph, wpl, out, CC);
}

// round 6
// speedup vs baseline: 1.1618x; 1.1048x over previous
#include <cuda_runtime.h>
#include <cuda_bf16.h>
#include <math.h>
#include <stdint.h>

// Problem constants
#define BB 4
#define TT 1024
#define CC 1024
#define NH 16
#define HD 64
#define KKEEP 391
#define REC 64
#define NONREC (TT - REC)       // 960

// ---------------- scratch (device globals; no allocation allowed) ----------
__device__ float g_qkv[BB * TT * 3 * CC];            // 50.3 MB fp32
__device__ float g_last[BB * NH * TT];
__device__ int   g_idx[BB * NH * KKEEP];
__device__ float g_qlast[BB * CC];
__device__ float g_u[BB * CC * NH];
__device__ __nv_bfloat16 g_xh[BB * TT * CC];
__device__ __nv_bfloat16 g_xl[BB * TT * CC];
__device__ __nv_bfloat16 g_wah[3 * CC * CC];         // W_attn^T hi/lo [3072][1024]
__device__ __nv_bfloat16 g_wal[3 * CC * CC];
__device__ __nv_bfloat16 g_wph[CC * CC];             // W_proj^T hi/lo
__device__ __nv_bfloat16 g_wpl[CC * CC];
__device__ __nv_bfloat16 g_yh[BB * TT * CC];
__device__ __nv_bfloat16 g_yl[BB * TT * CC];

// ---------------- helpers ---------------------------------------------------
__device__ __forceinline__ uint32_t smem_u32(const void* p) {
    uint32_t a;
    asm("{ .reg .u64 t; cvta.to.shared.u64 t, %1; cvt.u32.u64 %0, t; }" : "=r"(a) : "l"(p));
    return a;
}
__device__ __forceinline__ void cp_async16(uint32_t dst, const void* src) {
    asm volatile("cp.async.cg.shared.global [%0], [%1], 16;" :: "r"(dst), "l"(src));
}
__device__ __forceinline__ void cp_commit() {
    asm volatile("cp.async.commit_group;");
}
__device__ __forceinline__ void ldm_x4(uint32_t& r0, uint32_t& r1, uint32_t& r2, uint32_t& r3, uint32_t addr) {
    asm volatile("ldmatrix.sync.aligned.m8n8.x4.shared.b16 {%0,%1,%2,%3}, [%4];"
                 : "=r"(r0), "=r"(r1), "=r"(r2), "=r"(r3) : "r"(addr));
}
__device__ __forceinline__ void ldm_x2(uint32_t& r0, uint32_t& r1, uint32_t addr) {
    asm volatile("ldmatrix.sync.aligned.m8n8.x2.shared.b16 {%0,%1}, [%2];"
                 : "=r"(r0), "=r"(r1) : "r"(addr));
}
__device__ __forceinline__ void mma16816(float* d, const uint32_t* a, const uint32_t* b) {
    asm volatile(
        "mma.sync.aligned.m16n8k16.row.col.f32.bf16.bf16.f32 "
        "{%0,%1,%2,%3},{%4,%5,%6,%7},{%8,%9},{%0,%1,%2,%3};"
        : "+f"(d[0]), "+f"(d[1]), "+f"(d[2]), "+f"(d[3])
        : "r"(a[0]), "r"(a[1]), "r"(a[2]), "r"(a[3]), "r"(b[0]), "r"(b[1]));
}
__device__ __forceinline__ void split_bf16(float a, __nv_bfloat16& h, __nv_bfloat16& l) {
    h = __float2bfloat16(a);
    l = __float2bfloat16(a - __bfloat162float(h));
}

// ---------------- prep: fp32 -> (hi, lo) bf16 -------------------------------
__global__ __launch_bounds__(256) void split_kernel(
    const float* __restrict__ in, __nv_bfloat16* __restrict__ hi,
    __nv_bfloat16* __restrict__ lo, int n4)
{
    int i = blockIdx.x * 256 + threadIdx.x;
    if (i >= n4) return;
    float4 v = ((const float4*)in)[i];
    __nv_bfloat16 h0, h1, h2, h3, l0, l1, l2, l3;
    split_bf16(v.x, h0, l0); split_bf16(v.y, h1, l1);
    split_bf16(v.z, h2, l2); split_bf16(v.w, h3, l3);
    ((__nv_bfloat162*)hi)[i * 2 + 0] = __nv_bfloat162(h0, h1);
    ((__nv_bfloat162*)hi)[i * 2 + 1] = __nv_bfloat162(h2, h3);
    ((__nv_bfloat162*)lo)[i * 2 + 0] = __nv_bfloat162(l0, l1);
    ((__nv_bfloat162*)lo)[i * 2 + 1] = __nv_bfloat162(l2, l3);
}

// ---------------- prep: transpose fp32 [rows][cols] -> bf16 hi/lo [cols][rows]
__global__ __launch_bounds__(256) void transpose_split_kernel(
    const float* __restrict__ in, __nv_bfloat16* __restrict__ outh,
    __nv_bfloat16* __restrict__ outl, int rows, int cols)
{
    __shared__ float t[32][33];
    int bx = blockIdx.x * 32, by = blockIdx.y * 32;
    int x = bx + threadIdx.x;
    #pragma unroll
    for (int j = threadIdx.y; j < 32; j += 8)
        t[j][threadIdx.x] = in[(size_t)(by + j) * cols + x];
    __syncthreads();
    int xo = by + threadIdx.x;
    #pragma unroll
    for (int j = threadIdx.y; j < 32; j += 8) {
        float v = t[threadIdx.x][j];
        __nv_bfloat16 h, l;
        split_bf16(v, h, l);
        outh[(size_t)(bx + j) * rows + xo] = h;
        outl[(size_t)(bx + j) * rows + xo] = l;
    }
}

// ---------------- mma.sync bf16 3-term GEMM, cp.async double-buffered -------
// C[M,N] = (Ah+Al)[M,K]*(Bh+Bl)[N,K]^T, dropping Al*Bl.
// CTA 128x128, 8 warps (2m x 4n), warp tile 64x32, BK=32, 2-stage cp.async.
#define GK 1024
#define BKC 32
#define PADR 40                      // padded row: 40 bf16 = 80 bytes
#define ARR_SZ (128 * PADR * 2)      // 10240 bytes per array
#define STAGE_SZ (4 * ARR_SZ)        // 40960 bytes per stage
#define GSMEM (2 * STAGE_SZ)         // 81920

__device__ __forceinline__ void gemm_load_stage(
    uint32_t sdst, const __nv_bfloat16* Ahb, const __nv_bfloat16* Alb,
    const __nv_bfloat16* Bhb, const __nv_bfloat16* Blb, int k0, int tid)
{
    #pragma unroll
    for (int it = 0; it < 2; it++) {
        int i = tid + it * 256;
        int r = i >> 2, c = i & 3;               // c: 16B chunk (8 bf16)
        size_t go = (size_t)r * GK + k0 + c * 8;
        uint32_t d0 = sdst + (uint32_t)(r * (PADR * 2) + c * 16);
        cp_async16(d0,              Ahb + go);
        cp_async16(d0 + ARR_SZ,     Alb + go);
        cp_async16(d0 + 2 * ARR_SZ, Bhb + go);
        cp_async16(d0 + 3 * ARR_SZ, Blb + go);
    }
    cp_commit();
}

__global__ __launch_bounds__(256, 1) void gemm_bf16x3(
    const __nv_bfloat16* __restrict__ Ah, const __nv_bfloat16* __restrict__ Al,
    const __nv_bfloat16* __restrict__ Bh, const __nv_bfloat16* __restrict__ Bl,
    float* __restrict__ C, int N)
{
    extern __shared__ char dsm[];
    const uint32_t sb = smem_u32(dsm);

    const int tid = threadIdx.x;
    const int wid = tid >> 5;
    const int lane = tid & 31;
    const int wm = wid >> 2;
    const int wn = wid & 3;

    const int m0 = blockIdx.y * 128;
    const int n0 = blockIdx.x * 128;

    const __nv_bfloat16* Ahb = Ah + (size_t)m0 * GK;
    const __nv_bfloat16* Alb = Al + (size_t)m0 * GK;
    const __nv_bfloat16* Bhb = Bh + (size_t)n0 * GK;
    const __nv_bfloat16* Blb = Bl + (size_t)n0 * GK;

    float acc[4][4][4];
    #pragma unroll
    for (int i = 0; i < 4; i++)
        #pragma unroll
        for (int j = 0; j < 4; j++)
            #pragma unroll
            for (int r = 0; r < 4; r++) acc[i][j][r] = 0.f;

    const uint32_t aoff = (uint32_t)((wm * 64 + (lane & 15)) * (PADR * 2) + ((lane >> 4) << 4));
    const uint32_t boff = (uint32_t)((wn * 32 + (lane & 7)) * (PADR * 2) + (((lane >> 3) & 1) << 4));

    gemm_load_stage(sb, Ahb, Alb, Bhb, Blb, 0, tid);

    const int NCH = GK / BKC;      // 32
    for (int ch = 0; ch < NCH; ch++) {
        if (ch + 1 < NCH)
            gemm_load_stage(sb + ((ch + 1) & 1) * STAGE_SZ, Ahb, Alb, Bhb, Blb, (ch + 1) * BKC, tid);
        if (ch + 1 < NCH) {
            asm volatile("cp.async.wait_group 1;");
        } else {
            asm volatile("cp.async.wait_group 0;");
        }
        __syncthreads();

        const uint32_t st = sb + (ch & 1) * STAGE_SZ;
        #pragma unroll
        for (int ks = 0; ks < 2; ks++) {
            const uint32_t ksb = ks * 32;
            uint32_t ah[4][4], al[4][4], bh[4][2], bl[4][2];
            #pragma unroll
            for (int mt = 0; mt < 4; mt++) {
                uint32_t off = aoff + mt * 16 * (PADR * 2) + ksb;
                ldm_x4(ah[mt][0], ah[mt][1], ah[mt][2], ah[mt][3], st + off);
                ldm_x4(al[mt][0], al[mt][1], al[mt][2], al[mt][3], st + ARR_SZ + off);
            }
            #pragma unroll
            for (int nt = 0; nt < 4; nt++) {
                uint32_t off = boff + nt * 8 * (PADR * 2) + ksb;
                ldm_x2(bh[nt][0], bh[nt][1], st + 2 * ARR_SZ + off);
                ldm_x2(bl[nt][0], bl[nt][1], st + 3 * ARR_SZ + off);
            }
            #pragma unroll
            for (int mt = 0; mt < 4; mt++)
                #pragma unroll
                for (int nt = 0; nt < 4; nt++) {
                    mma16816(acc[mt][nt], ah[mt], bh[nt]);
                    mma16816(acc[mt][nt], ah[mt], bl[nt]);
                    mma16816(acc[mt][nt], al[mt], bh[nt]);
                }
        }
        __syncthreads();
    }

    const int mrow = m0 + wm * 64 + (lane >> 2);
    const int ncol = n0 + wn * 32 + (lane & 3) * 2;
    #pragma unroll
    for (int mt = 0; mt < 4; mt++)
        #pragma unroll
        for (int nt = 0; nt < 4; nt++) {
            float* c0 = C + (size_t)(mrow + mt * 16) * N + ncol + nt * 8;
            *(float2*)c0 = make_float2(acc[mt][nt][0], acc[mt][nt][1]);
            float* c1 = c0 + (size_t)8 * N;
            *(float2*)c1 = make_float2(acc[mt][nt][2], acc[mt][nt][3]);
        }
}

// ---------------- fp32 selection-score path ---------------------------------
__global__ __launch_bounds__(64) void qlast_kernel(
    const float* __restrict__ x, const float* __restrict__ Wa,
    float* __restrict__ qlast)
{
    const int b = blockIdx.x >> 4, h = blockIdx.x & 15;
    __shared__ float xs[CC];
    for (int c = threadIdx.x; c < CC; c += 64)
        xs[c] = x[((size_t)b * TT + (TT - 1)) * CC + c];
    __syncthreads();
    const int col = h * HD + threadIdx.x;
    float s = 0.f;
    for (int c = 0; c < CC; c++) s += xs[c] * Wa[(size_t)c * (3 * CC) + col];
    qlast[(b * NH + h) * HD + threadIdx.x] = s;
}

__global__ __launch_bounds__(256) void uproj_kernel(
    const float* __restrict__ Wa, const float* __restrict__ qlast,
    float* __restrict__ u)
{
    const int b = blockIdx.x;
    const int c = blockIdx.y * 16 + (threadIdx.x >> 4);
    const int h = threadIdx.x & 15;
    __shared__ float qs[CC];
    for (int i = threadIdx.x; i < CC; i += 256) qs[i] = qlast[b * CC + i];
    __syncthreads();
    const float* wrow = Wa + (size_t)c * (3 * CC) + CC + h * HD;
    const float* qh = qs + h * HD;
    float s = 0.f;
    #pragma unroll
    for (int d = 0; d < HD; d++) s += wrow[d] * qh[d];
    u[((size_t)b * CC + c) * NH + h] = s;
}

__global__ __launch_bounds__(256) void scores_kernel(
    const float* __restrict__ x, const float* __restrict__ u,
    float* __restrict__ last)
{
    const int b = blockIdx.x;
    const int t = blockIdx.y * 256 + threadIdx.x;
    __shared__ float us[128][NH];
    float acc[NH];
    #pragma unroll
    for (int h = 0; h < NH; h++) acc[h] = 0.f;
    const float* xr = x + ((size_t)b * TT + t) * CC;
    for (int c0 = 0; c0 < CC; c0 += 128) {
        __syncthreads();
        for (int i = threadIdx.x; i < 128 * NH; i += 256)
            ((float*)us)[i] = u[((size_t)b * CC + c0) * NH + i];
        __syncthreads();
        for (int ci = 0; ci < 128; ci++) {
            float xv = xr[c0 + ci];
            #pragma unroll
            for (int h = 0; h < NH; h++) acc[h] += xv * us[ci][h];
        }
    }
    #pragma unroll
    for (int h = 0; h < NH; h++)
        last[(b * NH + h) * TT + t] = acc[h] * 0.125f;
}

// ---------------- top-k set selection via bitonic sort ---------------------
__global__ __launch_bounds__(512) void topk_kernel(const float* __restrict__ last,
                                                   int* __restrict__ idxout)
{
    __shared__ unsigned long long s[TT];
    const int bh = blockIdx.x;
    const int tid = threadIdx.x;

    for (int t = tid; t < TT; t += 512) {
        unsigned u;
        if (t >= NONREC) {
            u = 0xFFFFFFFFu;
        } else {
            u = __float_as_uint(last[bh * TT + t]);
            u = (u & 0x80000000u) ? ~u : (u | 0x80000000u);
        }
        s[t] = ((unsigned long long)u << 32) | (unsigned)t;
    }
    __syncthreads();

    for (int k = 2; k <= TT; k <<= 1) {
        for (int j = k >> 1; j > 0; j >>= 1) {
            for (int i = tid; i < TT; i += 512) {
                int ix = i ^ j;
                if (ix > i) {
                    bool desc = ((i & k) == 0);
                    unsigned long long a = s[i], b = s[ix];
                    bool sw = desc ? (a < b) : (a > b);
                    if (sw) { s[i] = b; s[ix] = a; }
                }
            }
            __syncthreads();
        }
    }
    for (int i = tid; i < KKEEP; i += 512)
        idxout[bh * KKEEP + i] = (int)(s[i] & 0xFFFFFFFFu);
}

// ---------------- pruned attention; epilogue writes bf16 hi/lo --------------
#define KCHUNK 64

__global__ __launch_bounds__(128) void attn_kernel(
    const float* __restrict__ qkv, const int* __restrict__ idx,
    __nv_bfloat16* __restrict__ yh, __nv_bfloat16* __restrict__ yl)
{
    const int bh = blockIdx.x;
    const int b = bh >> 4, h = bh & 15;
    const int qt = blockIdx.y * 128 + threadIdx.x;

    __shared__ float Ks[KCHUNK][HD];
    __shared__ float Vs[KCHUNK][HD];

    float4 q4[HD / 4];
    {
        const float4* qrow = (const float4*)(qkv + ((size_t)b * TT + qt) * (3 * CC) + h * HD);
        #pragma unroll
        for (int d = 0; d < HD / 4; d++) {
            float4 v = qrow[d];
            q4[d] = make_float4(v.x * 0.125f, v.y * 0.125f, v.z * 0.125f, v.w * 0.125f);
        }
    }

    float l = 0.f;
    float4 a4[HD / 4];
    #pragma unroll
    for (int d = 0; d < HD / 4; d++) a4[d] = make_float4(0.f, 0.f, 0.f, 0.f);

    for (int c0 = 0; c0 < KKEEP; c0 += KCHUNK) {
        const int cn = min(KCHUNK, KKEEP - c0);
        __syncthreads();
        for (int i = threadIdx.x; i < cn * (HD / 4); i += 128) {
            int r = i >> 4;
            int c4 = (i & 15) * 4;
            int kt = idx[bh * KKEEP + c0 + r];
            const float* kr = qkv + ((size_t)b * TT + kt) * (3 * CC) + CC + h * HD;
            *(float4*)&Ks[r][c4] = *(const float4*)(kr + c4);
            *(float4*)&Vs[r][c4] = *(const float4*)(kr + CC + c4);
        }
        __syncthreads();

        for (int kk = 0; kk < cn; kk++) {
            const float4* kr = (const float4*)&Ks[kk][0];
            float sc = 0.f;
            #pragma unroll
            for (int d = 0; d < HD / 4; d++) {
                float4 kv = kr[d];
                sc += q4[d].x * kv.x + q4[d].y * kv.y + q4[d].z * kv.z + q4[d].w * kv.w;
            }
            float p = __expf(sc);
            l += p;
            const float4* vr = (const float4*)&Vs[kk][0];
            #pragma unroll
            for (int d = 0; d < HD / 4; d++) {
                float4 vv = vr[d];
                a4[d].x += p * vv.x; a4[d].y += p * vv.y;
                a4[d].z += p * vv.z; a4[d].w += p * vv.w;
            }
        }
    }

    const float invl = 1.f / l;
    const size_t off = ((size_t)b * TT + qt) * CC + h * HD;
    __nv_bfloat162* yh2 = (__nv_bfloat162*)(yh + off);
    __nv_bfloat162* yl2 = (__nv_bfloat162*)(yl + off);
    #pragma unroll
    for (int d = 0; d < HD / 4; d++) {
        float v0 = a4[d].x * invl, v1 = a4[d].y * invl;
        float v2 = a4[d].z * invl, v3 = a4[d].w * invl;
        __nv_bfloat16 h0, l0, h1, l1, h2, l2, h3, l3;
        split_bf16(v0, h0, l0); split_bf16(v1, h1, l1);
        split_bf16(v2, h2, l2); split_bf16(v3, h3, l3);
        yh2[d * 2 + 0] = __nv_bfloat162(h0, h1);
        yh2[d * 2 + 1] = __nv_bfloat162(h2, h3);
        yl2[d * 2 + 0] = __nv_bfloat162(l0, l1);
        yl2[d * 2 + 1] = __nv_bfloat162(l2, l3);
    }
}

// ---------------- launch ----------------------------------------------------
extern "C" void kernel_launch(void* const* d_in, const int* in_sizes, int n_in,
                              void* d_out, int out_size)
{
    const float* x  = (const float*)d_in[0];   // [4,1024,1024]
    const float* Wa = (const float*)d_in[1];   // [1024,3072]
    const float* Wp = (const float*)d_in[2];   // [1024,1024]
    float* out = (float*)d_out;                // [4,1024,1024]

    void* p;
    cudaGetSymbolAddress(&p, g_qkv);   float* qkv   = (float*)p;
    cudaGetSymbolAddress(&p, g_last);  float* last  = (float*)p;
    cudaGetSymbolAddress(&p, g_idx);   int*   idx   = (int*)p;
    cudaGetSymbolAddress(&p, g_qlast); float* qlast = (float*)p;
    cudaGetSymbolAddress(&p, g_u);     float* u     = (float*)p;
    cudaGetSymbolAddress(&p, g_xh);   __nv_bfloat16* xh  = (__nv_bfloat16*)p;
    cudaGetSymbolAddress(&p, g_xl);   __nv_bfloat16* xl  = (__nv_bfloat16*)p;
    cudaGetSymbolAddress(&p, g_wah);  __nv_bfloat16* wah = (__nv_bfloat16*)p;
    cudaGetSymbolAddress(&p, g_wal);  __nv_bfloat16* wal = (__nv_bfloat16*)p;
    cudaGetSymbolAddress(&p, g_wph);  __nv_bfloat16* wph = (__nv_bfloat16*)p;
    cudaGetSymbolAddress(&p, g_wpl);  __nv_bfloat16* wpl = (__nv_bfloat16*)p;
    cudaGetSymbolAddress(&p, g_yh);   __nv_bfloat16* yh  = (__nv_bfloat16*)p;
    cudaGetSymbolAddress(&p, g_yl);   __nv_bfloat16* yl  = (__nv_bfloat16*)p;

    cudaFuncSetAttribute(gemm_bf16x3, cudaFuncAttributeMaxDynamicSharedMemorySize, GSMEM);

    // 0) fp32 selection scores
    qlast_kernel<<<BB * NH, 64>>>(x, Wa, qlast);
    uproj_kernel<<<dim3(BB, CC / 16), 256>>>(Wa, qlast, u);
    scores_kernel<<<dim3(BB, TT / 256), 256>>>(x, u, last);
    topk_kernel<<<BB * NH, 512>>>(last, idx);

    // 1) prep: split x; transpose+split weights
    split_kernel<<<(BB * TT * CC / 4 + 255) / 256, 256>>>(x, xh, xl, BB * TT * CC / 4);
    transpose_split_kernel<<<dim3(3 * CC / 32, CC / 32), dim3(32, 8)>>>(Wa, wah, wal, CC, 3 * CC);
    transpose_split_kernel<<<dim3(CC / 32, CC / 32), dim3(32, 8)>>>(Wp, wph, wpl, CC, CC);

    // 2) qkv = x @ W_attn   (pipelined bf16x3)
    gemm_bf16x3<<<dim3(3 * CC / 128, BB * TT / 128), 256, GSMEM>>>(xh, xl, wah, wal, qkv, 3 * CC);

    // 3) pruned attention -> yh/yl (bf16 split fused in epilogue)
    attn_kernel<<<dim3(BB * NH, TT / 128), 128>>>(qkv, idx, yh, yl);

    // 4) out = y @ W_proj   (pipelined bf16x3)
    gemm_bf16x3<<<dim3(CC / 128, BB * TT / 128), 256, GSMEM>>>(yh, yl, wph, wpl, out, CC);
}

// round 7
// speedup vs baseline: 1.2601x; 1.0847x over previous
#include <cuda_runtime.h>
#include <cuda_bf16.h>
#include <math.h>
#include <stdint.h>

// Problem constants
#define BB 4
#define TT 1024
#define CC 1024
#define NH 16
#define HD 64
#define KKEEP 391
#define REC 64
#define NONREC (TT - REC)       // 960

// ---------------- scratch (device globals; no allocation allowed) ----------
__device__ float g_qkv[BB * TT * 3 * CC];            // 50.3 MB fp32
__device__ float g_last[BB * NH * TT];
__device__ int   g_idx[BB * NH * KKEEP];
__device__ float g_qlast[BB * CC];
__device__ float g_u[BB * CC * NH];
__device__ __nv_bfloat16 g_xh[BB * TT * CC];
__device__ __nv_bfloat16 g_xl[BB * TT * CC];
__device__ __nv_bfloat16 g_wah[3 * CC * CC];         // W_attn^T hi/lo [3072][1024]
__device__ __nv_bfloat16 g_wal[3 * CC * CC];
__device__ __nv_bfloat16 g_wph[CC * CC];             // W_proj^T hi/lo
__device__ __nv_bfloat16 g_wpl[CC * CC];
__device__ __nv_bfloat16 g_yh[BB * TT * CC];
__device__ __nv_bfloat16 g_yl[BB * TT * CC];

// ---------------- helpers ---------------------------------------------------
__device__ __forceinline__ uint32_t smem_u32(const void* p) {
    uint32_t a;
    asm("{ .reg .u64 t; cvta.to.shared.u64 t, %1; cvt.u32.u64 %0, t; }" : "=r"(a) : "l"(p));
    return a;
}
__device__ __forceinline__ void cp_async16(uint32_t dst, const void* src) {
    asm volatile("cp.async.cg.shared.global [%0], [%1], 16;" :: "r"(dst), "l"(src));
}
__device__ __forceinline__ void cp_commit() {
    asm volatile("cp.async.commit_group;");
}
__device__ __forceinline__ void ldm_x4(uint32_t& r0, uint32_t& r1, uint32_t& r2, uint32_t& r3, uint32_t addr) {
    asm volatile("ldmatrix.sync.aligned.m8n8.x4.shared.b16 {%0,%1,%2,%3}, [%4];"
                 : "=r"(r0), "=r"(r1), "=r"(r2), "=r"(r3) : "r"(addr));
}
__device__ __forceinline__ void ldm_x2(uint32_t& r0, uint32_t& r1, uint32_t addr) {
    asm volatile("ldmatrix.sync.aligned.m8n8.x2.shared.b16 {%0,%1}, [%2];"
                 : "=r"(r0), "=r"(r1) : "r"(addr));
}
__device__ __forceinline__ void mma16816(float* d, const uint32_t* a, const uint32_t* b) {
    asm volatile(
        "mma.sync.aligned.m16n8k16.row.col.f32.bf16.bf16.f32 "
        "{%0,%1,%2,%3},{%4,%5,%6,%7},{%8,%9},{%0,%1,%2,%3};"
        : "+f"(d[0]), "+f"(d[1]), "+f"(d[2]), "+f"(d[3])
        : "r"(a[0]), "r"(a[1]), "r"(a[2]), "r"(a[3]), "r"(b[0]), "r"(b[1]));
}
__device__ __forceinline__ void split_bf16(float a, __nv_bfloat16& h, __nv_bfloat16& l) {
    h = __float2bfloat16(a);
    l = __float2bfloat16(a - __bfloat162float(h));
}

// ---------------- prep: fp32 -> (hi, lo) bf16 -------------------------------
__global__ __launch_bounds__(256) void split_kernel(
    const float* __restrict__ in, __nv_bfloat16* __restrict__ hi,
    __nv_bfloat16* __restrict__ lo, int n4)
{
    int i = blockIdx.x * 256 + threadIdx.x;
    if (i >= n4) return;
    float4 v = ((const float4*)in)[i];
    __nv_bfloat16 h0, h1, h2, h3, l0, l1, l2, l3;
    split_bf16(v.x, h0, l0); split_bf16(v.y, h1, l1);
    split_bf16(v.z, h2, l2); split_bf16(v.w, h3, l3);
    ((__nv_bfloat162*)hi)[i * 2 + 0] = __nv_bfloat162(h0, h1);
    ((__nv_bfloat162*)hi)[i * 2 + 1] = __nv_bfloat162(h2, h3);
    ((__nv_bfloat162*)lo)[i * 2 + 0] = __nv_bfloat162(l0, l1);
    ((__nv_bfloat162*)lo)[i * 2 + 1] = __nv_bfloat162(l2, l3);
}

// ---------------- prep: transpose fp32 [rows][cols] -> bf16 hi/lo [cols][rows]
__global__ __launch_bounds__(256) void transpose_split_kernel(
    const float* __restrict__ in, __nv_bfloat16* __restrict__ outh,
    __nv_bfloat16* __restrict__ outl, int rows, int cols)
{
    __shared__ float t[32][33];
    int bx = blockIdx.x * 32, by = blockIdx.y * 32;
    int x = bx + threadIdx.x;
    #pragma unroll
    for (int j = threadIdx.y; j < 32; j += 8)
        t[j][threadIdx.x] = in[(size_t)(by + j) * cols + x];
    __syncthreads();
    int xo = by + threadIdx.x;
    #pragma unroll
    for (int j = threadIdx.y; j < 32; j += 8) {
        float v = t[threadIdx.x][j];
        __nv_bfloat16 h, l;
        split_bf16(v, h, l);
        outh[(size_t)(bx + j) * rows + xo] = h;
        outl[(size_t)(bx + j) * rows + xo] = l;
    }
}

// ---------------- mma.sync bf16 3-term GEMM, 3-stage cp.async, swizzled -----
// C[M,N] = (Ah+Al)[M,K]*(Bh+Bl)[N,K]^T, dropping Al*Bl.
// CTA 128x128, 8 warps (2m x 4n), warp tile 64x32, BK=32.
// Smem: 64B rows (4x16B chunks), XOR swizzle chunk' = chunk ^ ((row>>1)&3).
#define GK 1024
#define BKC 32
#define ARR2 (128 * 64)          // 8192 bytes per array (128 rows x 64B)
#define STG2 (4 * ARR2)          // 32768 bytes per stage
#define NSTG 3
#define GSMEM (NSTG * STG2)      // 98304

__device__ __forceinline__ void gemm_load_stage(
    uint32_t sdst, const __nv_bfloat16* Ahb, const __nv_bfloat16* Alb,
    const __nv_bfloat16* Bhb, const __nv_bfloat16* Blb, int k0, int tid)
{
    #pragma unroll
    for (int it = 0; it < 2; it++) {
        int i = tid + it * 256;
        int r = i >> 2, c = i & 3;                       // c: 16B chunk (8 bf16)
        int cs = c ^ ((r >> 1) & 3);                     // swizzled chunk
        size_t go = (size_t)r * GK + k0 + c * 8;
        uint32_t d0 = sdst + (uint32_t)(r * 64 + cs * 16);
        cp_async16(d0,            Ahb + go);
        cp_async16(d0 + ARR2,     Alb + go);
        cp_async16(d0 + 2 * ARR2, Bhb + go);
        cp_async16(d0 + 3 * ARR2, Blb + go);
    }
    cp_commit();
}

__global__ __launch_bounds__(256, 2) void gemm_bf16x3(
    const __nv_bfloat16* __restrict__ Ah, const __nv_bfloat16* __restrict__ Al,
    const __nv_bfloat16* __restrict__ Bh, const __nv_bfloat16* __restrict__ Bl,
    float* __restrict__ C, int N)
{
    extern __shared__ char dsm[];
    const uint32_t sb = smem_u32(dsm);

    const int tid = threadIdx.x;
    const int wid = tid >> 5;
    const int lane = tid & 31;
    const int wm = wid >> 2;
    const int wn = wid & 3;

    const int m0 = blockIdx.y * 128;
    const int n0 = blockIdx.x * 128;

    const __nv_bfloat16* Ahb = Ah + (size_t)m0 * GK;
    const __nv_bfloat16* Alb = Al + (size_t)m0 * GK;
    const __nv_bfloat16* Bhb = Bh + (size_t)n0 * GK;
    const __nv_bfloat16* Blb = Bl + (size_t)n0 * GK;

    float acc[4][4][4];
    #pragma unroll
    for (int i = 0; i < 4; i++)
        #pragma unroll
        for (int j = 0; j < 4; j++)
            #pragma unroll
            for (int r = 0; r < 4; r++) acc[i][j][r] = 0.f;

    // ldmatrix lane addressing (swizzle bits constant across mt/nt tiles)
    const int arow = wm * 64 + (lane & 15);
    const int achk = lane >> 4;                  // 0..1
    const uint32_t s_a = (uint32_t)((arow >> 1) & 3);
    const int brow = wn * 32 + (lane & 7);
    const int bchk = (lane >> 3) & 1;
    const uint32_t s_b = (uint32_t)((brow >> 1) & 3);

    gemm_load_stage(sb,        Ahb, Alb, Bhb, Blb, 0,   tid);
    gemm_load_stage(sb + STG2, Ahb, Alb, Bhb, Blb, BKC, tid);

    const int NCH = GK / BKC;      // 32
    for (int ch = 0; ch < NCH; ch++) {
        if (ch + 2 < NCH) {
            gemm_load_stage(sb + ((ch + 2) % NSTG) * STG2, Ahb, Alb, Bhb, Blb, (ch + 2) * BKC, tid);
            asm volatile("cp.async.wait_group 2;");
        } else if (ch + 1 < NCH) {
            asm volatile("cp.async.wait_group 1;");
        } else {
            asm volatile("cp.async.wait_group 0;");
        }
        __syncthreads();

        const uint32_t st = sb + (ch % NSTG) * STG2;
        #pragma unroll
        for (int ks = 0; ks < 2; ks++) {
            const uint32_t kc = (uint32_t)(ks * 2);
            uint32_t af[4][4], bf[4][2], bt[4][2];
            // A-hi, B-hi
            #pragma unroll
            for (int mt = 0; mt < 4; mt++) {
                uint32_t ad = st + (uint32_t)((arow + mt * 16) * 64) + (((kc + achk) ^ s_a) << 4);
                ldm_x4(af[mt][0], af[mt][1], af[mt][2], af[mt][3], ad);
            }
            #pragma unroll
            for (int nt = 0; nt < 4; nt++) {
                uint32_t bd = st + 2 * ARR2 + (uint32_t)((brow + nt * 8) * 64) + (((kc + bchk) ^ s_b) << 4);
                ldm_x2(bf[nt][0], bf[nt][1], bd);
            }
            #pragma unroll
            for (int mt = 0; mt < 4; mt++)
                #pragma unroll
                for (int nt = 0; nt < 4; nt++) mma16816(acc[mt][nt], af[mt], bf[nt]);
            // B-lo (A-hi reused)
            #pragma unroll
            for (int nt = 0; nt < 4; nt++) {
                uint32_t bd = st + 3 * ARR2 + (uint32_t)((brow + nt * 8) * 64) + (((kc + bchk) ^ s_b) << 4);
                ldm_x2(bt[nt][0], bt[nt][1], bd);
            }
            #pragma unroll
            for (int mt = 0; mt < 4; mt++)
                #pragma unroll
                for (int nt = 0; nt < 4; nt++) mma16816(acc[mt][nt], af[mt], bt[nt]);
            // A-lo (overwrite af), B-hi reused
            #pragma unroll
            for (int mt = 0; mt < 4; mt++) {
                uint32_t ad = st + ARR2 + (uint32_t)((arow + mt * 16) * 64) + (((kc + achk) ^ s_a) << 4);
                ldm_x4(af[mt][0], af[mt][1], af[mt][2], af[mt][3], ad);
            }
            #pragma unroll
            for (int mt = 0; mt < 4; mt++)
                #pragma unroll
                for (int nt = 0; nt < 4; nt++) mma16816(acc[mt][nt], af[mt], bf[nt]);
        }
        __syncthreads();
    }

    const int mrow = m0 + wm * 64 + (lane >> 2);
    const int ncol = n0 + wn * 32 + (lane & 3) * 2;
    #pragma unroll
    for (int mt = 0; mt < 4; mt++)
        #pragma unroll
        for (int nt = 0; nt < 4; nt++) {
            float* c0 = C + (size_t)(mrow + mt * 16) * N + ncol + nt * 8;
            *(float2*)c0 = make_float2(acc[mt][nt][0], acc[mt][nt][1]);
            float* c1 = c0 + (size_t)8 * N;
            *(float2*)c1 = make_float2(acc[mt][nt][2], acc[mt][nt][3]);
        }
}

// ---------------- fp32 selection-score path ---------------------------------
__global__ __launch_bounds__(64) void qlast_kernel(
    const float* __restrict__ x, const float* __restrict__ Wa,
    float* __restrict__ qlast)
{
    const int b = blockIdx.x >> 4, h = blockIdx.x & 15;
    __shared__ float xs[CC];
    for (int c = threadIdx.x; c < CC; c += 64)
        xs[c] = x[((size_t)b * TT + (TT - 1)) * CC + c];
    __syncthreads();
    const int col = h * HD + threadIdx.x;
    float s = 0.f;
    for (int c = 0; c < CC; c++) s += xs[c] * Wa[(size_t)c * (3 * CC) + col];
    qlast[(b * NH + h) * HD + threadIdx.x] = s;
}

__global__ __launch_bounds__(256) void uproj_kernel(
    const float* __restrict__ Wa, const float* __restrict__ qlast,
    float* __restrict__ u)
{
    const int b = blockIdx.x;
    const int c = blockIdx.y * 16 + (threadIdx.x >> 4);
    const int h = threadIdx.x & 15;
    __shared__ float qs[CC];
    for (int i = threadIdx.x; i < CC; i += 256) qs[i] = qlast[b * CC + i];
    __syncthreads();
    const float* wrow = Wa + (size_t)c * (3 * CC) + CC + h * HD;
    const float* qh = qs + h * HD;
    float s = 0.f;
    #pragma unroll
    for (int d = 0; d < HD; d++) s += wrow[d] * qh[d];
    u[((size_t)b * CC + c) * NH + h] = s;
}

__global__ __launch_bounds__(256) void scores_kernel(
    const float* __restrict__ x, const float* __restrict__ u,
    float* __restrict__ last)
{
    const int b = blockIdx.x;
    const int t = blockIdx.y * 256 + threadIdx.x;
    __shared__ float us[128][NH];
    float acc[NH];
    #pragma unroll
    for (int h = 0; h < NH; h++) acc[h] = 0.f;
    const float* xr = x + ((size_t)b * TT + t) * CC;
    for (int c0 = 0; c0 < CC; c0 += 128) {
        __syncthreads();
        for (int i = threadIdx.x; i < 128 * NH; i += 256)
            ((float*)us)[i] = u[((size_t)b * CC + c0) * NH + i];
        __syncthreads();
        for (int ci = 0; ci < 128; ci++) {
            float xv = xr[c0 + ci];
            #pragma unroll
            for (int h = 0; h < NH; h++) acc[h] += xv * us[ci][h];
        }
    }
    #pragma unroll
    for (int h = 0; h < NH; h++)
        last[(b * NH + h) * TT + t] = acc[h] * 0.125f;
}

// ---------------- top-k set selection via bitonic sort ---------------------
__global__ __launch_bounds__(512) void topk_kernel(const float* __restrict__ last,
                                                   int* __restrict__ idxout)
{
    __shared__ unsigned long long s[TT];
    const int bh = blockIdx.x;
    const int tid = threadIdx.x;

    for (int t = tid; t < TT; t += 512) {
        unsigned u;
        if (t >= NONREC) {
            u = 0xFFFFFFFFu;
        } else {
            u = __float_as_uint(last[bh * TT + t]);
            u = (u & 0x80000000u) ? ~u : (u | 0x80000000u);
        }
        s[t] = ((unsigned long long)u << 32) | (unsigned)t;
    }
    __syncthreads();

    for (int k = 2; k <= TT; k <<= 1) {
        for (int j = k >> 1; j > 0; j >>= 1) {
            for (int i = tid; i < TT; i += 512) {
                int ix = i ^ j;
                if (ix > i) {
                    bool desc = ((i & k) == 0);
                    unsigned long long a = s[i], b = s[ix];
                    bool sw = desc ? (a < b) : (a > b);
                    if (sw) { s[i] = b; s[ix] = a; }
                }
            }
            __syncthreads();
        }
    }
    for (int i = tid; i < KKEEP; i += 512)
        idxout[bh * KKEEP + i] = (int)(s[i] & 0xFFFFFFFFu);
}

// ---------------- pruned attention; epilogue writes bf16 hi/lo --------------
#define KCHUNK 64

__global__ __launch_bounds__(128) void attn_kernel(
    const float* __restrict__ qkv, const int* __restrict__ idx,
    __nv_bfloat16* __restrict__ yh, __nv_bfloat16* __restrict__ yl)
{
    const int bh = blockIdx.x;
    const int b = bh >> 4, h = bh & 15;
    const int qt = blockIdx.y * 128 + threadIdx.x;

    __shared__ float Ks[KCHUNK][HD];
    __shared__ float Vs[KCHUNK][HD];

    float4 q4[HD / 4];
    {
        const float4* qrow = (const float4*)(qkv + ((size_t)b * TT + qt) * (3 * CC) + h * HD);
        #pragma unroll
        for (int d = 0; d < HD / 4; d++) {
            float4 v = qrow[d];
            q4[d] = make_float4(v.x * 0.125f, v.y * 0.125f, v.z * 0.125f, v.w * 0.125f);
        }
    }

    float l = 0.f;
    float4 a4[HD / 4];
    #pragma unroll
    for (int d = 0; d < HD / 4; d++) a4[d] = make_float4(0.f, 0.f, 0.f, 0.f);

    for (int c0 = 0; c0 < KKEEP; c0 += KCHUNK) {
        const int cn = min(KCHUNK, KKEEP - c0);
        __syncthreads();
        for (int i = threadIdx.x; i < cn * (HD / 4); i += 128) {
            int r = i >> 4;
            int c4 = (i & 15) * 4;
            int kt = idx[bh * KKEEP + c0 + r];
            const float* kr = qkv + ((size_t)b * TT + kt) * (3 * CC) + CC + h * HD;
            *(float4*)&Ks[r][c4] = *(const float4*)(kr + c4);
            *(float4*)&Vs[r][c4] = *(const float4*)(kr + CC + c4);
        }
        __syncthreads();

        for (int kk = 0; kk < cn; kk++) {
            const float4* kr = (const float4*)&Ks[kk][0];
            float sc = 0.f;
            #pragma unroll
            for (int d = 0; d < HD / 4; d++) {
                float4 kv = kr[d];
                sc += q4[d].x * kv.x + q4[d].y * kv.y + q4[d].z * kv.z + q4[d].w * kv.w;
            }
            float p = __expf(sc);
            l += p;
            const float4* vr = (const float4*)&Vs[kk][0];
            #pragma unroll
            for (int d = 0; d < HD / 4; d++) {
                float4 vv = vr[d];
                a4[d].x += p * vv.x; a4[d].y += p * vv.y;
                a4[d].z += p * vv.z; a4[d].w += p * vv.w;
            }
        }
    }

    const float invl = 1.f / l;
    const size_t off = ((size_t)b * TT + qt) * CC + h * HD;
    __nv_bfloat162* yh2 = (__nv_bfloat162*)(yh + off);
    __nv_bfloat162* yl2 = (__nv_bfloat162*)(yl + off);
    #pragma unroll
    for (int d = 0; d < HD / 4; d++) {
        float v0 = a4[d].x * invl, v1 = a4[d].y * invl;
        float v2 = a4[d].z * invl, v3 = a4[d].w * invl;
        __nv_bfloat16 h0, l0, h1, l1, h2, l2, h3, l3;
        split_bf16(v0, h0, l0); split_bf16(v1, h1, l1);
        split_bf16(v2, h2, l2); split_bf16(v3, h3, l3);
        yh2[d * 2 + 0] = __nv_bfloat162(h0, h1);
        yh2[d * 2 + 1] = __nv_bfloat162(h2, h3);
        yl2[d * 2 + 0] = __nv_bfloat162(l0, l1);
        yl2[d * 2 + 1] = __nv_bfloat162(l2, l3);
    }
}

// ---------------- launch ----------------------------------------------------
extern "C" void kernel_launch(void* const* d_in, const int* in_sizes, int n_in,
                              void* d_out, int out_size)
{
    const float* x  = (const float*)d_in[0];   // [4,1024,1024]
    const float* Wa = (const float*)d_in[1];   // [1024,3072]
    const float* Wp = (const float*)d_in[2];   // [1024,1024]
    float* out = (float*)d_out;                // [4,1024,1024]

    void* p;
    cudaGetSymbolAddress(&p, g_qkv);   float* qkv   = (float*)p;
    cudaGetSymbolAddress(&p, g_last);  float* last  = (float*)p;
    cudaGetSymbolAddress(&p, g_idx);   int*   idx   = (int*)p;
    cudaGetSymbolAddress(&p, g_qlast); float* qlast = (float*)p;
    cudaGetSymbolAddress(&p, g_u);     float* u     = (float*)p;
    cudaGetSymbolAddress(&p, g_xh);   __nv_bfloat16* xh  = (__nv_bfloat16*)p;
    cudaGetSymbolAddress(&p, g_xl);   __nv_bfloat16* xl  = (__nv_bfloat16*)p;
    cudaGetSymbolAddress(&p, g_wah);  __nv_bfloat16* wah = (__nv_bfloat16*)p;
    cudaGetSymbolAddress(&p, g_wal);  __nv_bfloat16* wal = (__nv_bfloat16*)p;
    cudaGetSymbolAddress(&p, g_wph);  __nv_bfloat16* wph = (__nv_bfloat16*)p;
    cudaGetSymbolAddress(&p, g_wpl);  __nv_bfloat16* wpl = (__nv_bfloat16*)p;
    cudaGetSymbolAddress(&p, g_yh);   __nv_bfloat16* yh  = (__nv_bfloat16*)p;
    cudaGetSymbolAddress(&p, g_yl);   __nv_bfloat16* yl  = (__nv_bfloat16*)p;

    cudaFuncSetAttribute(gemm_bf16x3, cudaFuncAttributeMaxDynamicSharedMemorySize, GSMEM);

    // 0) fp32 selection scores
    qlast_kernel<<<BB * NH, 64>>>(x, Wa, qlast);
    uproj_kernel<<<dim3(BB, CC / 16), 256>>>(Wa, qlast, u);
    scores_kernel<<<dim3(BB, TT / 256), 256>>>(x, u, last);
    topk_kernel<<<BB * NH, 512>>>(last, idx);

    // 1) prep: split x; transpose+split weights
    split_kernel<<<(BB * TT * CC / 4 + 255) / 256, 256>>>(x, xh, xl, BB * TT * CC / 4);
    transpose_split_kernel<<<dim3(3 * CC / 32, CC / 32), dim3(32, 8)>>>(Wa, wah, wal, CC, 3 * CC);
    transpose_split_kernel<<<dim3(CC / 32, CC / 32), dim3(32, 8)>>>(Wp, wph, wpl, CC, CC);

    // 2) qkv = x @ W_attn   (3-stage pipelined bf16x3, 2 CTAs/SM)
    gemm_bf16x3<<<dim3(3 * CC / 128, BB * TT / 128), 256, GSMEM>>>(xh, xl, wah, wal, qkv, 3 * CC);

    // 3) pruned attention -> yh/yl (bf16 split fused in epilogue)
    attn_kernel<<<dim3(BB * NH, TT / 128), 128>>>(qkv, idx, yh, yl);

    // 4) out = y @ W_proj   (3-stage pipelined bf16x3, 2 CTAs/SM)
    gemm_bf16x3<<<dim3(CC / 128, BB * TT / 128), 256, GSMEM>>>(yh, yl, wph, wpl, out, CC);
}

// round 8
// speedup vs baseline: 1.2678x; 1.0061x over previous
#include <cuda_runtime.h>
#include <cuda_bf16.h>
#include <math.h>
#include <stdint.h>

// Problem constants
#define BB 4
#define TT 1024
#define CC 1024
#define NH 16
#define HD 64
#define KKEEP 391
#define REC 64
#define NONREC (TT - REC)       // 960

// ---------------- scratch (device globals; no allocation allowed) ----------
__device__ float g_qkv[BB * TT * 3 * CC];            // 50.3 MB fp32
__device__ float g_last[BB * NH * TT];
__device__ int   g_idx[BB * NH * KKEEP];
__device__ float g_qlast[BB * CC];
__device__ float g_u[BB * CC * NH];
__device__ __nv_bfloat16 g_xh[BB * TT * CC];
__device__ __nv_bfloat16 g_xl[BB * TT * CC];
__device__ __nv_bfloat16 g_wah[3 * CC * CC];         // W_attn^T hi/lo [3072][1024]
__device__ __nv_bfloat16 g_wal[3 * CC * CC];
__device__ __nv_bfloat16 g_wph[CC * CC];             // W_proj^T hi/lo
__device__ __nv_bfloat16 g_wpl[CC * CC];
__device__ __nv_bfloat16 g_yh[BB * TT * CC];
__device__ __nv_bfloat16 g_yl[BB * TT * CC];

// ---------------- helpers ---------------------------------------------------
__device__ __forceinline__ uint32_t smem_u32(const void* p) {
    uint32_t a;
    asm("{ .reg .u64 t; cvta.to.shared.u64 t, %1; cvt.u32.u64 %0, t; }" : "=r"(a) : "l"(p));
    return a;
}
__device__ __forceinline__ void cp_async16(uint32_t dst, const void* src) {
    asm volatile("cp.async.cg.shared.global [%0], [%1], 16;" :: "r"(dst), "l"(src));
}
__device__ __forceinline__ void cp_commit() {
    asm volatile("cp.async.commit_group;");
}
__device__ __forceinline__ void ldm_x4(uint32_t& r0, uint32_t& r1, uint32_t& r2, uint32_t& r3, uint32_t addr) {
    asm volatile("ldmatrix.sync.aligned.m8n8.x4.shared.b16 {%0,%1,%2,%3}, [%4];"
                 : "=r"(r0), "=r"(r1), "=r"(r2), "=r"(r3) : "r"(addr));
}
__device__ __forceinline__ void ldm_x2(uint32_t& r0, uint32_t& r1, uint32_t addr) {
    asm volatile("ldmatrix.sync.aligned.m8n8.x2.shared.b16 {%0,%1}, [%2];"
                 : "=r"(r0), "=r"(r1) : "r"(addr));
}
__device__ __forceinline__ void mma16816(float* d, const uint32_t* a, const uint32_t* b) {
    asm volatile(
        "mma.sync.aligned.m16n8k16.row.col.f32.bf16.bf16.f32 "
        "{%0,%1,%2,%3},{%4,%5,%6,%7},{%8,%9},{%0,%1,%2,%3};"
        : "+f"(d[0]), "+f"(d[1]), "+f"(d[2]), "+f"(d[3])
        : "r"(a[0]), "r"(a[1]), "r"(a[2]), "r"(a[3]), "r"(b[0]), "r"(b[1]));
}
__device__ __forceinline__ void split_bf16(float a, __nv_bfloat16& h, __nv_bfloat16& l) {
    h = __float2bfloat16(a);
    l = __float2bfloat16(a - __bfloat162float(h));
}

// ---------------- merged prep: split x + transpose-split both weights -------
// grid.x = 4096 (split x) + 3072 (Wa) + 1024 (Wp) = 8192, 256 threads
#define PREP_SPLIT 4096
#define PREP_WA (PREP_SPLIT + 3072)
#define PREP_TOTAL (PREP_WA + 1024)

__global__ __launch_bounds__(256) void prep_kernel(
    const float* __restrict__ x, const float* __restrict__ Wa, const float* __restrict__ Wp,
    __nv_bfloat16* __restrict__ xh, __nv_bfloat16* __restrict__ xl,
    __nv_bfloat16* __restrict__ wah, __nv_bfloat16* __restrict__ wal,
    __nv_bfloat16* __restrict__ wph, __nv_bfloat16* __restrict__ wpl)
{
    const int bid = blockIdx.x;
    if (bid < PREP_SPLIT) {
        // split x: 1M float4s
        int i = bid * 256 + threadIdx.x;
        float4 v = ((const float4*)x)[i];
        __nv_bfloat16 h0, h1, h2, h3, l0, l1, l2, l3;
        split_bf16(v.x, h0, l0); split_bf16(v.y, h1, l1);
        split_bf16(v.z, h2, l2); split_bf16(v.w, h3, l3);
        ((__nv_bfloat162*)xh)[i * 2 + 0] = __nv_bfloat162(h0, h1);
        ((__nv_bfloat162*)xh)[i * 2 + 1] = __nv_bfloat162(h2, h3);
        ((__nv_bfloat162*)xl)[i * 2 + 0] = __nv_bfloat162(l0, l1);
        ((__nv_bfloat162*)xl)[i * 2 + 1] = __nv_bfloat162(l2, l3);
        return;
    }
    // transpose-split
    const float* in;
    __nv_bfloat16 *outh, *outl;
    int rows, cols, bx, by;
    if (bid < PREP_WA) {
        int id = bid - PREP_SPLIT;
        in = Wa; outh = wah; outl = wal; rows = CC; cols = 3 * CC;
        bx = (id % 96) * 32; by = (id / 96) * 32;
    } else {
        int id = bid - PREP_WA;
        in = Wp; outh = wph; outl = wpl; rows = CC; cols = CC;
        bx = (id % 32) * 32; by = (id / 32) * 32;
    }
    __shared__ float t[32][33];
    const int tx = threadIdx.x & 31, ty = threadIdx.x >> 5;
    int xcol = bx + tx;
    #pragma unroll
    for (int j = ty; j < 32; j += 8)
        t[j][tx] = in[(size_t)(by + j) * cols + xcol];
    __syncthreads();
    int xo = by + tx;
    #pragma unroll
    for (int j = ty; j < 32; j += 8) {
        float v = t[tx][j];
        __nv_bfloat16 h, l;
        split_bf16(v, h, l);
        outh[(size_t)(bx + j) * rows + xo] = h;
        outl[(size_t)(bx + j) * rows + xo] = l;
    }
}

// ---------------- mma.sync bf16 3-term GEMM, 3-stage cp.async, swizzled -----
// C[M,N] = (Ah+Al)[M,K]*(Bh+Bl)[N,K]^T, dropping Al*Bl.
// CTA 128x128, 8 warps (2m x 4n), warp tile 64x32, BK=32, single sync/chunk.
#define GK 1024
#define BKC 32
#define ARR2 (128 * 64)          // 8192 bytes per array (128 rows x 64B)
#define STG2 (4 * ARR2)          // 32768 bytes per stage
#define NSTG 3
#define GSMEM (NSTG * STG2)      // 98304

__device__ __forceinline__ void gemm_load_stage(
    uint32_t sdst, const __nv_bfloat16* Ahb, const __nv_bfloat16* Alb,
    const __nv_bfloat16* Bhb, const __nv_bfloat16* Blb, int k0, int tid)
{
    #pragma unroll
    for (int it = 0; it < 2; it++) {
        int i = tid + it * 256;
        int r = i >> 2, c = i & 3;                       // c: 16B chunk (8 bf16)
        int cs = c ^ ((r >> 1) & 3);                     // swizzled chunk
        size_t go = (size_t)r * GK + k0 + c * 8;
        uint32_t d0 = sdst + (uint32_t)(r * 64 + cs * 16);
        cp_async16(d0,            Ahb + go);
        cp_async16(d0 + ARR2,     Alb + go);
        cp_async16(d0 + 2 * ARR2, Bhb + go);
        cp_async16(d0 + 3 * ARR2, Blb + go);
    }
    cp_commit();
}

__global__ __launch_bounds__(256, 2) void gemm_bf16x3(
    const __nv_bfloat16* __restrict__ Ah, const __nv_bfloat16* __restrict__ Al,
    const __nv_bfloat16* __restrict__ Bh, const __nv_bfloat16* __restrict__ Bl,
    float* __restrict__ C, int N)
{
    extern __shared__ char dsm[];
    const uint32_t sb = smem_u32(dsm);

    const int tid = threadIdx.x;
    const int wid = tid >> 5;
    const int lane = tid & 31;
    const int wm = wid >> 2;
    const int wn = wid & 3;

    const int m0 = blockIdx.y * 128;
    const int n0 = blockIdx.x * 128;

    const __nv_bfloat16* Ahb = Ah + (size_t)m0 * GK;
    const __nv_bfloat16* Alb = Al + (size_t)m0 * GK;
    const __nv_bfloat16* Bhb = Bh + (size_t)n0 * GK;
    const __nv_bfloat16* Blb = Bl + (size_t)n0 * GK;

    float acc[4][4][4];
    #pragma unroll
    for (int i = 0; i < 4; i++)
        #pragma unroll
        for (int j = 0; j < 4; j++)
            #pragma unroll
            for (int r = 0; r < 4; r++) acc[i][j][r] = 0.f;

    const int arow = wm * 64 + (lane & 15);
    const int achk = lane >> 4;
    const uint32_t s_a = (uint32_t)((arow >> 1) & 3);
    const int brow = wn * 32 + (lane & 7);
    const int bchk = (lane >> 3) & 1;
    const uint32_t s_b = (uint32_t)((brow >> 1) & 3);

    gemm_load_stage(sb,        Ahb, Alb, Bhb, Blb, 0,   tid);
    gemm_load_stage(sb + STG2, Ahb, Alb, Bhb, Blb, BKC, tid);

    const int NCH = GK / BKC;      // 32
    for (int ch = 0; ch < NCH; ch++) {
        if (ch + 1 < NCH) {
            asm volatile("cp.async.wait_group 1;");
        } else {
            asm volatile("cp.async.wait_group 0;");
        }
        __syncthreads();
        // prefetch ch+2 AFTER the barrier: barrier proves compute(ch-1) done,
        // so overwriting stage (ch+2)%3 == (ch-1)%3 is safe. One sync/chunk.
        if (ch + 2 < NCH)
            gemm_load_stage(sb + ((ch + 2) % NSTG) * STG2, Ahb, Alb, Bhb, Blb, (ch + 2) * BKC, tid);

        const uint32_t st = sb + (ch % NSTG) * STG2;
        #pragma unroll
        for (int ks = 0; ks < 2; ks++) {
            const uint32_t kc = (uint32_t)(ks * 2);
            uint32_t af[4][4], bf[4][2], bt[4][2];
            #pragma unroll
            for (int mt = 0; mt < 4; mt++) {
                uint32_t ad = st + (uint32_t)((arow + mt * 16) * 64) + (((kc + achk) ^ s_a) << 4);
                ldm_x4(af[mt][0], af[mt][1], af[mt][2], af[mt][3], ad);
            }
            #pragma unroll
            for (int nt = 0; nt < 4; nt++) {
                uint32_t bd = st + 2 * ARR2 + (uint32_t)((brow + nt * 8) * 64) + (((kc + bchk) ^ s_b) << 4);
                ldm_x2(bf[nt][0], bf[nt][1], bd);
            }
            #pragma unroll
            for (int mt = 0; mt < 4; mt++)
                #pragma unroll
                for (int nt = 0; nt < 4; nt++) mma16816(acc[mt][nt], af[mt], bf[nt]);
            #pragma unroll
            for (int nt = 0; nt < 4; nt++) {
                uint32_t bd = st + 3 * ARR2 + (uint32_t)((brow + nt * 8) * 64) + (((kc + bchk) ^ s_b) << 4);
                ldm_x2(bt[nt][0], bt[nt][1], bd);
            }
            #pragma unroll
            for (int mt = 0; mt < 4; mt++)
                #pragma unroll
                for (int nt = 0; nt < 4; nt++) mma16816(acc[mt][nt], af[mt], bt[nt]);
            #pragma unroll
            for (int mt = 0; mt < 4; mt++) {
                uint32_t ad = st + ARR2 + (uint32_t)((arow + mt * 16) * 64) + (((kc + achk) ^ s_a) << 4);
                ldm_x4(af[mt][0], af[mt][1], af[mt][2], af[mt][3], ad);
            }
            #pragma unroll
            for (int mt = 0; mt < 4; mt++)
                #pragma unroll
                for (int nt = 0; nt < 4; nt++) mma16816(acc[mt][nt], af[mt], bf[nt]);
        }
        __syncthreads();   // protect stage reuse for the post-barrier prefetch pattern
    }

    const int mrow = m0 + wm * 64 + (lane >> 2);
    const int ncol = n0 + wn * 32 + (lane & 3) * 2;
    #pragma unroll
    for (int mt = 0; mt < 4; mt++)
        #pragma unroll
        for (int nt = 0; nt < 4; nt++) {
            float* c0 = C + (size_t)(mrow + mt * 16) * N + ncol + nt * 8;
            *(float2*)c0 = make_float2(acc[mt][nt][0], acc[mt][nt][1]);
            float* c1 = c0 + (size_t)8 * N;
            *(float2*)c1 = make_float2(acc[mt][nt][2], acc[mt][nt][3]);
        }
}

// ---------------- fp32 selection-score path ---------------------------------
__global__ __launch_bounds__(64) void qlast_kernel(
    const float* __restrict__ x, const float* __restrict__ Wa,
    float* __restrict__ qlast)
{
    const int b = blockIdx.x >> 4, h = blockIdx.x & 15;
    __shared__ float xs[CC];
    for (int c = threadIdx.x; c < CC; c += 64)
        xs[c] = x[((size_t)b * TT + (TT - 1)) * CC + c];
    __syncthreads();
    const int col = h * HD + threadIdx.x;
    float s = 0.f;
    for (int c = 0; c < CC; c++) s += xs[c] * Wa[(size_t)c * (3 * CC) + col];
    qlast[(b * NH + h) * HD + threadIdx.x] = s;
}

__global__ __launch_bounds__(256) void uproj_kernel(
    const float* __restrict__ Wa, const float* __restrict__ qlast,
    float* __restrict__ u)
{
    const int b = blockIdx.x;
    const int c = blockIdx.y * 16 + (threadIdx.x >> 4);
    const int h = threadIdx.x & 15;
    __shared__ float qs[CC];
    for (int i = threadIdx.x; i < CC; i += 256) qs[i] = qlast[b * CC + i];
    __syncthreads();
    const float* wrow = Wa + (size_t)c * (3 * CC) + CC + h * HD;
    const float* qh = qs + h * HD;
    float s = 0.f;
    #pragma unroll
    for (int d = 0; d < HD; d++) s += wrow[d] * qh[d];
    u[((size_t)b * CC + c) * NH + h] = s;
}

__global__ __launch_bounds__(256) void scores_kernel(
    const float* __restrict__ x, const float* __restrict__ u,
    float* __restrict__ last)
{
    const int b = blockIdx.x;
    const int t = blockIdx.y * 256 + threadIdx.x;
    __shared__ float us[128][NH];
    float acc[NH];
    #pragma unroll
    for (int h = 0; h < NH; h++) acc[h] = 0.f;
    const float* xr = x + ((size_t)b * TT + t) * CC;
    for (int c0 = 0; c0 < CC; c0 += 128) {
        __syncthreads();
        for (int i = threadIdx.x; i < 128 * NH; i += 256)
            ((float*)us)[i] = u[((size_t)b * CC + c0) * NH + i];
        __syncthreads();
        for (int ci = 0; ci < 128; ci++) {
            float xv = xr[c0 + ci];
            #pragma unroll
            for (int h = 0; h < NH; h++) acc[h] += xv * us[ci][h];
        }
    }
    #pragma unroll
    for (int h = 0; h < NH; h++)
        last[(b * NH + h) * TT + t] = acc[h] * 0.125f;
}

// ---------------- top-k set selection via bitonic sort ---------------------
__global__ __launch_bounds__(512) void topk_kernel(const float* __restrict__ last,
                                                   int* __restrict__ idxout)
{
    __shared__ unsigned long long s[TT];
    const int bh = blockIdx.x;
    const int tid = threadIdx.x;

    for (int t = tid; t < TT; t += 512) {
        unsigned u;
        if (t >= NONREC) {
            u = 0xFFFFFFFFu;
        } else {
            u = __float_as_uint(last[bh * TT + t]);
            u = (u & 0x80000000u) ? ~u : (u | 0x80000000u);
        }
        s[t] = ((unsigned long long)u << 32) | (unsigned)t;
    }
    __syncthreads();

    for (int k = 2; k <= TT; k <<= 1) {
        for (int j = k >> 1; j > 0; j >>= 1) {
            for (int i = tid; i < TT; i += 512) {
                int ix = i ^ j;
                if (ix > i) {
                    bool desc = ((i & k) == 0);
                    unsigned long long a = s[i], b = s[ix];
                    bool sw = desc ? (a < b) : (a > b);
                    if (sw) { s[i] = b; s[ix] = a; }
                }
            }
            __syncthreads();
        }
    }
    for (int i = tid; i < KKEEP; i += 512)
        idxout[bh * KKEEP + i] = (int)(s[i] & 0xFFFFFFFFu);
}

// ---------------- pruned attention; epilogue writes bf16 hi/lo --------------
#define KCHUNK 64

__global__ __launch_bounds__(128) void attn_kernel(
    const float* __restrict__ qkv, const int* __restrict__ idx,
    __nv_bfloat16* __restrict__ yh, __nv_bfloat16* __restrict__ yl)
{
    const int bh = blockIdx.x;
    const int b = bh >> 4, h = bh & 15;
    const int qt = blockIdx.y * 128 + threadIdx.x;

    __shared__ float Ks[KCHUNK][HD];
    __shared__ float Vs[KCHUNK][HD];

    float4 q4[HD / 4];
    {
        const float4* qrow = (const float4*)(qkv + ((size_t)b * TT + qt) * (3 * CC) + h * HD);
        #pragma unroll
        for (int d = 0; d < HD / 4; d++) {
            float4 v = qrow[d];
            q4[d] = make_float4(v.x * 0.125f, v.y * 0.125f, v.z * 0.125f, v.w * 0.125f);
        }
    }

    float l = 0.f;
    float4 a4[HD / 4];
    #pragma unroll
    for (int d = 0; d < HD / 4; d++) a4[d] = make_float4(0.f, 0.f, 0.f, 0.f);

    for (int c0 = 0; c0 < KKEEP; c0 += KCHUNK) {
        const int cn = min(KCHUNK, KKEEP - c0);
        __syncthreads();
        for (int i = threadIdx.x; i < cn * (HD / 4); i += 128) {
            int r = i >> 4;
            int c4 = (i & 15) * 4;
            int kt = idx[bh * KKEEP + c0 + r];
            const float* kr = qkv + ((size_t)b * TT + kt) * (3 * CC) + CC + h * HD;
            *(float4*)&Ks[r][c4] = *(const float4*)(kr + c4);
            *(float4*)&Vs[r][c4] = *(const float4*)(kr + CC + c4);
        }
        __syncthreads();

        for (int kk = 0; kk < cn; kk++) {
            const float4* kr = (const float4*)&Ks[kk][0];
            float sc = 0.f;
            #pragma unroll
            for (int d = 0; d < HD / 4; d++) {
                float4 kv = kr[d];
                sc += q4[d].x * kv.x + q4[d].y * kv.y + q4[d].z * kv.z + q4[d].w * kv.w;
            }
            float p = __expf(sc);
            l += p;
            const float4* vr = (const float4*)&Vs[kk][0];
            #pragma unroll
            for (int d = 0; d < HD / 4; d++) {
                float4 vv = vr[d];
                a4[d].x += p * vv.x; a4[d].y += p * vv.y;
                a4[d].z += p * vv.z; a4[d].w += p * vv.w;
            }
        }
    }

    const float invl = 1.f / l;
    const size_t off = ((size_t)b * TT + qt) * CC + h * HD;
    __nv_bfloat162* yh2 = (__nv_bfloat162*)(yh + off);
    __nv_bfloat162* yl2 = (__nv_bfloat162*)(yl + off);
    #pragma unroll
    for (int d = 0; d < HD / 4; d++) {
        float v0 = a4[d].x * invl, v1 = a4[d].y * invl;
        float v2 = a4[d].z * invl, v3 = a4[d].w * invl;
        __nv_bfloat16 h0, l0, h1, l1, h2, l2, h3, l3;
        split_bf16(v0, h0, l0); split_bf16(v1, h1, l1);
        split_bf16(v2, h2, l2); split_bf16(v3, h3, l3);
        yh2[d * 2 + 0] = __nv_bfloat162(h0, h1);
        yh2[d * 2 + 1] = __nv_bfloat162(h2, h3);
        yl2[d * 2 + 0] = __nv_bfloat162(l0, l1);
        yl2[d * 2 + 1] = __nv_bfloat162(l2, l3);
    }
}

// ---------------- launch ----------------------------------------------------
extern "C" void kernel_launch(void* const* d_in, const int* in_sizes, int n_in,
                              void* d_out, int out_size)
{
    const float* x  = (const float*)d_in[0];   // [4,1024,1024]
    const float* Wa = (const float*)d_in[1];   // [1024,3072]
    const float* Wp = (const float*)d_in[2];   // [1024,1024]
    float* out = (float*)d_out;                // [4,1024,1024]

    void* p;
    cudaGetSymbolAddress(&p, g_qkv);   float* qkv   = (float*)p;
    cudaGetSymbolAddress(&p, g_last);  float* last  = (float*)p;
    cudaGetSymbolAddress(&p, g_idx);   int*   idx   = (int*)p;
    cudaGetSymbolAddress(&p, g_qlast); float* qlast = (float*)p;
    cudaGetSymbolAddress(&p, g_u);     float* u     = (float*)p;
    cudaGetSymbolAddress(&p, g_xh);   __nv_bfloat16* xh  = (__nv_bfloat16*)p;
    cudaGetSymbolAddress(&p, g_xl);   __nv_bfloat16* xl  = (__nv_bfloat16*)p;
    cudaGetSymbolAddress(&p, g_wah);  __nv_bfloat16* wah = (__nv_bfloat16*)p;
    cudaGetSymbolAddress(&p, g_wal);  __nv_bfloat16* wal = (__nv_bfloat16*)p;
    cudaGetSymbolAddress(&p, g_wph);  __nv_bfloat16* wph = (__nv_bfloat16*)p;
    cudaGetSymbolAddress(&p, g_wpl);  __nv_bfloat16* wpl = (__nv_bfloat16*)p;
    cudaGetSymbolAddress(&p, g_yh);   __nv_bfloat16* yh  = (__nv_bfloat16*)p;
    cudaGetSymbolAddress(&p, g_yl);   __nv_bfloat16* yl  = (__nv_bfloat16*)p;

    cudaFuncSetAttribute(gemm_bf16x3, cudaFuncAttributeMaxDynamicSharedMemorySize, GSMEM);

    // launches 1-4: fp32 selection scores
    qlast_kernel<<<BB * NH, 64>>>(x, Wa, qlast);
    uproj_kernel<<<dim3(BB, CC / 16), 256>>>(Wa, qlast, u);
    scores_kernel<<<dim3(BB, TT / 256), 256>>>(x, u, last);
    topk_kernel<<<BB * NH, 512>>>(last, idx);

    // launch 5: merged prep (split x + transpose-split Wa, Wp)
    prep_kernel<<<PREP_TOTAL, 256>>>(x, Wa, Wp, xh, xl, wah, wal, wph, wpl);

    // launch 6 (ncu -s 5 -c 1 captures this): qkv = x @ W_attn
    gemm_bf16x3<<<dim3(3 * CC / 128, BB * TT / 128), 256, GSMEM>>>(xh, xl, wah, wal, qkv, 3 * CC);

    // launch 7: pruned attention -> yh/yl
    attn_kernel<<<dim3(BB * NH, TT / 128), 128>>>(qkv, idx, yh, yl);

    // launch 8: out = y @ W_proj
    gemm_bf16x3<<<dim3(CC / 128, BB * TT / 128), 256, GSMEM>>>(yh, yl, wph, wpl, out, CC);
}

// round 9
// speedup vs baseline: 1.2758x; 1.0063x over previous
#include <cuda_runtime.h>
#include <cuda_bf16.h>
#include <math.h>
#include <stdint.h>

// Problem constants
#define BB 4
#define TT 1024
#define CC 1024
#define NH 16
#define HD 64
#define KKEEP 391
#define REC 64
#define NONREC (TT - REC)       // 960

// ---------------- scratch (device globals; no allocation allowed) ----------
__device__ float g_qkv[BB * TT * 3 * CC];            // 50.3 MB fp32
__device__ float g_last[BB * NH * TT];
__device__ int   g_idx[BB * NH * KKEEP];
__device__ float g_qlast[BB * CC];
__device__ float g_u[BB * CC * NH];
__device__ __nv_bfloat16 g_xh[BB * TT * CC];
__device__ __nv_bfloat16 g_xl[BB * TT * CC];
__device__ __nv_bfloat16 g_wah[3 * CC * CC];         // W_attn^T hi/lo [3072][1024]
__device__ __nv_bfloat16 g_wal[3 * CC * CC];
__device__ __nv_bfloat16 g_wph[CC * CC];             // W_proj^T hi/lo
__device__ __nv_bfloat16 g_wpl[CC * CC];
__device__ __nv_bfloat16 g_yh[BB * TT * CC];
__device__ __nv_bfloat16 g_yl[BB * TT * CC];

// ---------------- helpers ---------------------------------------------------
__device__ __forceinline__ uint32_t smem_u32(const void* p) {
    uint32_t a;
    asm("{ .reg .u64 t; cvta.to.shared.u64 t, %1; cvt.u32.u64 %0, t; }" : "=r"(a) : "l"(p));
    return a;
}
__device__ __forceinline__ void cp_async16(uint32_t dst, const void* src) {
    asm volatile("cp.async.cg.shared.global [%0], [%1], 16;" :: "r"(dst), "l"(src));
}
__device__ __forceinline__ void cp_commit() {
    asm volatile("cp.async.commit_group;");
}
__device__ __forceinline__ void ldm_x4(uint32_t& r0, uint32_t& r1, uint32_t& r2, uint32_t& r3, uint32_t addr) {
    asm volatile("ldmatrix.sync.aligned.m8n8.x4.shared.b16 {%0,%1,%2,%3}, [%4];"
                 : "=r"(r0), "=r"(r1), "=r"(r2), "=r"(r3) : "r"(addr));
}
__device__ __forceinline__ void ldm_x2(uint32_t& r0, uint32_t& r1, uint32_t addr) {
    asm volatile("ldmatrix.sync.aligned.m8n8.x2.shared.b16 {%0,%1}, [%2];"
                 : "=r"(r0), "=r"(r1) : "r"(addr));
}
__device__ __forceinline__ void mma16816(float* d, const uint32_t* a, const uint32_t* b) {
    asm volatile(
        "mma.sync.aligned.m16n8k16.row.col.f32.bf16.bf16.f32 "
        "{%0,%1,%2,%3},{%4,%5,%6,%7},{%8,%9},{%0,%1,%2,%3};"
        : "+f"(d[0]), "+f"(d[1]), "+f"(d[2]), "+f"(d[3])
        : "r"(a[0]), "r"(a[1]), "r"(a[2]), "r"(a[3]), "r"(b[0]), "r"(b[1]));
}
__device__ __forceinline__ void split_bf16(float a, __nv_bfloat16& h, __nv_bfloat16& l) {
    h = __float2bfloat16(a);
    l = __float2bfloat16(a - __bfloat162float(h));
}

// ---------------- merged prep: split x + transpose-split both weights -------
// grid.x = 4096 (split x) + 3072 (Wa) + 1024 (Wp) = 8192, 256 threads
#define PREP_SPLIT 4096
#define PREP_WA (PREP_SPLIT + 3072)
#define PREP_TOTAL (PREP_WA + 1024)

__global__ __launch_bounds__(256) void prep_kernel(
    const float* __restrict__ x, const float* __restrict__ Wa, const float* __restrict__ Wp,
    __nv_bfloat16* __restrict__ xh, __nv_bfloat16* __restrict__ xl,
    __nv_bfloat16* __restrict__ wah, __nv_bfloat16* __restrict__ wal,
    __nv_bfloat16* __restrict__ wph, __nv_bfloat16* __restrict__ wpl)
{
    const int bid = blockIdx.x;
    if (bid < PREP_SPLIT) {
        // split x: 1M float4s
        int i = bid * 256 + threadIdx.x;
        float4 v = ((const float4*)x)[i];
        __nv_bfloat16 h0, h1, h2, h3, l0, l1, l2, l3;
        split_bf16(v.x, h0, l0); split_bf16(v.y, h1, l1);
        split_bf16(v.z, h2, l2); split_bf16(v.w, h3, l3);
        ((__nv_bfloat162*)xh)[i * 2 + 0] = __nv_bfloat162(h0, h1);
        ((__nv_bfloat162*)xh)[i * 2 + 1] = __nv_bfloat162(h2, h3);
        ((__nv_bfloat162*)xl)[i * 2 + 0] = __nv_bfloat162(l0, l1);
        ((__nv_bfloat162*)xl)[i * 2 + 1] = __nv_bfloat162(l2, l3);
        return;
    }
    // transpose-split
    const float* in;
    __nv_bfloat16 *outh, *outl;
    int rows, cols, bx, by;
    if (bid < PREP_WA) {
        int id = bid - PREP_SPLIT;
        in = Wa; outh = wah; outl = wal; rows = CC; cols = 3 * CC;
        bx = (id % 96) * 32; by = (id / 96) * 32;
    } else {
        int id = bid - PREP_WA;
        in = Wp; outh = wph; outl = wpl; rows = CC; cols = CC;
        bx = (id % 32) * 32; by = (id / 32) * 32;
    }
    __shared__ float t[32][33];
    const int tx = threadIdx.x & 31, ty = threadIdx.x >> 5;
    int xcol = bx + tx;
    #pragma unroll
    for (int j = ty; j < 32; j += 8)
        t[j][tx] = in[(size_t)(by + j) * cols + xcol];
    __syncthreads();
    int xo = by + tx;
    #pragma unroll
    for (int j = ty; j < 32; j += 8) {
        float v = t[tx][j];
        __nv_bfloat16 h, l;
        split_bf16(v, h, l);
        outh[(size_t)(bx + j) * rows + xo] = h;
        outl[(size_t)(bx + j) * rows + xo] = l;
    }
}

// ---------------- mma.sync bf16 3-term GEMM, 3-stage cp.async, swizzled -----
// C[M,N] = (Ah+Al)[M,K]*(Bh+Bl)[N,K]^T, dropping Al*Bl.
// CTA 128x128, 8 warps (2m x 4n), warp tile 64x32, BK=32, single sync/chunk.
#define GK 1024
#define BKC 32
#define ARR2 (128 * 64)          // 8192 bytes per array (128 rows x 64B)
#define STG2 (4 * ARR2)          // 32768 bytes per stage
#define NSTG 3
#define GSMEM (NSTG * STG2)      // 98304

__device__ __forceinline__ void gemm_load_stage(
    uint32_t sdst, const __nv_bfloat16* Ahb, const __nv_bfloat16* Alb,
    const __nv_bfloat16* Bhb, const __nv_bfloat16* Blb, int k0, int tid)
{
    #pragma unroll
    for (int it = 0; it < 2; it++) {
        int i = tid + it * 256;
        int r = i >> 2, c = i & 3;                       // c: 16B chunk (8 bf16)
        int cs = c ^ ((r >> 1) & 3);                     // swizzled chunk
        size_t go = (size_t)r * GK + k0 + c * 8;
        uint32_t d0 = sdst + (uint32_t)(r * 64 + cs * 16);
        cp_async16(d0,            Ahb + go);
        cp_async16(d0 + ARR2,     Alb + go);
        cp_async16(d0 + 2 * ARR2, Bhb + go);
        cp_async16(d0 + 3 * ARR2, Blb + go);
    }
    cp_commit();
}

__global__ __launch_bounds__(256, 2) void gemm_bf16x3(
    const __nv_bfloat16* __restrict__ Ah, const __nv_bfloat16* __restrict__ Al,
    const __nv_bfloat16* __restrict__ Bh, const __nv_bfloat16* __restrict__ Bl,
    float* __restrict__ C, int N)
{
    extern __shared__ char dsm[];
    const uint32_t sb = smem_u32(dsm);

    const int tid = threadIdx.x;
    const int wid = tid >> 5;
    const int lane = tid & 31;
    const int wm = wid >> 2;
    const int wn = wid & 3;

    const int m0 = blockIdx.y * 128;
    const int n0 = blockIdx.x * 128;

    const __nv_bfloat16* Ahb = Ah + (size_t)m0 * GK;
    const __nv_bfloat16* Alb = Al + (size_t)m0 * GK;
    const __nv_bfloat16* Bhb = Bh + (size_t)n0 * GK;
    const __nv_bfloat16* Blb = Bl + (size_t)n0 * GK;

    float acc[4][4][4];
    #pragma unroll
    for (int i = 0; i < 4; i++)
        #pragma unroll
        for (int j = 0; j < 4; j++)
            #pragma unroll
            for (int r = 0; r < 4; r++) acc[i][j][r] = 0.f;

    const int arow = wm * 64 + (lane & 15);
    const int achk = lane >> 4;
    const uint32_t s_a = (uint32_t)((arow >> 1) & 3);
    const int brow = wn * 32 + (lane & 7);
    const int bchk = (lane >> 3) & 1;
    const uint32_t s_b = (uint32_t)((brow >> 1) & 3);

    gemm_load_stage(sb,        Ahb, Alb, Bhb, Blb, 0,   tid);
    gemm_load_stage(sb + STG2, Ahb, Alb, Bhb, Blb, BKC, tid);

    const int NCH = GK / BKC;      // 32
    for (int ch = 0; ch < NCH; ch++) {
        if (ch + 1 < NCH) {
            asm volatile("cp.async.wait_group 1;");
        } else {
            asm volatile("cp.async.wait_group 0;");
        }
        __syncthreads();
        // prefetch ch+2 AFTER the barrier: barrier proves compute(ch-1) done,
        // so overwriting stage (ch+2)%3 == (ch-1)%3 is safe. One sync/chunk.
        if (ch + 2 < NCH)
            gemm_load_stage(sb + ((ch + 2) % NSTG) * STG2, Ahb, Alb, Bhb, Blb, (ch + 2) * BKC, tid);

        const uint32_t st = sb + (ch % NSTG) * STG2;
        #pragma unroll
        for (int ks = 0; ks < 2; ks++) {
            const uint32_t kc = (uint32_t)(ks * 2);
            uint32_t af[4][4], bf[4][2], bt[4][2];
            #pragma unroll
            for (int mt = 0; mt < 4; mt++) {
                uint32_t ad = st + (uint32_t)((arow + mt * 16) * 64) + (((kc + achk) ^ s_a) << 4);
                ldm_x4(af[mt][0], af[mt][1], af[mt][2], af[mt][3], ad);
            }
            #pragma unroll
            for (int nt = 0; nt < 4; nt++) {
                uint32_t bd = st + 2 * ARR2 + (uint32_t)((brow + nt * 8) * 64) + (((kc + bchk) ^ s_b) << 4);
                ldm_x2(bf[nt][0], bf[nt][1], bd);
            }
            #pragma unroll
            for (int mt = 0; mt < 4; mt++)
                #pragma unroll
                for (int nt = 0; nt < 4; nt++) mma16816(acc[mt][nt], af[mt], bf[nt]);
            #pragma unroll
            for (int nt = 0; nt < 4; nt++) {
                uint32_t bd = st + 3 * ARR2 + (uint32_t)((brow + nt * 8) * 64) + (((kc + bchk) ^ s_b) << 4);
                ldm_x2(bt[nt][0], bt[nt][1], bd);
            }
            #pragma unroll
            for (int mt = 0; mt < 4; mt++)
                #pragma unroll
                for (int nt = 0; nt < 4; nt++) mma16816(acc[mt][nt], af[mt], bt[nt]);
            #pragma unroll
            for (int mt = 0; mt < 4; mt++) {
                uint32_t ad = st + ARR2 + (uint32_t)((arow + mt * 16) * 64) + (((kc + achk) ^ s_a) << 4);
                ldm_x4(af[mt][0], af[mt][1], af[mt][2], af[mt][3], ad);
            }
            #pragma unroll
            for (int mt = 0; mt < 4; mt++)
                #pragma unroll
                for (int nt = 0; nt < 4; nt++) mma16816(acc[mt][nt], af[mt], bf[nt]);
        }
        __syncthreads();   // protect stage reuse for the post-barrier prefetch pattern
    }

    const int mrow = m0 + wm * 64 + (lane >> 2);
    const int ncol = n0 + wn * 32 + (lane & 3) * 2;
    #pragma unroll
    for (int mt = 0; mt < 4; mt++)
        #pragma unroll
        for (int nt = 0; nt < 4; nt++) {
            float* c0 = C + (size_t)(mrow + mt * 16) * N + ncol + nt * 8;
            *(float2*)c0 = make_float2(acc[mt][nt][0], acc[mt][nt][1]);
            float* c1 = c0 + (size_t)8 * N;
            *(float2*)c1 = make_float2(acc[mt][nt][2], acc[mt][nt][3]);
        }
}

// ---------------- fp32 selection-score path ---------------------------------
__global__ __launch_bounds__(64) void qlast_kernel(
    const float* __restrict__ x, const float* __restrict__ Wa,
    float* __restrict__ qlast)
{
    const int b = blockIdx.x >> 4, h = blockIdx.x & 15;
    __shared__ float xs[CC];
    for (int c = threadIdx.x; c < CC; c += 64)
        xs[c] = x[((size_t)b * TT + (TT - 1)) * CC + c];
    __syncthreads();
    const int col = h * HD + threadIdx.x;
    float s = 0.f;
    for (int c = 0; c < CC; c++) s += xs[c] * Wa[(size_t)c * (3 * CC) + col];
    qlast[(b * NH + h) * HD + threadIdx.x] = s;
}

__global__ __launch_bounds__(256) void uproj_kernel(
    const float* __restrict__ Wa, const float* __restrict__ qlast,
    float* __restrict__ u)
{
    const int b = blockIdx.x;
    const int c = blockIdx.y * 16 + (threadIdx.x >> 4);
    const int h = threadIdx.x & 15;
    __shared__ float qs[CC];
    for (int i = threadIdx.x; i < CC; i += 256) qs[i] = qlast[b * CC + i];
    __syncthreads();
    const float* wrow = Wa + (size_t)c * (3 * CC) + CC + h * HD;
    const float* qh = qs + h * HD;
    float s = 0.f;
    #pragma unroll
    for (int d = 0; d < HD; d++) s += wrow[d] * qh[d];
    u[((size_t)b * CC + c) * NH + h] = s;
}

__global__ __launch_bounds__(256) void scores_kernel(
    const float* __restrict__ x, const float* __restrict__ u,
    float* __restrict__ last)
{
    const int b = blockIdx.x;
    const int t = blockIdx.y * 256 + threadIdx.x;
    __shared__ float us[128][NH];
    float acc[NH];
    #pragma unroll
    for (int h = 0; h < NH; h++) acc[h] = 0.f;
    const float* xr = x + ((size_t)b * TT + t) * CC;
    for (int c0 = 0; c0 < CC; c0 += 128) {
        __syncthreads();
        for (int i = threadIdx.x; i < 128 * NH; i += 256)
            ((float*)us)[i] = u[((size_t)b * CC + c0) * NH + i];
        __syncthreads();
        for (int ci = 0; ci < 128; ci++) {
            float xv = xr[c0 + ci];
            #pragma unroll
            for (int h = 0; h < NH; h++) acc[h] += xv * us[ci][h];
        }
    }
    #pragma unroll
    for (int h = 0; h < NH; h++)
        last[(b * NH + h) * TT + t] = acc[h] * 0.125f;
}

// ---------------- top-k set selection via bitonic sort ---------------------
__global__ __launch_bounds__(512) void topk_kernel(const float* __restrict__ last,
                                                   int* __restrict__ idxout)
{
    __shared__ unsigned long long s[TT];
    const int bh = blockIdx.x;
    const int tid = threadIdx.x;

    for (int t = tid; t < TT; t += 512) {
        unsigned u;
        if (t >= NONREC) {
            u = 0xFFFFFFFFu;
        } else {
            u = __float_as_uint(last[bh * TT + t]);
            u = (u & 0x80000000u) ? ~u : (u | 0x80000000u);
        }
        s[t] = ((unsigned long long)u << 32) | (unsigned)t;
    }
    __syncthreads();

    for (int k = 2; k <= TT; k <<= 1) {
        for (int j = k >> 1; j > 0; j >>= 1) {
            for (int i = tid; i < TT; i += 512) {
                int ix = i ^ j;
                if (ix > i) {
                    bool desc = ((i & k) == 0);
                    unsigned long long a = s[i], b = s[ix];
                    bool sw = desc ? (a < b) : (a > b);
                    if (sw) { s[i] = b; s[ix] = a; }
                }
            }
            __syncthreads();
        }
    }
    for (int i = tid; i < KKEEP; i += 512)
        idxout[bh * KKEEP + i] = (int)(s[i] & 0xFFFFFFFFu);
}

// ---------------- pruned attention; epilogue writes bf16 hi/lo --------------
#define KCHUNK 64

__global__ __launch_bounds__(128) void attn_kernel(
    const float* __restrict__ qkv, const int* __restrict__ idx,
    __nv_bfloat16* __restrict__ yh, __nv_bfloat16* __restrict__ yl)
{
    const int bh = blockIdx.x;
    const int b = bh >> 4, h = bh & 15;
    const int qt = blockIdx.y * 128 + threadIdx.x;

    __shared__ float Ks[KCHUNK][HD];
    __shared__ float Vs[KCHUNK][HD];

    float4 q4[HD / 4];
    {
        const float4* qrow = (const float4*)(qkv + ((size_t)b * TT + qt) * (3 * CC) + h * HD);
        #pragma unroll
        for (int d = 0; d < HD / 4; d++) {
            float4 v = qrow[d];
            q4[d] = make_float4(v.x * 0.125f, v.y * 0.125f, v.z * 0.125f, v.w * 0.125f);
        }
    }

    float l = 0.f;
    float4 a4[HD / 4];
    #pragma unroll
    for (int d = 0; d < HD / 4; d++) a4[d] = make_float4(0.f, 0.f, 0.f, 0.f);

    for (int c0 = 0; c0 < KKEEP; c0 += KCHUNK) {
        const int cn = min(KCHUNK, KKEEP - c0);
        __syncthreads();
        for (int i = threadIdx.x; i < cn * (HD / 4); i += 128) {
            int r = i >> 4;
            int c4 = (i & 15) * 4;
            int kt = idx[bh * KKEEP + c0 + r];
            const float* kr = qkv + ((size_t)b * TT + kt) * (3 * CC) + CC + h * HD;
            *(float4*)&Ks[r][c4] = *(const float4*)(kr + c4);
            *(float4*)&Vs[r][c4] = *(const float4*)(kr + CC + c4);
        }
        __syncthreads();

        for (int kk = 0; kk < cn; kk++) {
            const float4* kr = (const float4*)&Ks[kk][0];
            float sc = 0.f;
            #pragma unroll
            for (int d = 0; d < HD / 4; d++) {
                float4 kv = kr[d];
                sc += q4[d].x * kv.x + q4[d].y * kv.y + q4[d].z * kv.z + q4[d].w * kv.w;
            }
            float p = __expf(sc);
            l += p;
            const float4* vr = (const float4*)&Vs[kk][0];
            #pragma unroll
            for (int d = 0; d < HD / 4; d++) {
                float4 vv = vr[d];
                a4[d].x += p * vv.x; a4[d].y += p * vv.y;
                a4[d].z += p * vv.z; a4[d].w += p * vv.w;
            }
        }
    }

    const float invl = 1.f / l;
    const size_t off = ((size_t)b * TT + qt) * CC + h * HD;
    __nv_bfloat162* yh2 = (__nv_bfloat162*)(yh + off);
    __nv_bfloat162* yl2 = (__nv_bfloat162*)(yl + off);
    #pragma unroll
    for (int d = 0; d < HD / 4; d++) {
        float v0 = a4[d].x * invl, v1 = a4[d].y * invl;
        float v2 = a4[d].z * invl, v3 = a4[d].w * invl;
        __nv_bfloat16 h0, l0, h1, l1, h2, l2, h3, l3;
        split_bf16(v0, h0, l0); split_bf16(v1, h1, l1);
        split_bf16(v2, h2, l2); split_bf16(v3, h3, l3);
        yh2[d * 2 + 0] = __nv_bfloat162(h0, h1);
        yh2[d * 2 + 1] = __nv_bfloat162(h2, h3);
        yl2[d * 2 + 0] = __nv_bfloat162(l0, l1);
        yl2[d * 2 + 1] = __nv_bfloat162(l2, l3);
    }
}

// ---------------- launch ----------------------------------------------------
extern "C" void kernel_launch(void* const* d_in, const int* in_sizes, int n_in,
                              void* d_out, int out_size)
{
    const float* x  = (const float*)d_in[0];   // [4,1024,1024]
    const float* Wa = (const float*)d_in[1];   // [1024,3072]
    const float* Wp = (const float*)d_in[2];   // [1024,1024]
    float* out = (float*)d_out;                // [4,1024,1024]

    void* p;
    cudaGetSymbolAddress(&p, g_qkv);   float* qkv   = (float*)p;
    cudaGetSymbolAddress(&p, g_last);  float* last  = (float*)p;
    cudaGetSymbolAddress(&p, g_idx);   int*   idx   = (int*)p;
    cudaGetSymbolAddress(&p, g_qlast); float* qlast = (float*)p;
    cudaGetSymbolAddress(&p, g_u);     float* u     = (float*)p;
    cudaGetSymbolAddress(&p, g_xh);   __nv_bfloat16* xh  = (__nv_bfloat16*)p;
    cudaGetSymbolAddress(&p, g_xl);   __nv_bfloat16* xl  = (__nv_bfloat16*)p;
    cudaGetSymbolAddress(&p, g_wah);  __nv_bfloat16* wah = (__nv_bfloat16*)p;
    cudaGetSymbolAddress(&p, g_wal);  __nv_bfloat16* wal = (__nv_bfloat16*)p;
    cudaGetSymbolAddress(&p, g_wph);  __nv_bfloat16* wph = (__nv_bfloat16*)p;
    cudaGetSymbolAddress(&p, g_wpl);  __nv_bfloat16* wpl = (__nv_bfloat16*)p;
    cudaGetSymbolAddress(&p, g_yh);   __nv_bfloat16* yh  = (__nv_bfloat16*)p;
    cudaGetSymbolAddress(&p, g_yl);   __nv_bfloat16* yl  = (__nv_bfloat16*)p;

    cudaFuncSetAttribute(gemm_bf16x3, cudaFuncAttributeMaxDynamicSharedMemorySize, GSMEM);

    // launches 1-4: fp32 selection scores
    qlast_kernel<<<BB * NH, 64>>>(x, Wa, qlast);
    uproj_kernel<<<dim3(BB, CC / 16), 256>>>(Wa, qlast, u);
    scores_kernel<<<dim3(BB, TT / 256), 256>>>(x, u, last);
    topk_kernel<<<BB * NH, 512>>>(last, idx);

    // launch 5: merged prep (split x + transpose-split Wa, Wp)
    prep_kernel<<<PREP_TOTAL, 256>>>(x, Wa, Wp, xh, xl, wah, wal, wph, wpl);

    // launch 6 (ncu -s 5 -c 1 captures this): qkv = x @ W_attn
    gemm_bf16x3<<<dim3(3 * CC / 128, BB * TT / 128), 256, GSMEM>>>(xh, xl, wah, wal, qkv, 3 * CC);

    // launch 7: pruned attention -> yh/yl
    attn_kernel<<<dim3(BB * NH, TT / 128), 128>>>(qkv, idx, yh, yl);

    // launch 8: out = y @ W_proj
    gemm_bf16x3<<<dim3(CC / 128, BB * TT / 128), 256, GSMEM>>>(yh, yl, wph, wpl, out, CC);
}

// round 10
// speedup vs baseline: 1.2949x; 1.0150x over previous
#include <cuda_runtime.h>
#include <cuda_bf16.h>
#include <math.h>
#include <stdint.h>

// Problem constants
#define BB 4
#define TT 1024
#define CC 1024
#define NH 16
#define HD 64
#define KKEEP 391
#define REC 64
#define NONREC (TT - REC)       // 960

// ---------------- scratch (device globals; no allocation allowed) ----------
__device__ float g_qkv[BB * TT * 3 * CC];            // 50.3 MB fp32
__device__ float g_last[BB * NH * TT];
__device__ int   g_idx[BB * NH * KKEEP];
__device__ float g_qlast[BB * CC];
__device__ float g_u[BB * CC * NH];
__device__ __nv_bfloat16 g_xh[BB * TT * CC];
__device__ __nv_bfloat16 g_xl[BB * TT * CC];
__device__ __nv_bfloat16 g_wah[3 * CC * CC];         // W_attn^T hi/lo [3072][1024]
__device__ __nv_bfloat16 g_wal[3 * CC * CC];
__device__ __nv_bfloat16 g_wph[CC * CC];             // W_proj^T hi/lo
__device__ __nv_bfloat16 g_wpl[CC * CC];
__device__ __nv_bfloat16 g_yh[BB * TT * CC];
__device__ __nv_bfloat16 g_yl[BB * TT * CC];

// ---------------- helpers ---------------------------------------------------
__device__ __forceinline__ uint32_t smem_u32(const void* p) {
    uint32_t a;
    asm("{ .reg .u64 t; cvta.to.shared.u64 t, %1; cvt.u32.u64 %0, t; }" : "=r"(a) : "l"(p));
    return a;
}
__device__ __forceinline__ void cp_async16(uint32_t dst, const void* src) {
    asm volatile("cp.async.cg.shared.global [%0], [%1], 16;" :: "r"(dst), "l"(src));
}
__device__ __forceinline__ void cp_commit() {
    asm volatile("cp.async.commit_group;");
}
__device__ __forceinline__ void ldm_x4(uint32_t& r0, uint32_t& r1, uint32_t& r2, uint32_t& r3, uint32_t addr) {
    asm volatile("ldmatrix.sync.aligned.m8n8.x4.shared.b16 {%0,%1,%2,%3}, [%4];"
                 : "=r"(r0), "=r"(r1), "=r"(r2), "=r"(r3) : "r"(addr));
}
__device__ __forceinline__ void ldm_x2(uint32_t& r0, uint32_t& r1, uint32_t addr) {
    asm volatile("ldmatrix.sync.aligned.m8n8.x2.shared.b16 {%0,%1}, [%2];"
                 : "=r"(r0), "=r"(r1) : "r"(addr));
}
__device__ __forceinline__ void mma16816(float* d, const uint32_t* a, const uint32_t* b) {
    asm volatile(
        "mma.sync.aligned.m16n8k16.row.col.f32.bf16.bf16.f32 "
        "{%0,%1,%2,%3},{%4,%5,%6,%7},{%8,%9},{%0,%1,%2,%3};"
        : "+f"(d[0]), "+f"(d[1]), "+f"(d[2]), "+f"(d[3])
        : "r"(a[0]), "r"(a[1]), "r"(a[2]), "r"(a[3]), "r"(b[0]), "r"(b[1]));
}
__device__ __forceinline__ void split_bf16(float a, __nv_bfloat16& h, __nv_bfloat16& l) {
    h = __float2bfloat16(a);
    l = __float2bfloat16(a - __bfloat162float(h));
}

// ---------------- merged prep: split x + transpose-split both weights -------
#define PREP_SPLIT 4096
#define PREP_WA (PREP_SPLIT + 3072)
#define PREP_TOTAL (PREP_WA + 1024)

__global__ __launch_bounds__(256) void prep_kernel(
    const float* __restrict__ x, const float* __restrict__ Wa, const float* __restrict__ Wp,
    __nv_bfloat16* __restrict__ xh, __nv_bfloat16* __restrict__ xl,
    __nv_bfloat16* __restrict__ wah, __nv_bfloat16* __restrict__ wal,
    __nv_bfloat16* __restrict__ wph, __nv_bfloat16* __restrict__ wpl)
{
    const int bid = blockIdx.x;
    if (bid < PREP_SPLIT) {
        int i = bid * 256 + threadIdx.x;
        float4 v = ((const float4*)x)[i];
        __nv_bfloat16 h0, h1, h2, h3, l0, l1, l2, l3;
        split_bf16(v.x, h0, l0); split_bf16(v.y, h1, l1);
        split_bf16(v.z, h2, l2); split_bf16(v.w, h3, l3);
        ((__nv_bfloat162*)xh)[i * 2 + 0] = __nv_bfloat162(h0, h1);
        ((__nv_bfloat162*)xh)[i * 2 + 1] = __nv_bfloat162(h2, h3);
        ((__nv_bfloat162*)xl)[i * 2 + 0] = __nv_bfloat162(l0, l1);
        ((__nv_bfloat162*)xl)[i * 2 + 1] = __nv_bfloat162(l2, l3);
        return;
    }
    const float* in;
    __nv_bfloat16 *outh, *outl;
    int rows, cols, bx, by;
    if (bid < PREP_WA) {
        int id = bid - PREP_SPLIT;
        in = Wa; outh = wah; outl = wal; rows = CC; cols = 3 * CC;
        bx = (id % 96) * 32; by = (id / 96) * 32;
    } else {
        int id = bid - PREP_WA;
        in = Wp; outh = wph; outl = wpl; rows = CC; cols = CC;
        bx = (id % 32) * 32; by = (id / 32) * 32;
    }
    __shared__ float t[32][33];
    const int tx = threadIdx.x & 31, ty = threadIdx.x >> 5;
    int xcol = bx + tx;
    #pragma unroll
    for (int j = ty; j < 32; j += 8)
        t[j][tx] = in[(size_t)(by + j) * cols + xcol];
    __syncthreads();
    int xo = by + tx;
    #pragma unroll
    for (int j = ty; j < 32; j += 8) {
        float v = t[tx][j];
        __nv_bfloat16 h, l;
        split_bf16(v, h, l);
        outh[(size_t)(bx + j) * rows + xo] = h;
        outl[(size_t)(bx + j) * rows + xo] = l;
    }
}

// ---------------- mma.sync bf16 3-term GEMM (unchanged from R9) -------------
#define GK 1024
#define BKC 32
#define ARR2 (128 * 64)
#define STG2 (4 * ARR2)
#define NSTG 3
#define GSMEM (NSTG * STG2)

__device__ __forceinline__ void gemm_load_stage(
    uint32_t sdst, const __nv_bfloat16* Ahb, const __nv_bfloat16* Alb,
    const __nv_bfloat16* Bhb, const __nv_bfloat16* Blb, int k0, int tid)
{
    #pragma unroll
    for (int it = 0; it < 2; it++) {
        int i = tid + it * 256;
        int r = i >> 2, c = i & 3;
        int cs = c ^ ((r >> 1) & 3);
        size_t go = (size_t)r * GK + k0 + c * 8;
        uint32_t d0 = sdst + (uint32_t)(r * 64 + cs * 16);
        cp_async16(d0,            Ahb + go);
        cp_async16(d0 + ARR2,     Alb + go);
        cp_async16(d0 + 2 * ARR2, Bhb + go);
        cp_async16(d0 + 3 * ARR2, Blb + go);
    }
    cp_commit();
}

__global__ __launch_bounds__(256, 2) void gemm_bf16x3(
    const __nv_bfloat16* __restrict__ Ah, const __nv_bfloat16* __restrict__ Al,
    const __nv_bfloat16* __restrict__ Bh, const __nv_bfloat16* __restrict__ Bl,
    float* __restrict__ C, int N)
{
    extern __shared__ char dsm[];
    const uint32_t sb = smem_u32(dsm);

    const int tid = threadIdx.x;
    const int wid = tid >> 5;
    const int lane = tid & 31;
    const int wm = wid >> 2;
    const int wn = wid & 3;

    const int m0 = blockIdx.y * 128;
    const int n0 = blockIdx.x * 128;

    const __nv_bfloat16* Ahb = Ah + (size_t)m0 * GK;
    const __nv_bfloat16* Alb = Al + (size_t)m0 * GK;
    const __nv_bfloat16* Bhb = Bh + (size_t)n0 * GK;
    const __nv_bfloat16* Blb = Bl + (size_t)n0 * GK;

    float acc[4][4][4];
    #pragma unroll
    for (int i = 0; i < 4; i++)
        #pragma unroll
        for (int j = 0; j < 4; j++)
            #pragma unroll
            for (int r = 0; r < 4; r++) acc[i][j][r] = 0.f;

    const int arow = wm * 64 + (lane & 15);
    const int achk = lane >> 4;
    const uint32_t s_a = (uint32_t)((arow >> 1) & 3);
    const int brow = wn * 32 + (lane & 7);
    const int bchk = (lane >> 3) & 1;
    const uint32_t s_b = (uint32_t)((brow >> 1) & 3);

    gemm_load_stage(sb,        Ahb, Alb, Bhb, Blb, 0,   tid);
    gemm_load_stage(sb + STG2, Ahb, Alb, Bhb, Blb, BKC, tid);

    const int NCH = GK / BKC;
    for (int ch = 0; ch < NCH; ch++) {
        if (ch + 1 < NCH) {
            asm volatile("cp.async.wait_group 1;");
        } else {
            asm volatile("cp.async.wait_group 0;");
        }
        __syncthreads();
        if (ch + 2 < NCH)
            gemm_load_stage(sb + ((ch + 2) % NSTG) * STG2, Ahb, Alb, Bhb, Blb, (ch + 2) * BKC, tid);

        const uint32_t st = sb + (ch % NSTG) * STG2;
        #pragma unroll
        for (int ks = 0; ks < 2; ks++) {
            const uint32_t kc = (uint32_t)(ks * 2);
            uint32_t af[4][4], bf[4][2], bt[4][2];
            #pragma unroll
            for (int mt = 0; mt < 4; mt++) {
                uint32_t ad = st + (uint32_t)((arow + mt * 16) * 64) + (((kc + achk) ^ s_a) << 4);
                ldm_x4(af[mt][0], af[mt][1], af[mt][2], af[mt][3], ad);
            }
            #pragma unroll
            for (int nt = 0; nt < 4; nt++) {
                uint32_t bd = st + 2 * ARR2 + (uint32_t)((brow + nt * 8) * 64) + (((kc + bchk) ^ s_b) << 4);
                ldm_x2(bf[nt][0], bf[nt][1], bd);
            }
            #pragma unroll
            for (int mt = 0; mt < 4; mt++)
                #pragma unroll
                for (int nt = 0; nt < 4; nt++) mma16816(acc[mt][nt], af[mt], bf[nt]);
            #pragma unroll
            for (int nt = 0; nt < 4; nt++) {
                uint32_t bd = st + 3 * ARR2 + (uint32_t)((brow + nt * 8) * 64) + (((kc + bchk) ^ s_b) << 4);
                ldm_x2(bt[nt][0], bt[nt][1], bd);
            }
            #pragma unroll
            for (int mt = 0; mt < 4; mt++)
                #pragma unroll
                for (int nt = 0; nt < 4; nt++) mma16816(acc[mt][nt], af[mt], bt[nt]);
            #pragma unroll
            for (int mt = 0; mt < 4; mt++) {
                uint32_t ad = st + ARR2 + (uint32_t)((arow + mt * 16) * 64) + (((kc + achk) ^ s_a) << 4);
                ldm_x4(af[mt][0], af[mt][1], af[mt][2], af[mt][3], ad);
            }
            #pragma unroll
            for (int mt = 0; mt < 4; mt++)
                #pragma unroll
                for (int nt = 0; nt < 4; nt++) mma16816(acc[mt][nt], af[mt], bf[nt]);
        }
        __syncthreads();
    }

    const int mrow = m0 + wm * 64 + (lane >> 2);
    const int ncol = n0 + wn * 32 + (lane & 3) * 2;
    #pragma unroll
    for (int mt = 0; mt < 4; mt++)
        #pragma unroll
        for (int nt = 0; nt < 4; nt++) {
            float* c0 = C + (size_t)(mrow + mt * 16) * N + ncol + nt * 8;
            *(float2*)c0 = make_float2(acc[mt][nt][0], acc[mt][nt][1]);
            float* c1 = c0 + (size_t)8 * N;
            *(float2*)c1 = make_float2(acc[mt][nt][2], acc[mt][nt][3]);
        }
}

// ---------------- fp32 selection-score path ---------------------------------
__global__ __launch_bounds__(64) void qlast_kernel(
    const float* __restrict__ x, const float* __restrict__ Wa,
    float* __restrict__ qlast)
{
    const int b = blockIdx.x >> 4, h = blockIdx.x & 15;
    __shared__ float xs[CC];
    for (int c = threadIdx.x; c < CC; c += 64)
        xs[c] = x[((size_t)b * TT + (TT - 1)) * CC + c];
    __syncthreads();
    const int col = h * HD + threadIdx.x;
    float s = 0.f;
    for (int c = 0; c < CC; c++) s += xs[c] * Wa[(size_t)c * (3 * CC) + col];
    qlast[(b * NH + h) * HD + threadIdx.x] = s;
}

__global__ __launch_bounds__(256) void uproj_kernel(
    const float* __restrict__ Wa, const float* __restrict__ qlast,
    float* __restrict__ u)
{
    const int b = blockIdx.x;
    const int c = blockIdx.y * 16 + (threadIdx.x >> 4);
    const int h = threadIdx.x & 15;
    __shared__ float qs[CC];
    for (int i = threadIdx.x; i < CC; i += 256) qs[i] = qlast[b * CC + i];
    __syncthreads();
    const float* wrow = Wa + (size_t)c * (3 * CC) + CC + h * HD;
    const float* qh = qs + h * HD;
    float s = 0.f;
    #pragma unroll
    for (int d = 0; d < HD; d++) s += wrow[d] * qh[d];
    u[((size_t)b * CC + c) * NH + h] = s;
}

// block: 256 thr = 64 t-rows x 4 h-groups; grid (BB, TT/64) = 64 blocks
__global__ __launch_bounds__(256) void scores_kernel(
    const float* __restrict__ x, const float* __restrict__ u,
    float* __restrict__ last)
{
    const int b = blockIdx.x;
    const int tloc = threadIdx.x & 63;
    const int hg = threadIdx.x >> 6;            // 0..3 -> heads hg*4..hg*4+3
    const int t = blockIdx.y * 64 + tloc;
    __shared__ float us[128][NH];
    float acc0[4], acc1[4];
    #pragma unroll
    for (int j = 0; j < 4; j++) { acc0[j] = 0.f; acc1[j] = 0.f; }
    const float* xr = x + ((size_t)b * TT + t) * CC;
    for (int c0 = 0; c0 < CC; c0 += 128) {
        __syncthreads();
        for (int i = threadIdx.x; i < 128 * NH; i += 256)
            ((float*)us)[i] = u[((size_t)b * CC + c0) * NH + i];
        __syncthreads();
        #pragma unroll 4
        for (int ci = 0; ci < 128; ci += 2) {
            float xv0 = xr[c0 + ci];
            float xv1 = xr[c0 + ci + 1];
            #pragma unroll
            for (int j = 0; j < 4; j++) {
                acc0[j] += xv0 * us[ci][hg * 4 + j];
                acc1[j] += xv1 * us[ci + 1][hg * 4 + j];
            }
        }
    }
    #pragma unroll
    for (int j = 0; j < 4; j++)
        last[(b * NH + hg * 4 + j) * TT + t] = (acc0[j] + acc1[j]) * 0.125f;
}

// ---------------- top-k set selection via bitonic sort ---------------------
__global__ __launch_bounds__(512) void topk_kernel(const float* __restrict__ last,
                                                   int* __restrict__ idxout)
{
    __shared__ unsigned long long s[TT];
    const int bh = blockIdx.x;
    const int tid = threadIdx.x;

    for (int t = tid; t < TT; t += 512) {
        unsigned u;
        if (t >= NONREC) {
            u = 0xFFFFFFFFu;
        } else {
            u = __float_as_uint(last[bh * TT + t]);
            u = (u & 0x80000000u) ? ~u : (u | 0x80000000u);
        }
        s[t] = ((unsigned long long)u << 32) | (unsigned)t;
    }
    __syncthreads();

    for (int k = 2; k <= TT; k <<= 1) {
        for (int j = k >> 1; j > 0; j >>= 1) {
            for (int i = tid; i < TT; i += 512) {
                int ix = i ^ j;
                if (ix > i) {
                    bool desc = ((i & k) == 0);
                    unsigned long long a = s[i], b = s[ix];
                    bool sw = desc ? (a < b) : (a > b);
                    if (sw) { s[i] = b; s[ix] = a; }
                }
            }
            __syncthreads();
        }
    }
    for (int i = tid; i < KKEEP; i += 512)
        idxout[bh * KKEEP + i] = (int)(s[i] & 0xFFFFFFFFu);
}

// ---------------- pruned attention; ILP-fixed inner loop ---------------------
#define KCHUNK 64

__global__ __launch_bounds__(128, 3) void attn_kernel(
    const float* __restrict__ qkv, const int* __restrict__ idx,
    __nv_bfloat16* __restrict__ yh, __nv_bfloat16* __restrict__ yl)
{
    const int bh = blockIdx.x;
    const int b = bh >> 4, h = bh & 15;
    const int qt = blockIdx.y * 128 + threadIdx.x;

    __shared__ float Ks[KCHUNK][HD];
    __shared__ float Vs[KCHUNK][HD];

    float4 q4[HD / 4];
    {
        const float4* qrow = (const float4*)(qkv + ((size_t)b * TT + qt) * (3 * CC) + h * HD);
        #pragma unroll
        for (int d = 0; d < HD / 4; d++) {
            float4 v = qrow[d];
            q4[d] = make_float4(v.x * 0.125f, v.y * 0.125f, v.z * 0.125f, v.w * 0.125f);
        }
    }

    float l = 0.f;
    float4 a4[HD / 4];
    #pragma unroll
    for (int d = 0; d < HD / 4; d++) a4[d] = make_float4(0.f, 0.f, 0.f, 0.f);

    for (int c0 = 0; c0 < KKEEP; c0 += KCHUNK) {
        const int cn = min(KCHUNK, KKEEP - c0);
        __syncthreads();
        for (int i = threadIdx.x; i < cn * (HD / 4); i += 128) {
            int r = i >> 4;
            int c4 = (i & 15) * 4;
            int kt = idx[bh * KKEEP + c0 + r];
            const float* kr = qkv + ((size_t)b * TT + kt) * (3 * CC) + CC + h * HD;
            *(float4*)&Ks[r][c4] = *(const float4*)(kr + c4);
            *(float4*)&Vs[r][c4] = *(const float4*)(kr + CC + c4);
        }
        __syncthreads();

        #pragma unroll 2
        for (int kk = 0; kk < cn; kk++) {
            const float4* kr = (const float4*)&Ks[kk][0];
            // 8 partial score accumulators: chain length 8 FMAs instead of 64
            float sp[8];
            #pragma unroll
            for (int j = 0; j < 8; j++) sp[j] = 0.f;
            #pragma unroll
            for (int d = 0; d < HD / 4; d++) {
                float4 kv = kr[d];
                sp[d & 7] += q4[d].x * kv.x + q4[d].y * kv.y
                           + q4[d].z * kv.z + q4[d].w * kv.w;
            }
            float sc = ((sp[0] + sp[1]) + (sp[2] + sp[3]))
                     + ((sp[4] + sp[5]) + (sp[6] + sp[7]));
            float p = __expf(sc);
            l += p;
            const float4* vr = (const float4*)&Vs[kk][0];
            #pragma unroll
            for (int d = 0; d < HD / 4; d++) {
                float4 vv = vr[d];
                a4[d].x += p * vv.x; a4[d].y += p * vv.y;
                a4[d].z += p * vv.z; a4[d].w += p * vv.w;
            }
        }
    }

    const float invl = 1.f / l;
    const size_t off = ((size_t)b * TT + qt) * CC + h * HD;
    __nv_bfloat162* yh2 = (__nv_bfloat162*)(yh + off);
    __nv_bfloat162* yl2 = (__nv_bfloat162*)(yl + off);
    #pragma unroll
    for (int d = 0; d < HD / 4; d++) {
        float v0 = a4[d].x * invl, v1 = a4[d].y * invl;
        float v2 = a4[d].z * invl, v3 = a4[d].w * invl;
        __nv_bfloat16 h0, l0, h1, l1, h2, l2, h3, l3;
        split_bf16(v0, h0, l0); split_bf16(v1, h1, l1);
        split_bf16(v2, h2, l2); split_bf16(v3, h3, l3);
        yh2[d * 2 + 0] = __nv_bfloat162(h0, h1);
        yh2[d * 2 + 1] = __nv_bfloat162(h2, h3);
        yl2[d * 2 + 0] = __nv_bfloat162(l0, l1);
        yl2[d * 2 + 1] = __nv_bfloat162(l2, l3);
    }
}

// ---------------- launch ----------------------------------------------------
extern "C" void kernel_launch(void* const* d_in, const int* in_sizes, int n_in,
                              void* d_out, int out_size)
{
    const float* x  = (const float*)d_in[0];   // [4,1024,1024]
    const float* Wa = (const float*)d_in[1];   // [1024,3072]
    const float* Wp = (const float*)d_in[2];   // [1024,1024]
    float* out = (float*)d_out;                // [4,1024,1024]

    void* p;
    cudaGetSymbolAddress(&p, g_qkv);   float* qkv   = (float*)p;
    cudaGetSymbolAddress(&p, g_last);  float* last  = (float*)p;
    cudaGetSymbolAddress(&p, g_idx);   int*   idx   = (int*)p;
    cudaGetSymbolAddress(&p, g_qlast); float* qlast = (float*)p;
    cudaGetSymbolAddress(&p, g_u);     float* u     = (float*)p;
    cudaGetSymbolAddress(&p, g_xh);   __nv_bfloat16* xh  = (__nv_bfloat16*)p;
    cudaGetSymbolAddress(&p, g_xl);   __nv_bfloat16* xl  = (__nv_bfloat16*)p;
    cudaGetSymbolAddress(&p, g_wah);  __nv_bfloat16* wah = (__nv_bfloat16*)p;
    cudaGetSymbolAddress(&p, g_wal);  __nv_bfloat16* wal = (__nv_bfloat16*)p;
    cudaGetSymbolAddress(&p, g_wph);  __nv_bfloat16* wph = (__nv_bfloat16*)p;
    cudaGetSymbolAddress(&p, g_wpl);  __nv_bfloat16* wpl = (__nv_bfloat16*)p;
    cudaGetSymbolAddress(&p, g_yh);   __nv_bfloat16* yh  = (__nv_bfloat16*)p;
    cudaGetSymbolAddress(&p, g_yl);   __nv_bfloat16* yl  = (__nv_bfloat16*)p;

    cudaFuncSetAttribute(gemm_bf16x3, cudaFuncAttributeMaxDynamicSharedMemorySize, GSMEM);

    // fp32 selection scores
    qlast_kernel<<<BB * NH, 64>>>(x, Wa, qlast);
    uproj_kernel<<<dim3(BB, CC / 16), 256>>>(Wa, qlast, u);
    scores_kernel<<<dim3(BB, TT / 64), 256>>>(x, u, last);
    topk_kernel<<<BB * NH, 512>>>(last, idx);

    // merged prep (split x + transpose-split Wa, Wp)
    prep_kernel<<<PREP_TOTAL, 256>>>(x, Wa, Wp, xh, xl, wah, wal, wph, wpl);

    // qkv = x @ W_attn
    gemm_bf16x3<<<dim3(3 * CC / 128, BB * TT / 128), 256, GSMEM>>>(xh, xl, wah, wal, qkv, 3 * CC);

    // pruned attention -> yh/yl
    attn_kernel<<<dim3(BB * NH, TT / 128), 128>>>(qkv, idx, yh, yl);

    // out = y @ W_proj
    gemm_bf16x3<<<dim3(CC / 128, BB * TT / 128), 256, GSMEM>>>(yh, yl, wph, wpl, out, CC);
}

// round 11
// speedup vs baseline: 1.3032x; 1.0064x over previous
#include <cuda_runtime.h>
#include <cuda_bf16.h>
#include <math.h>
#include <stdint.h>

// Problem constants
#define BB 4
#define TT 1024
#define CC 1024
#define NH 16
#define HD 64
#define KKEEP 391
#define REC 64
#define NONREC (TT - REC)       // 960

// ---------------- scratch (device globals; no allocation allowed) ----------
__device__ float g_qkv[BB * TT * 3 * CC];            // 50.3 MB fp32
__device__ float g_last[BB * NH * TT];
__device__ int   g_idx[BB * NH * KKEEP];
__device__ float g_qlast[BB * CC];
__device__ float g_u[BB * CC * NH];
__device__ __nv_bfloat16 g_xh[BB * TT * CC];
__device__ __nv_bfloat16 g_xl[BB * TT * CC];
__device__ __nv_bfloat16 g_wah[3 * CC * CC];         // W_attn^T hi/lo [3072][1024]
__device__ __nv_bfloat16 g_wal[3 * CC * CC];
__device__ __nv_bfloat16 g_wph[CC * CC];             // W_proj^T hi/lo
__device__ __nv_bfloat16 g_wpl[CC * CC];
__device__ __nv_bfloat16 g_yh[BB * TT * CC];
__device__ __nv_bfloat16 g_yl[BB * TT * CC];

// ---------------- helpers ---------------------------------------------------
__device__ __forceinline__ uint32_t smem_u32(const void* p) {
    uint32_t a;
    asm("{ .reg .u64 t; cvta.to.shared.u64 t, %1; cvt.u32.u64 %0, t; }" : "=r"(a) : "l"(p));
    return a;
}
__device__ __forceinline__ void cp_async16(uint32_t dst, const void* src) {
    asm volatile("cp.async.cg.shared.global [%0], [%1], 16;" :: "r"(dst), "l"(src));
}
__device__ __forceinline__ void cp_commit() {
    asm volatile("cp.async.commit_group;");
}
__device__ __forceinline__ void ldm_x4(uint32_t& r0, uint32_t& r1, uint32_t& r2, uint32_t& r3, uint32_t addr) {
    asm volatile("ldmatrix.sync.aligned.m8n8.x4.shared.b16 {%0,%1,%2,%3}, [%4];"
                 : "=r"(r0), "=r"(r1), "=r"(r2), "=r"(r3) : "r"(addr));
}
__device__ __forceinline__ void ldm_x2(uint32_t& r0, uint32_t& r1, uint32_t addr) {
    asm volatile("ldmatrix.sync.aligned.m8n8.x2.shared.b16 {%0,%1}, [%2];"
                 : "=r"(r0), "=r"(r1) : "r"(addr));
}
__device__ __forceinline__ void mma16816(float* d, const uint32_t* a, const uint32_t* b) {
    asm volatile(
        "mma.sync.aligned.m16n8k16.row.col.f32.bf16.bf16.f32 "
        "{%0,%1,%2,%3},{%4,%5,%6,%7},{%8,%9},{%0,%1,%2,%3};"
        : "+f"(d[0]), "+f"(d[1]), "+f"(d[2]), "+f"(d[3])
        : "r"(a[0]), "r"(a[1]), "r"(a[2]), "r"(a[3]), "r"(b[0]), "r"(b[1]));
}
__device__ __forceinline__ void split_bf16(float a, __nv_bfloat16& h, __nv_bfloat16& l) {
    h = __float2bfloat16(a);
    l = __float2bfloat16(a - __bfloat162float(h));
}

// ---------------- merged prep: split x + transpose-split both weights -------
#define PREP_SPLIT 4096
#define PREP_WA (PREP_SPLIT + 3072)
#define PREP_TOTAL (PREP_WA + 1024)

__global__ __launch_bounds__(256) void prep_kernel(
    const float* __restrict__ x, const float* __restrict__ Wa, const float* __restrict__ Wp,
    __nv_bfloat16* __restrict__ xh, __nv_bfloat16* __restrict__ xl,
    __nv_bfloat16* __restrict__ wah, __nv_bfloat16* __restrict__ wal,
    __nv_bfloat16* __restrict__ wph, __nv_bfloat16* __restrict__ wpl)
{
    const int bid = blockIdx.x;
    if (bid < PREP_SPLIT) {
        int i = bid * 256 + threadIdx.x;
        float4 v = ((const float4*)x)[i];
        __nv_bfloat16 h0, h1, h2, h3, l0, l1, l2, l3;
        split_bf16(v.x, h0, l0); split_bf16(v.y, h1, l1);
        split_bf16(v.z, h2, l2); split_bf16(v.w, h3, l3);
        ((__nv_bfloat162*)xh)[i * 2 + 0] = __nv_bfloat162(h0, h1);
        ((__nv_bfloat162*)xh)[i * 2 + 1] = __nv_bfloat162(h2, h3);
        ((__nv_bfloat162*)xl)[i * 2 + 0] = __nv_bfloat162(l0, l1);
        ((__nv_bfloat162*)xl)[i * 2 + 1] = __nv_bfloat162(l2, l3);
        return;
    }
    const float* in;
    __nv_bfloat16 *outh, *outl;
    int rows, cols, bx, by;
    if (bid < PREP_WA) {
        int id = bid - PREP_SPLIT;
        in = Wa; outh = wah; outl = wal; rows = CC; cols = 3 * CC;
        bx = (id % 96) * 32; by = (id / 96) * 32;
    } else {
        int id = bid - PREP_WA;
        in = Wp; outh = wph; outl = wpl; rows = CC; cols = CC;
        bx = (id % 32) * 32; by = (id / 32) * 32;
    }
    __shared__ float t[32][33];
    const int tx = threadIdx.x & 31, ty = threadIdx.x >> 5;
    int xcol = bx + tx;
    #pragma unroll
    for (int j = ty; j < 32; j += 8)
        t[j][tx] = in[(size_t)(by + j) * cols + xcol];
    __syncthreads();
    int xo = by + tx;
    #pragma unroll
    for (int j = ty; j < 32; j += 8) {
        float v = t[tx][j];
        __nv_bfloat16 h, l;
        split_bf16(v, h, l);
        outh[(size_t)(bx + j) * rows + xo] = h;
        outl[(size_t)(bx + j) * rows + xo] = l;
    }
}

// ---------------- mma.sync bf16 3-term GEMM (unchanged) ---------------------
#define GK 1024
#define BKC 32
#define ARR2 (128 * 64)
#define STG2 (4 * ARR2)
#define NSTG 3
#define GSMEM (NSTG * STG2)

__device__ __forceinline__ void gemm_load_stage(
    uint32_t sdst, const __nv_bfloat16* Ahb, const __nv_bfloat16* Alb,
    const __nv_bfloat16* Bhb, const __nv_bfloat16* Blb, int k0, int tid)
{
    #pragma unroll
    for (int it = 0; it < 2; it++) {
        int i = tid + it * 256;
        int r = i >> 2, c = i & 3;
        int cs = c ^ ((r >> 1) & 3);
        size_t go = (size_t)r * GK + k0 + c * 8;
        uint32_t d0 = sdst + (uint32_t)(r * 64 + cs * 16);
        cp_async16(d0,            Ahb + go);
        cp_async16(d0 + ARR2,     Alb + go);
        cp_async16(d0 + 2 * ARR2, Bhb + go);
        cp_async16(d0 + 3 * ARR2, Blb + go);
    }
    cp_commit();
}

__global__ __launch_bounds__(256, 2) void gemm_bf16x3(
    const __nv_bfloat16* __restrict__ Ah, const __nv_bfloat16* __restrict__ Al,
    const __nv_bfloat16* __restrict__ Bh, const __nv_bfloat16* __restrict__ Bl,
    float* __restrict__ C, int N)
{
    extern __shared__ char dsm[];
    const uint32_t sb = smem_u32(dsm);

    const int tid = threadIdx.x;
    const int wid = tid >> 5;
    const int lane = tid & 31;
    const int wm = wid >> 2;
    const int wn = wid & 3;

    const int m0 = blockIdx.y * 128;
    const int n0 = blockIdx.x * 128;

    const __nv_bfloat16* Ahb = Ah + (size_t)m0 * GK;
    const __nv_bfloat16* Alb = Al + (size_t)m0 * GK;
    const __nv_bfloat16* Bhb = Bh + (size_t)n0 * GK;
    const __nv_bfloat16* Blb = Bl + (size_t)n0 * GK;

    float acc[4][4][4];
    #pragma unroll
    for (int i = 0; i < 4; i++)
        #pragma unroll
        for (int j = 0; j < 4; j++)
            #pragma unroll
            for (int r = 0; r < 4; r++) acc[i][j][r] = 0.f;

    const int arow = wm * 64 + (lane & 15);
    const int achk = lane >> 4;
    const uint32_t s_a = (uint32_t)((arow >> 1) & 3);
    const int brow = wn * 32 + (lane & 7);
    const int bchk = (lane >> 3) & 1;
    const uint32_t s_b = (uint32_t)((brow >> 1) & 3);

    gemm_load_stage(sb,        Ahb, Alb, Bhb, Blb, 0,   tid);
    gemm_load_stage(sb + STG2, Ahb, Alb, Bhb, Blb, BKC, tid);

    const int NCH = GK / BKC;
    for (int ch = 0; ch < NCH; ch++) {
        if (ch + 1 < NCH) {
            asm volatile("cp.async.wait_group 1;");
        } else {
            asm volatile("cp.async.wait_group 0;");
        }
        __syncthreads();
        if (ch + 2 < NCH)
            gemm_load_stage(sb + ((ch + 2) % NSTG) * STG2, Ahb, Alb, Bhb, Blb, (ch + 2) * BKC, tid);

        const uint32_t st = sb + (ch % NSTG) * STG2;
        #pragma unroll
        for (int ks = 0; ks < 2; ks++) {
            const uint32_t kc = (uint32_t)(ks * 2);
            uint32_t af[4][4], bf[4][2], bt[4][2];
            #pragma unroll
            for (int mt = 0; mt < 4; mt++) {
                uint32_t ad = st + (uint32_t)((arow + mt * 16) * 64) + (((kc + achk) ^ s_a) << 4);
                ldm_x4(af[mt][0], af[mt][1], af[mt][2], af[mt][3], ad);
            }
            #pragma unroll
            for (int nt = 0; nt < 4; nt++) {
                uint32_t bd = st + 2 * ARR2 + (uint32_t)((brow + nt * 8) * 64) + (((kc + bchk) ^ s_b) << 4);
                ldm_x2(bf[nt][0], bf[nt][1], bd);
            }
            #pragma unroll
            for (int mt = 0; mt < 4; mt++)
                #pragma unroll
                for (int nt = 0; nt < 4; nt++) mma16816(acc[mt][nt], af[mt], bf[nt]);
            #pragma unroll
            for (int nt = 0; nt < 4; nt++) {
                uint32_t bd = st + 3 * ARR2 + (uint32_t)((brow + nt * 8) * 64) + (((kc + bchk) ^ s_b) << 4);
                ldm_x2(bt[nt][0], bt[nt][1], bd);
            }
            #pragma unroll
            for (int mt = 0; mt < 4; mt++)
                #pragma unroll
                for (int nt = 0; nt < 4; nt++) mma16816(acc[mt][nt], af[mt], bt[nt]);
            #pragma unroll
            for (int mt = 0; mt < 4; mt++) {
                uint32_t ad = st + ARR2 + (uint32_t)((arow + mt * 16) * 64) + (((kc + achk) ^ s_a) << 4);
                ldm_x4(af[mt][0], af[mt][1], af[mt][2], af[mt][3], ad);
            }
            #pragma unroll
            for (int mt = 0; mt < 4; mt++)
                #pragma unroll
                for (int nt = 0; nt < 4; nt++) mma16816(acc[mt][nt], af[mt], bf[nt]);
        }
        __syncthreads();
    }

    const int mrow = m0 + wm * 64 + (lane >> 2);
    const int ncol = n0 + wn * 32 + (lane & 3) * 2;
    #pragma unroll
    for (int mt = 0; mt < 4; mt++)
        #pragma unroll
        for (int nt = 0; nt < 4; nt++) {
            float* c0 = C + (size_t)(mrow + mt * 16) * N + ncol + nt * 8;
            *(float2*)c0 = make_float2(acc[mt][nt][0], acc[mt][nt][1]);
            float* c1 = c0 + (size_t)8 * N;
            *(float2*)c1 = make_float2(acc[mt][nt][2], acc[mt][nt][3]);
        }
}

// ---------------- fp32 selection-score path ---------------------------------
__global__ __launch_bounds__(64) void qlast_kernel(
    const float* __restrict__ x, const float* __restrict__ Wa,
    float* __restrict__ qlast)
{
    const int b = blockIdx.x >> 4, h = blockIdx.x & 15;
    __shared__ float xs[CC];
    for (int c = threadIdx.x; c < CC; c += 64)
        xs[c] = x[((size_t)b * TT + (TT - 1)) * CC + c];
    __syncthreads();
    const int col = h * HD + threadIdx.x;
    float s = 0.f;
    for (int c = 0; c < CC; c++) s += xs[c] * Wa[(size_t)c * (3 * CC) + col];
    qlast[(b * NH + h) * HD + threadIdx.x] = s;
}

__global__ __launch_bounds__(256) void uproj_kernel(
    const float* __restrict__ Wa, const float* __restrict__ qlast,
    float* __restrict__ u)
{
    const int b = blockIdx.x;
    const int c = blockIdx.y * 16 + (threadIdx.x >> 4);
    const int h = threadIdx.x & 15;
    __shared__ float qs[CC];
    for (int i = threadIdx.x; i < CC; i += 256) qs[i] = qlast[b * CC + i];
    __syncthreads();
    const float* wrow = Wa + (size_t)c * (3 * CC) + CC + h * HD;
    const float* qh = qs + h * HD;
    float s = 0.f;
    #pragma unroll
    for (int d = 0; d < HD; d++) s += wrow[d] * qh[d];
    u[((size_t)b * CC + c) * NH + h] = s;
}

__global__ __launch_bounds__(256) void scores_kernel(
    const float* __restrict__ x, const float* __restrict__ u,
    float* __restrict__ last)
{
    const int b = blockIdx.x;
    const int tloc = threadIdx.x & 63;
    const int hg = threadIdx.x >> 6;
    const int t = blockIdx.y * 64 + tloc;
    __shared__ float us[128][NH];
    float acc0[4], acc1[4];
    #pragma unroll
    for (int j = 0; j < 4; j++) { acc0[j] = 0.f; acc1[j] = 0.f; }
    const float* xr = x + ((size_t)b * TT + t) * CC;
    for (int c0 = 0; c0 < CC; c0 += 128) {
        __syncthreads();
        for (int i = threadIdx.x; i < 128 * NH; i += 256)
            ((float*)us)[i] = u[((size_t)b * CC + c0) * NH + i];
        __syncthreads();
        #pragma unroll 4
        for (int ci = 0; ci < 128; ci += 2) {
            float xv0 = xr[c0 + ci];
            float xv1 = xr[c0 + ci + 1];
            #pragma unroll
            for (int j = 0; j < 4; j++) {
                acc0[j] += xv0 * us[ci][hg * 4 + j];
                acc1[j] += xv1 * us[ci + 1][hg * 4 + j];
            }
        }
    }
    #pragma unroll
    for (int j = 0; j < 4; j++)
        last[(b * NH + hg * 4 + j) * TT + t] = (acc0[j] + acc1[j]) * 0.125f;
}

// ---------------- top-k set selection via bitonic sort ---------------------
__global__ __launch_bounds__(512) void topk_kernel(const float* __restrict__ last,
                                                   int* __restrict__ idxout)
{
    __shared__ unsigned long long s[TT];
    const int bh = blockIdx.x;
    const int tid = threadIdx.x;

    for (int t = tid; t < TT; t += 512) {
        unsigned u;
        if (t >= NONREC) {
            u = 0xFFFFFFFFu;
        } else {
            u = __float_as_uint(last[bh * TT + t]);
            u = (u & 0x80000000u) ? ~u : (u | 0x80000000u);
        }
        s[t] = ((unsigned long long)u << 32) | (unsigned)t;
    }
    __syncthreads();

    for (int k = 2; k <= TT; k <<= 1) {
        for (int j = k >> 1; j > 0; j >>= 1) {
            for (int i = tid; i < TT; i += 512) {
                int ix = i ^ j;
                if (ix > i) {
                    bool desc = ((i & k) == 0);
                    unsigned long long a = s[i], b = s[ix];
                    bool sw = desc ? (a < b) : (a > b);
                    if (sw) { s[i] = b; s[ix] = a; }
                }
            }
            __syncthreads();
        }
    }
    for (int i = tid; i < KKEEP; i += 512)
        idxout[bh * KKEEP + i] = (int)(s[i] & 0xFFFFFFFFu);
}

// ---------------- pruned attention; cp.async double-buffered KV gather ------
#define AKC 64
#define ASTG_F (AKC * HD * 2)            // floats per stage (K+V) = 8192
#define ASTG_B (ASTG_F * 4)              // 32768 bytes
#define ASMEM (2 * ASTG_B)               // 65536

__device__ __forceinline__ void attn_prefetch(
    uint32_t sbase, int s, const float* qkv, const int* idxp,
    int b, int h, int c0, int cn, int tid)
{
    const uint32_t dst = sbase + (uint32_t)s * ASTG_B;
    for (int i = tid; i < cn * 16; i += 128) {
        int r = i >> 4;
        int c4 = i & 15;
        int kt = idxp[c0 + r];
        const float* kr = qkv + ((size_t)b * TT + kt) * (3 * CC) + CC + h * HD + c4 * 4;
        uint32_t off = (uint32_t)(r * 256 + c4 * 16);
        cp_async16(dst + off, kr);                 // K row
        cp_async16(dst + 16384 + off, kr + CC);    // V row
    }
    cp_commit();
}

__global__ __launch_bounds__(128, 3) void attn_kernel(
    const float* __restrict__ qkv, const int* __restrict__ idx,
    __nv_bfloat16* __restrict__ yh, __nv_bfloat16* __restrict__ yl)
{
    extern __shared__ float akv[];
    const uint32_t sb = smem_u32(akv);
    const int tid = threadIdx.x;
    const int bh = blockIdx.x;
    const int b = bh >> 4, h = bh & 15;
    const int qt = blockIdx.y * 128 + tid;
    const int* idxp = idx + bh * KKEEP;

    float4 q4[HD / 4];
    {
        const float4* qrow = (const float4*)(qkv + ((size_t)b * TT + qt) * (3 * CC) + h * HD);
        #pragma unroll
        for (int d = 0; d < HD / 4; d++) {
            float4 v = qrow[d];
            q4[d] = make_float4(v.x * 0.125f, v.y * 0.125f, v.z * 0.125f, v.w * 0.125f);
        }
    }

    float l = 0.f;
    float4 a4[HD / 4];
    #pragma unroll
    for (int d = 0; d < HD / 4; d++) a4[d] = make_float4(0.f, 0.f, 0.f, 0.f);

    const int nch = (KKEEP + AKC - 1) / AKC;       // 7
    attn_prefetch(sb, 0, qkv, idxp, b, h, 0, AKC < KKEEP ? AKC : KKEEP, tid);

    for (int ch = 0; ch < nch; ch++) {
        __syncthreads();   // all threads done with the stage we're about to overwrite
        if (ch + 1 < nch) {
            int c1 = (ch + 1) * AKC;
            attn_prefetch(sb, (ch + 1) & 1, qkv, idxp, b, h, c1,
                          min(AKC, KKEEP - c1), tid);
            asm volatile("cp.async.wait_group 1;");
        } else {
            asm volatile("cp.async.wait_group 0;");
        }
        __syncthreads();

        const float* Ks = akv + (ch & 1) * ASTG_F;
        const float* Vs = Ks + AKC * HD;
        const int cn = min(AKC, KKEEP - ch * AKC);

        #pragma unroll 2
        for (int kk = 0; kk < cn; kk++) {
            const float4* kr = (const float4*)(Ks + kk * HD);
            float sp[8];
            #pragma unroll
            for (int j = 0; j < 8; j++) sp[j] = 0.f;
            #pragma unroll
            for (int d = 0; d < HD / 4; d++) {
                float4 kv = kr[d];
                sp[d & 7] += q4[d].x * kv.x + q4[d].y * kv.y
                           + q4[d].z * kv.z + q4[d].w * kv.w;
            }
            float sc = ((sp[0] + sp[1]) + (sp[2] + sp[3]))
                     + ((sp[4] + sp[5]) + (sp[6] + sp[7]));
            float p = __expf(sc);
            l += p;
            const float4* vr = (const float4*)(Vs + kk * HD);
            #pragma unroll
            for (int d = 0; d < HD / 4; d++) {
                float4 vv = vr[d];
                a4[d].x += p * vv.x; a4[d].y += p * vv.y;
                a4[d].z += p * vv.z; a4[d].w += p * vv.w;
            }
        }
    }

    const float invl = 1.f / l;
    const size_t off = ((size_t)b * TT + qt) * CC + h * HD;
    __nv_bfloat162* yh2 = (__nv_bfloat162*)(yh + off);
    __nv_bfloat162* yl2 = (__nv_bfloat162*)(yl + off);
    #pragma unroll
    for (int d = 0; d < HD / 4; d++) {
        float v0 = a4[d].x * invl, v1 = a4[d].y * invl;
        float v2 = a4[d].z * invl, v3 = a4[d].w * invl;
        __nv_bfloat16 h0, l0, h1, l1, h2, l2, h3, l3;
        split_bf16(v0, h0, l0); split_bf16(v1, h1, l1);
        split_bf16(v2, h2, l2); split_bf16(v3, h3, l3);
        yh2[d * 2 + 0] = __nv_bfloat162(h0, h1);
        yh2[d * 2 + 1] = __nv_bfloat162(h2, h3);
        yl2[d * 2 + 0] = __nv_bfloat162(l0, l1);
        yl2[d * 2 + 1] = __nv_bfloat162(l2, l3);
    }
}

// ---------------- launch ----------------------------------------------------
extern "C" void kernel_launch(void* const* d_in, const int* in_sizes, int n_in,
                              void* d_out, int out_size)
{
    const float* x  = (const float*)d_in[0];   // [4,1024,1024]
    const float* Wa = (const float*)d_in[1];   // [1024,3072]
    const float* Wp = (const float*)d_in[2];   // [1024,1024]
    float* out = (float*)d_out;                // [4,1024,1024]

    void* p;
    cudaGetSymbolAddress(&p, g_qkv);   float* qkv   = (float*)p;
    cudaGetSymbolAddress(&p, g_last);  float* last  = (float*)p;
    cudaGetSymbolAddress(&p, g_idx);   int*   idx   = (int*)p;
    cudaGetSymbolAddress(&p, g_qlast); float* qlast = (float*)p;
    cudaGetSymbolAddress(&p, g_u);     float* u     = (float*)p;
    cudaGetSymbolAddress(&p, g_xh);   __nv_bfloat16* xh  = (__nv_bfloat16*)p;
    cudaGetSymbolAddress(&p, g_xl);   __nv_bfloat16* xl  = (__nv_bfloat16*)p;
    cudaGetSymbolAddress(&p, g_wah);  __nv_bfloat16* wah = (__nv_bfloat16*)p;
    cudaGetSymbolAddress(&p, g_wal);  __nv_bfloat16* wal = (__nv_bfloat16*)p;
    cudaGetSymbolAddress(&p, g_wph);  __nv_bfloat16* wph = (__nv_bfloat16*)p;
    cudaGetSymbolAddress(&p, g_wpl);  __nv_bfloat16* wpl = (__nv_bfloat16*)p;
    cudaGetSymbolAddress(&p, g_yh);   __nv_bfloat16* yh  = (__nv_bfloat16*)p;
    cudaGetSymbolAddress(&p, g_yl);   __nv_bfloat16* yl  = (__nv_bfloat16*)p;

    cudaFuncSetAttribute(gemm_bf16x3, cudaFuncAttributeMaxDynamicSharedMemorySize, GSMEM);
    cudaFuncSetAttribute(attn_kernel, cudaFuncAttributeMaxDynamicSharedMemorySize, ASMEM);

    // slot 1-3: qlast, uproj, prep (all independent of qkv)
    qlast_kernel<<<BB * NH, 64>>>(x, Wa, qlast);
    uproj_kernel<<<dim3(BB, CC / 16), 256>>>(Wa, qlast, u);
    prep_kernel<<<PREP_TOTAL, 256>>>(x, Wa, Wp, xh, xl, wah, wal, wph, wpl);

    // slot 4 (ncu captures this): qkv = x @ W_attn
    gemm_bf16x3<<<dim3(3 * CC / 128, BB * TT / 128), 256, GSMEM>>>(xh, xl, wah, wal, qkv, 3 * CC);

    // slot 5-6: selection scores + topk
    scores_kernel<<<dim3(BB, TT / 64), 256>>>(x, u, last);
    topk_kernel<<<BB * NH, 512>>>(last, idx);

    // slot 7: pruned attention -> yh/yl (cp.async double-buffered gather)
    attn_kernel<<<dim3(BB * NH, TT / 128), 128, ASMEM>>>(qkv, idx, yh, yl);

    // slot 8: out = y @ W_proj
    gemm_bf16x3<<<dim3(CC / 128, BB * TT / 128), 256, GSMEM>>>(yh, yl, wph, wpl, out, CC);
}

// round 12
// speedup vs baseline: 1.6425x; 1.2603x over previous
#include <cuda_runtime.h>
#include <cuda_bf16.h>
#include <math.h>
#include <stdint.h>

// Problem constants
#define BB 4
#define TT 1024
#define CC 1024
#define NH 16
#define HD 64
#define KKEEP 391
#define REC 64
#define NONREC (TT - REC)       // 960

// ---------------- scratch (device globals; no allocation allowed) ----------
__device__ float g_last[BB * NH * TT];
__device__ int   g_idx[BB * NH * KKEEP];
__device__ float g_qlast[BB * CC];
__device__ float g_u[BB * CC * NH];
__device__ __nv_bfloat16 g_xh[BB * TT * CC];
__device__ __nv_bfloat16 g_xl[BB * TT * CC];
__device__ __nv_bfloat16 g_wah[3 * CC * CC];         // W_attn^T hi/lo [3072][1024]
__device__ __nv_bfloat16 g_wal[3 * CC * CC];
__device__ __nv_bfloat16 g_wph[CC * CC];             // W_proj^T hi/lo
__device__ __nv_bfloat16 g_wpl[CC * CC];
__device__ __nv_bfloat16 g_yh[BB * TT * CC];
__device__ __nv_bfloat16 g_yl[BB * TT * CC];
// split QKV (written by gemm_qkv epilogue)
__device__ __nv_bfloat16 g_qh[BB * TT * CC];         // Q * 0.125, hi/lo
__device__ __nv_bfloat16 g_ql[BB * TT * CC];
__device__ __nv_bfloat16 g_kh[BB * TT * CC];
__device__ __nv_bfloat16 g_kl[BB * TT * CC];
__device__ __nv_bfloat16 g_vh[BB * TT * CC];
__device__ __nv_bfloat16 g_vl[BB * TT * CC];

// ---------------- helpers ---------------------------------------------------
__device__ __forceinline__ uint32_t smem_u32(const void* p) {
    uint32_t a;
    asm("{ .reg .u64 t; cvta.to.shared.u64 t, %1; cvt.u32.u64 %0, t; }" : "=r"(a) : "l"(p));
    return a;
}
__device__ __forceinline__ void cp_async16(uint32_t dst, const void* src) {
    asm volatile("cp.async.cg.shared.global [%0], [%1], 16;" :: "r"(dst), "l"(src));
}
__device__ __forceinline__ void cp_commit() {
    asm volatile("cp.async.commit_group;");
}
__device__ __forceinline__ void ldm_x4(uint32_t& r0, uint32_t& r1, uint32_t& r2, uint32_t& r3, uint32_t addr) {
    asm volatile("ldmatrix.sync.aligned.m8n8.x4.shared.b16 {%0,%1,%2,%3}, [%4];"
                 : "=r"(r0), "=r"(r1), "=r"(r2), "=r"(r3) : "r"(addr));
}
__device__ __forceinline__ void ldm_x2(uint32_t& r0, uint32_t& r1, uint32_t addr) {
    asm volatile("ldmatrix.sync.aligned.m8n8.x2.shared.b16 {%0,%1}, [%2];"
                 : "=r"(r0), "=r"(r1) : "r"(addr));
}
__device__ __forceinline__ void ldm_x4t(uint32_t* r, uint32_t addr) {
    asm volatile("ldmatrix.sync.aligned.m8n8.x4.trans.shared.b16 {%0,%1,%2,%3}, [%4];"
                 : "=r"(r[0]), "=r"(r[1]), "=r"(r[2]), "=r"(r[3]) : "r"(addr));
}
__device__ __forceinline__ void mma16816(float* d, const uint32_t* a, const uint32_t* b) {
    asm volatile(
        "mma.sync.aligned.m16n8k16.row.col.f32.bf16.bf16.f32 "
        "{%0,%1,%2,%3},{%4,%5,%6,%7},{%8,%9},{%0,%1,%2,%3};"
        : "+f"(d[0]), "+f"(d[1]), "+f"(d[2]), "+f"(d[3])
        : "r"(a[0]), "r"(a[1]), "r"(a[2]), "r"(a[3]), "r"(b[0]), "r"(b[1]));
}
__device__ __forceinline__ void split_bf16(float a, __nv_bfloat16& h, __nv_bfloat16& l) {
    h = __float2bfloat16(a);
    l = __float2bfloat16(a - __bfloat162float(h));
}
__device__ __forceinline__ uint32_t pack_bf16(float lo, float hi) {
    __nv_bfloat162 t(__float2bfloat16(lo), __float2bfloat16(hi));
    return *(uint32_t*)&t;
}
// split v0,v1 into hi/lo bf16x2 words
__device__ __forceinline__ void split_pair(float v0, float v1, uint32_t& wh, uint32_t& wl) {
    __nv_bfloat16 h0, l0, h1, l1;
    split_bf16(v0, h0, l0); split_bf16(v1, h1, l1);
    __nv_bfloat162 th(h0, h1), tl(l0, l1);
    wh = *(uint32_t*)&th; wl = *(uint32_t*)&tl;
}

// ---------------- merged prep: split x + transpose-split both weights -------
#define PREP_SPLIT 4096
#define PREP_WA (PREP_SPLIT + 3072)
#define PREP_TOTAL (PREP_WA + 1024)

__global__ __launch_bounds__(256) void prep_kernel(
    const float* __restrict__ x, const float* __restrict__ Wa, const float* __restrict__ Wp,
    __nv_bfloat16* __restrict__ xh, __nv_bfloat16* __restrict__ xl,
    __nv_bfloat16* __restrict__ wah, __nv_bfloat16* __restrict__ wal,
    __nv_bfloat16* __restrict__ wph, __nv_bfloat16* __restrict__ wpl)
{
    const int bid = blockIdx.x;
    if (bid < PREP_SPLIT) {
        int i = bid * 256 + threadIdx.x;
        float4 v = ((const float4*)x)[i];
        uint32_t h01, l01, h23, l23;
        split_pair(v.x, v.y, h01, l01);
        split_pair(v.z, v.w, h23, l23);
        ((uint32_t*)xh)[i * 2 + 0] = h01;
        ((uint32_t*)xh)[i * 2 + 1] = h23;
        ((uint32_t*)xl)[i * 2 + 0] = l01;
        ((uint32_t*)xl)[i * 2 + 1] = l23;
        return;
    }
    const float* in;
    __nv_bfloat16 *outh, *outl;
    int rows, cols, bx, by;
    if (bid < PREP_WA) {
        int id = bid - PREP_SPLIT;
        in = Wa; outh = wah; outl = wal; rows = CC; cols = 3 * CC;
        bx = (id % 96) * 32; by = (id / 96) * 32;
    } else {
        int id = bid - PREP_WA;
        in = Wp; outh = wph; outl = wpl; rows = CC; cols = CC;
        bx = (id % 32) * 32; by = (id / 32) * 32;
    }
    __shared__ float t[32][33];
    const int tx = threadIdx.x & 31, ty = threadIdx.x >> 5;
    int xcol = bx + tx;
    #pragma unroll
    for (int j = ty; j < 32; j += 8)
        t[j][tx] = in[(size_t)(by + j) * cols + xcol];
    __syncthreads();
    int xo = by + tx;
    #pragma unroll
    for (int j = ty; j < 32; j += 8) {
        float v = t[tx][j];
        __nv_bfloat16 h, l;
        split_bf16(v, h, l);
        outh[(size_t)(bx + j) * rows + xo] = h;
        outl[(size_t)(bx + j) * rows + xo] = l;
    }
}

// ---------------- mma.sync bf16 3-term GEMM core ----------------------------
#define GK 1024
#define BKC 32
#define ARR2 (128 * 64)
#define STG2 (4 * ARR2)
#define NSTG 3
#define GSMEM (NSTG * STG2)

__device__ __forceinline__ void gemm_load_stage(
    uint32_t sdst, const __nv_bfloat16* Ahb, const __nv_bfloat16* Alb,
    const __nv_bfloat16* Bhb, const __nv_bfloat16* Blb, int k0, int tid)
{
    #pragma unroll
    for (int it = 0; it < 2; it++) {
        int i = tid + it * 256;
        int r = i >> 2, c = i & 3;
        int cs = c ^ ((r >> 1) & 3);
        size_t go = (size_t)r * GK + k0 + c * 8;
        uint32_t d0 = sdst + (uint32_t)(r * 64 + cs * 16);
        cp_async16(d0,            Ahb + go);
        cp_async16(d0 + ARR2,     Alb + go);
        cp_async16(d0 + 2 * ARR2, Bhb + go);
        cp_async16(d0 + 3 * ARR2, Blb + go);
    }
    cp_commit();
}

// mainloop shared by both GEMM kernels; leaves results in acc
#define GEMM_MAIN(acc, Ah, Al, Bh, Bl)                                          \
    extern __shared__ char dsm[];                                               \
    const uint32_t sb = smem_u32(dsm);                                          \
    const int tid = threadIdx.x;                                                \
    const int wid = tid >> 5;                                                   \
    const int lane = tid & 31;                                                  \
    const int wm = wid >> 2;                                                    \
    const int wn = wid & 3;                                                     \
    const int m0 = blockIdx.y * 128;                                            \
    const int n0 = blockIdx.x * 128;                                            \
    const __nv_bfloat16* Ahb = Ah + (size_t)m0 * GK;                            \
    const __nv_bfloat16* Alb = Al + (size_t)m0 * GK;                            \
    const __nv_bfloat16* Bhb = Bh + (size_t)n0 * GK;                            \
    const __nv_bfloat16* Blb = Bl + (size_t)n0 * GK;                            \
    float acc[4][4][4];                                                         \
    _Pragma("unroll")                                                           \
    for (int i = 0; i < 4; i++)                                                 \
        _Pragma("unroll")                                                       \
        for (int j = 0; j < 4; j++)                                             \
            _Pragma("unroll")                                                   \
            for (int r = 0; r < 4; r++) acc[i][j][r] = 0.f;                     \
    const int arow = wm * 64 + (lane & 15);                                     \
    const int achk = lane >> 4;                                                 \
    const uint32_t s_a = (uint32_t)((arow >> 1) & 3);                           \
    const int brow = wn * 32 + (lane & 7);                                      \
    const int bchk = (lane >> 3) & 1;                                           \
    const uint32_t s_b = (uint32_t)((brow >> 1) & 3);                           \
    gemm_load_stage(sb,        Ahb, Alb, Bhb, Blb, 0,   tid);                   \
    gemm_load_stage(sb + STG2, Ahb, Alb, Bhb, Blb, BKC, tid);                   \
    const int NCH = GK / BKC;                                                   \
    for (int ch = 0; ch < NCH; ch++) {                                          \
        if (ch + 1 < NCH) { asm volatile("cp.async.wait_group 1;"); }           \
        else              { asm volatile("cp.async.wait_group 0;"); }           \
        __syncthreads();                                                        \
        if (ch + 2 < NCH)                                                       \
            gemm_load_stage(sb + ((ch + 2) % NSTG) * STG2, Ahb, Alb, Bhb, Blb,  \
                            (ch + 2) * BKC, tid);                               \
        const uint32_t st = sb + (ch % NSTG) * STG2;                            \
        _Pragma("unroll")                                                       \
        for (int ks = 0; ks < 2; ks++) {                                        \
            const uint32_t kc = (uint32_t)(ks * 2);                             \
            uint32_t af[4][4], bf[4][2], bt[4][2];                              \
            _Pragma("unroll")                                                   \
            for (int mt = 0; mt < 4; mt++) {                                    \
                uint32_t ad = st + (uint32_t)((arow + mt * 16) * 64) + (((kc + achk) ^ s_a) << 4); \
                ldm_x4(af[mt][0], af[mt][1], af[mt][2], af[mt][3], ad);         \
            }                                                                   \
            _Pragma("unroll")                                                   \
            for (int nt = 0; nt < 4; nt++) {                                    \
                uint32_t bd = st + 2 * ARR2 + (uint32_t)((brow + nt * 8) * 64) + (((kc + bchk) ^ s_b) << 4); \
                ldm_x2(bf[nt][0], bf[nt][1], bd);                               \
            }                                                                   \
            _Pragma("unroll")                                                   \
            for (int mt = 0; mt < 4; mt++)                                      \
                _Pragma("unroll")                                               \
                for (int nt = 0; nt < 4; nt++) mma16816(acc[mt][nt], af[mt], bf[nt]); \
            _Pragma("unroll")                                                   \
            for (int nt = 0; nt < 4; nt++) {                                    \
                uint32_t bd = st + 3 * ARR2 + (uint32_t)((brow + nt * 8) * 64) + (((kc + bchk) ^ s_b) << 4); \
                ldm_x2(bt[nt][0], bt[nt][1], bd);                               \
            }                                                                   \
            _Pragma("unroll")                                                   \
            for (int mt = 0; mt < 4; mt++)                                      \
                _Pragma("unroll")                                               \
                for (int nt = 0; nt < 4; nt++) mma16816(acc[mt][nt], af[mt], bt[nt]); \
            _Pragma("unroll")                                                   \
            for (int mt = 0; mt < 4; mt++) {                                    \
                uint32_t ad = st + ARR2 + (uint32_t)((arow + mt * 16) * 64) + (((kc + achk) ^ s_a) << 4); \
                ldm_x4(af[mt][0], af[mt][1], af[mt][2], af[mt][3], ad);         \
            }                                                                   \
            _Pragma("unroll")                                                   \
            for (int mt = 0; mt < 4; mt++)                                      \
                _Pragma("unroll")                                               \
                for (int nt = 0; nt < 4; nt++) mma16816(acc[mt][nt], af[mt], bf[nt]); \
        }                                                                       \
        __syncthreads();                                                        \
    }

// GEMM2: fp32 C output
__global__ __launch_bounds__(256, 2) void gemm_bf16x3(
    const __nv_bfloat16* __restrict__ Ah, const __nv_bfloat16* __restrict__ Al,
    const __nv_bfloat16* __restrict__ Bh, const __nv_bfloat16* __restrict__ Bl,
    float* __restrict__ C, int N)
{
    GEMM_MAIN(acc, Ah, Al, Bh, Bl)
    const int mrow = m0 + wm * 64 + (lane >> 2);
    const int ncol = n0 + wn * 32 + (lane & 3) * 2;
    #pragma unroll
    for (int mt = 0; mt < 4; mt++)
        #pragma unroll
        for (int nt = 0; nt < 4; nt++) {
            float* c0 = C + (size_t)(mrow + mt * 16) * N + ncol + nt * 8;
            *(float2*)c0 = make_float2(acc[mt][nt][0], acc[mt][nt][1]);
            float* c1 = c0 + (size_t)8 * N;
            *(float2*)c1 = make_float2(acc[mt][nt][2], acc[mt][nt][3]);
        }
}

// GEMM1: N=3072 fixed; epilogue splits into q(scaled)/k/v bf16 hi/lo
__global__ __launch_bounds__(256, 2) void gemm_qkv(
    const __nv_bfloat16* __restrict__ Ah, const __nv_bfloat16* __restrict__ Al,
    const __nv_bfloat16* __restrict__ Bh, const __nv_bfloat16* __restrict__ Bl,
    __nv_bfloat16* __restrict__ qh, __nv_bfloat16* __restrict__ ql,
    __nv_bfloat16* __restrict__ kh, __nv_bfloat16* __restrict__ kl,
    __nv_bfloat16* __restrict__ vh, __nv_bfloat16* __restrict__ vl)
{
    GEMM_MAIN(acc, Ah, Al, Bh, Bl)
    const int region = n0 >> 10;
    __nv_bfloat16 *oh, *ol;
    float sc;
    if (region == 0)      { oh = qh; ol = ql; sc = 0.125f; }
    else if (region == 1) { oh = kh; ol = kl; sc = 1.f; }
    else                  { oh = vh; ol = vl; sc = 1.f; }
    const int mrow = m0 + wm * 64 + (lane >> 2);
    const int colr = (n0 & 1023) + wn * 32 + (lane & 3) * 2;
    #pragma unroll
    for (int mt = 0; mt < 4; mt++)
        #pragma unroll
        for (int nt = 0; nt < 4; nt++) {
            size_t o0 = (size_t)(mrow + mt * 16) * CC + colr + nt * 8;
            uint32_t wh, wl;
            split_pair(acc[mt][nt][0] * sc, acc[mt][nt][1] * sc, wh, wl);
            *(uint32_t*)(oh + o0) = wh;
            *(uint32_t*)(ol + o0) = wl;
            size_t o1 = o0 + (size_t)8 * CC;
            split_pair(acc[mt][nt][2] * sc, acc[mt][nt][3] * sc, wh, wl);
            *(uint32_t*)(oh + o1) = wh;
            *(uint32_t*)(ol + o1) = wl;
        }
}

// ---------------- fp32 selection-score path ---------------------------------
__global__ __launch_bounds__(64) void qlast_kernel(
    const float* __restrict__ x, const float* __restrict__ Wa,
    float* __restrict__ qlast)
{
    const int b = blockIdx.x >> 4, h = blockIdx.x & 15;
    __shared__ float xs[CC];
    for (int c = threadIdx.x; c < CC; c += 64)
        xs[c] = x[((size_t)b * TT + (TT - 1)) * CC + c];
    __syncthreads();
    const int col = h * HD + threadIdx.x;
    float s = 0.f;
    for (int c = 0; c < CC; c++) s += xs[c] * Wa[(size_t)c * (3 * CC) + col];
    qlast[(b * NH + h) * HD + threadIdx.x] = s;
}

__global__ __launch_bounds__(256) void uproj_kernel(
    const float* __restrict__ Wa, const float* __restrict__ qlast,
    float* __restrict__ u)
{
    const int b = blockIdx.x;
    const int c = blockIdx.y * 16 + (threadIdx.x >> 4);
    const int h = threadIdx.x & 15;
    __shared__ float qs[CC];
    for (int i = threadIdx.x; i < CC; i += 256) qs[i] = qlast[b * CC + i];
    __syncthreads();
    const float* wrow = Wa + (size_t)c * (3 * CC) + CC + h * HD;
    const float* qh = qs + h * HD;
    float s = 0.f;
    #pragma unroll
    for (int d = 0; d < HD; d++) s += wrow[d] * qh[d];
    u[((size_t)b * CC + c) * NH + h] = s;
}

__global__ __launch_bounds__(256) void scores_kernel(
    const float* __restrict__ x, const float* __restrict__ u,
    float* __restrict__ last)
{
    const int b = blockIdx.x;
    const int tloc = threadIdx.x & 63;
    const int hg = threadIdx.x >> 6;
    const int t = blockIdx.y * 64 + tloc;
    __shared__ float us[128][NH];
    float acc0[4], acc1[4];
    #pragma unroll
    for (int j = 0; j < 4; j++) { acc0[j] = 0.f; acc1[j] = 0.f; }
    const float* xr = x + ((size_t)b * TT + t) * CC;
    for (int c0 = 0; c0 < CC; c0 += 128) {
        __syncthreads();
        for (int i = threadIdx.x; i < 128 * NH; i += 256)
            ((float*)us)[i] = u[((size_t)b * CC + c0) * NH + i];
        __syncthreads();
        #pragma unroll 4
        for (int ci = 0; ci < 128; ci += 2) {
            float xv0 = xr[c0 + ci];
            float xv1 = xr[c0 + ci + 1];
            #pragma unroll
            for (int j = 0; j < 4; j++) {
                acc0[j] += xv0 * us[ci][hg * 4 + j];
                acc1[j] += xv1 * us[ci + 1][hg * 4 + j];
            }
        }
    }
    #pragma unroll
    for (int j = 0; j < 4; j++)
        last[(b * NH + hg * 4 + j) * TT + t] = (acc0[j] + acc1[j]) * 0.125f;
}

// ---------------- top-k set selection via bitonic sort ---------------------
__global__ __launch_bounds__(512) void topk_kernel(const float* __restrict__ last,
                                                   int* __restrict__ idxout)
{
    __shared__ unsigned long long s[TT];
    const int bh = blockIdx.x;
    const int tid = threadIdx.x;

    for (int t = tid; t < TT; t += 512) {
        unsigned u;
        if (t >= NONREC) {
            u = 0xFFFFFFFFu;
        } else {
            u = __float_as_uint(last[bh * TT + t]);
            u = (u & 0x80000000u) ? ~u : (u | 0x80000000u);
        }
        s[t] = ((unsigned long long)u << 32) | (unsigned)t;
    }
    __syncthreads();

    for (int k = 2; k <= TT; k <<= 1) {
        for (int j = k >> 1; j > 0; j >>= 1) {
            for (int i = tid; i < TT; i += 512) {
                int ix = i ^ j;
                if (ix > i) {
                    bool desc = ((i & k) == 0);
                    unsigned long long a = s[i], b = s[ix];
                    bool sw = desc ? (a < b) : (a > b);
                    if (sw) { s[i] = b; s[ix] = a; }
                }
            }
            __syncthreads();
        }
    }
    for (int i = tid; i < KKEEP; i += 512)
        idxout[bh * KKEEP + i] = (int)(s[i] & 0xFFFFFFFFu);
}

// ---------------- mma-based pruned attention --------------------------------
// CTA: one (b,h) x 128-query tile; 4 warps, each owns 32 query rows.
// smem: Q hi/lo [128][64]bf16 (16KB each) + 2 KV stages (KH,KL,VH,VL 8KB each)
#define ASMEM (32768 + 2 * 32768)        // 98304

__device__ __forceinline__ void attn_kv_prefetch(
    char* smp, uint32_t sb, uint32_t stgoff,
    const __nv_bfloat16* kh, const __nv_bfloat16* kl,
    const __nv_bfloat16* vh, const __nv_bfloat16* vl,
    const int* idxp, int b, int hoff, int c0, int cn, int tid)
{
    for (int i = tid; i < 64 * 8; i += 128) {
        int r = i >> 3, c = i & 7;
        uint32_t off = (uint32_t)(r * 128 + (((c ^ (r & 7))) << 4));
        if (r < cn) {
            int kt = idxp[c0 + r];
            size_t g = ((size_t)(b * TT + kt)) * CC + hoff + c * 8;
            cp_async16(sb + stgoff + off,         kh + g);
            cp_async16(sb + stgoff + 8192 + off,  kl + g);
            cp_async16(sb + stgoff + 16384 + off, vh + g);
            cp_async16(sb + stgoff + 24576 + off, vl + g);
        } else {
            uint4 z = make_uint4(0, 0, 0, 0);
            *(uint4*)(smp + stgoff + off) = z;
            *(uint4*)(smp + stgoff + 8192 + off) = z;
            *(uint4*)(smp + stgoff + 16384 + off) = z;
            *(uint4*)(smp + stgoff + 24576 + off) = z;
        }
    }
    cp_commit();
}

__global__ __launch_bounds__(128) void attn_kernel(
    const __nv_bfloat16* __restrict__ qh, const __nv_bfloat16* __restrict__ ql,
    const __nv_bfloat16* __restrict__ kh, const __nv_bfloat16* __restrict__ kl,
    const __nv_bfloat16* __restrict__ vh, const __nv_bfloat16* __restrict__ vl,
    const int* __restrict__ idx,
    __nv_bfloat16* __restrict__ yh, __nv_bfloat16* __restrict__ yl)
{
    extern __shared__ char asmem[];
    const uint32_t sb = smem_u32(asmem);
    const int tid = threadIdx.x;
    const int wq = tid >> 5;
    const int lane = tid & 31;
    const int bh = blockIdx.x;
    const int b = bh >> 4, h = bh & 15;
    const int qt0 = blockIdx.y * 128;
    const int hoff = h * HD;
    const int* idxp = idx + bh * KKEEP;

    // Q prefetch (group 0): rows of qh/ql (already scaled by 1/8)
    for (int i = tid; i < 128 * 8; i += 128) {
        int r = i >> 3, c = i & 7;
        size_t g = ((size_t)(b * TT + qt0 + r)) * CC + hoff + c * 8;
        uint32_t off = (uint32_t)(r * 128 + (((c ^ (r & 7))) << 4));
        cp_async16(sb + off, qh + g);
        cp_async16(sb + 16384 + off, ql + g);
    }
    cp_commit();

    const int nch = (KKEEP + 63) / 64;   // 7
    attn_kv_prefetch(asmem, sb, 32768, kh, kl, vh, vl, idxp, b, hoff, 0, 64, tid);

    float o[2][8][4];
    #pragma unroll
    for (int mt = 0; mt < 2; mt++)
        #pragma unroll
        for (int dt = 0; dt < 8; dt++)
            #pragma unroll
            for (int r = 0; r < 4; r++) o[mt][dt][r] = 0.f;
    float la[4] = {0.f, 0.f, 0.f, 0.f};

    for (int ch = 0; ch < nch; ch++) {
        if (ch + 1 < nch) {
            int c1 = (ch + 1) * 64;
            attn_kv_prefetch(asmem, sb, 32768 + ((ch + 1) & 1) * 32768,
                             kh, kl, vh, vl, idxp, b, hoff, c1,
                             min(64, KKEEP - c1), tid);
            asm volatile("cp.async.wait_group 1;");
        } else {
            asm volatile("cp.async.wait_group 0;");
        }
        __syncthreads();

        const uint32_t stg = sb + 32768 + (uint32_t)((ch & 1) * 32768);

        #pragma unroll
        for (int mt = 0; mt < 2; mt++) {
            // Q A-fragments for this m16 tile (4 k-steps over 64 dims)
            uint32_t ah[4][4], al[4][4];
            {
                int row = wq * 32 + mt * 16 + (lane & 15);
                #pragma unroll
                for (int kd = 0; kd < 4; kd++) {
                    int chv = kd * 2 + (lane >> 4);
                    uint32_t ad = (uint32_t)(row * 128 + (((chv ^ (row & 7))) << 4));
                    ldm_x4(ah[kd][0], ah[kd][1], ah[kd][2], ah[kd][3], sb + ad);
                    ldm_x4(al[kd][0], al[kd][1], al[kd][2], al[kd][3], sb + 16384 + ad);
                }
            }
            #pragma unroll
            for (int ntp = 0; ntp < 4; ntp++) {      // 16-key groups
                float s0[4] = {0.f, 0.f, 0.f, 0.f};
                float s1[4] = {0.f, 0.f, 0.f, 0.f};
                {
                    int rowe = ntp * 16 + (lane & 7);
                    int rowo = rowe + 8;
                    #pragma unroll
                    for (int kd = 0; kd < 4; kd++) {
                        int chv = kd * 2 + ((lane >> 3) & 1);
                        uint32_t ae = (uint32_t)(rowe * 128 + (((chv ^ (rowe & 7))) << 4));
                        uint32_t ao = (uint32_t)(rowo * 128 + (((chv ^ (rowo & 7))) << 4));
                        uint32_t bhe[2], ble[2], bho[2], blo2[2];
                        ldm_x2(bhe[0], bhe[1], stg + ae);
                        ldm_x2(ble[0], ble[1], stg + 8192 + ae);
                        ldm_x2(bho[0], bho[1], stg + ao);
                        ldm_x2(blo2[0], blo2[1], stg + 8192 + ao);
                        mma16816(s0, ah[kd], bhe);
                        mma16816(s0, ah[kd], ble);
                        mma16816(s0, al[kd], bhe);
                        mma16816(s1, ah[kd], bho);
                        mma16816(s1, ah[kd], blo2);
                        mma16816(s1, al[kd], bho);
                    }
                }
                // exp + mask (set p=0 for padded keys)
                const int kb = ch * 64 + ntp * 16 + 2 * (lane & 3);
                float p0 = (kb     < KKEEP) ? __expf(s0[0]) : 0.f;
                float p1 = (kb + 1 < KKEEP) ? __expf(s0[1]) : 0.f;
                float p2 = (kb     < KKEEP) ? __expf(s0[2]) : 0.f;
                float p3 = (kb + 1 < KKEEP) ? __expf(s0[3]) : 0.f;
                float p4 = (kb + 8 < KKEEP) ? __expf(s1[0]) : 0.f;
                float p5 = (kb + 9 < KKEEP) ? __expf(s1[1]) : 0.f;
                float p6 = (kb + 8 < KKEEP) ? __expf(s1[2]) : 0.f;
                float p7 = (kb + 9 < KKEEP) ? __expf(s1[3]) : 0.f;
                la[mt * 2 + 0] += (p0 + p1) + (p4 + p5);
                la[mt * 2 + 1] += (p2 + p3) + (p6 + p7);
                // split P and pack as m16k16 A-fragments (hi, lo)
                uint32_t phi[4], plo[4];
                {
                    float vs[8] = {p0, p1, p2, p3, p4, p5, p6, p7};
                    #pragma unroll
                    for (int j = 0; j < 4; j++) {
                        __nv_bfloat16 ha = __float2bfloat16(vs[2 * j]);
                        __nv_bfloat16 hb = __float2bfloat16(vs[2 * j + 1]);
                        __nv_bfloat162 th(ha, hb);
                        phi[j] = *(uint32_t*)&th;
                        __nv_bfloat162 tl(__float2bfloat16(vs[2 * j] - __bfloat162float(ha)),
                                          __float2bfloat16(vs[2 * j + 1] - __bfloat162float(hb)));
                        plo[j] = *(uint32_t*)&tl;
                    }
                }
                // PV: keys ntp*16..+15 as k16; V B-frags via ldmatrix.trans
                #pragma unroll
                for (int dp = 0; dp < 4; dp++) {     // 16-dim groups
                    int g = lane >> 3;
                    int krow = ntp * 16 + ((g & 1) << 3) + (lane & 7);
                    int chv = dp * 2 + (g >> 1);
                    uint32_t av = (uint32_t)(krow * 128 + (((chv ^ (krow & 7))) << 4));
                    uint32_t vbh[4], vbl[4];
                    ldm_x4t(vbh, stg + 16384 + av);
                    ldm_x4t(vbl, stg + 24576 + av);
                    mma16816(o[mt][dp * 2],     phi, &vbh[0]);
                    mma16816(o[mt][dp * 2],     plo, &vbh[0]);
                    mma16816(o[mt][dp * 2],     phi, &vbl[0]);
                    mma16816(o[mt][dp * 2 + 1], phi, &vbh[2]);
                    mma16816(o[mt][dp * 2 + 1], plo, &vbh[2]);
                    mma16816(o[mt][dp * 2 + 1], phi, &vbl[2]);
                }
            }
        }
        __syncthreads();
    }

    // reduce l across the 4 lanes sharing each row (xor bits 0,1)
    #pragma unroll
    for (int j = 0; j < 4; j++) {
        la[j] += __shfl_xor_sync(0xFFFFFFFFu, la[j], 1);
        la[j] += __shfl_xor_sync(0xFFFFFFFFu, la[j], 2);
        la[j] = 1.f / la[j];
    }

    // write O / l, split to bf16 hi/lo for GEMM2
    #pragma unroll
    for (int mt = 0; mt < 2; mt++) {
        const int row0 = qt0 + wq * 32 + mt * 16 + (lane >> 2);
        #pragma unroll
        for (int dt = 0; dt < 8; dt++) {
            const int col = dt * 8 + 2 * (lane & 3);
            size_t a0 = ((size_t)(b * TT + row0)) * CC + hoff + col;
            uint32_t wh, wl;
            split_pair(o[mt][dt][0] * la[mt * 2], o[mt][dt][1] * la[mt * 2], wh, wl);
            *(uint32_t*)(yh + a0) = wh;
            *(uint32_t*)(yl + a0) = wl;
            size_t a1 = a0 + (size_t)8 * CC;
            split_pair(o[mt][dt][2] * la[mt * 2 + 1], o[mt][dt][3] * la[mt * 2 + 1], wh, wl);
            *(uint32_t*)(yh + a1) = wh;
            *(uint32_t*)(yl + a1) = wl;
        }
    }
}

// ---------------- launch ----------------------------------------------------
extern "C" void kernel_launch(void* const* d_in, const int* in_sizes, int n_in,
                              void* d_out, int out_size)
{
    const float* x  = (const float*)d_in[0];   // [4,1024,1024]
    const float* Wa = (const float*)d_in[1];   // [1024,3072]
    const float* Wp = (const float*)d_in[2];   // [1024,1024]
    float* out = (float*)d_out;                // [4,1024,1024]

    void* p;
    cudaGetSymbolAddress(&p, g_last);  float* last  = (float*)p;
    cudaGetSymbolAddress(&p, g_idx);   int*   idx   = (int*)p;
    cudaGetSymbolAddress(&p, g_qlast); float* qlast = (float*)p;
    cudaGetSymbolAddress(&p, g_u);     float* u     = (float*)p;
    cudaGetSymbolAddress(&p, g_xh);   __nv_bfloat16* xh  = (__nv_bfloat16*)p;
    cudaGetSymbolAddress(&p, g_xl);   __nv_bfloat16* xl  = (__nv_bfloat16*)p;
    cudaGetSymbolAddress(&p, g_wah);  __nv_bfloat16* wah = (__nv_bfloat16*)p;
    cudaGetSymbolAddress(&p, g_wal);  __nv_bfloat16* wal = (__nv_bfloat16*)p;
    cudaGetSymbolAddress(&p, g_wph);  __nv_bfloat16* wph = (__nv_bfloat16*)p;
    cudaGetSymbolAddress(&p, g_wpl);  __nv_bfloat16* wpl = (__nv_bfloat16*)p;
    cudaGetSymbolAddress(&p, g_yh);   __nv_bfloat16* yh  = (__nv_bfloat16*)p;
    cudaGetSymbolAddress(&p, g_yl);   __nv_bfloat16* yl  = (__nv_bfloat16*)p;
    cudaGetSymbolAddress(&p, g_qh);   __nv_bfloat16* qhp = (__nv_bfloat16*)p;
    cudaGetSymbolAddress(&p, g_ql);   __nv_bfloat16* qlp = (__nv_bfloat16*)p;
    cudaGetSymbolAddress(&p, g_kh);   __nv_bfloat16* khp = (__nv_bfloat16*)p;
    cudaGetSymbolAddress(&p, g_kl);   __nv_bfloat16* klp = (__nv_bfloat16*)p;
    cudaGetSymbolAddress(&p, g_vh);   __nv_bfloat16* vhp = (__nv_bfloat16*)p;
    cudaGetSymbolAddress(&p, g_vl);   __nv_bfloat16* vlp = (__nv_bfloat16*)p;

    cudaFuncSetAttribute(gemm_bf16x3, cudaFuncAttributeMaxDynamicSharedMemorySize, GSMEM);
    cudaFuncSetAttribute(gemm_qkv, cudaFuncAttributeMaxDynamicSharedMemorySize, GSMEM);
    cudaFuncSetAttribute(attn_kernel, cudaFuncAttributeMaxDynamicSharedMemorySize, ASMEM);

    // slot 1-3: qlast, uproj, prep
    qlast_kernel<<<BB * NH, 64>>>(x, Wa, qlast);
    uproj_kernel<<<dim3(BB, CC / 16), 256>>>(Wa, qlast, u);
    prep_kernel<<<PREP_TOTAL, 256>>>(x, Wa, Wp, xh, xl, wah, wal, wph, wpl);

    // slot 4 (profiled): qkv GEMM with splitting epilogue
    gemm_qkv<<<dim3(3 * CC / 128, BB * TT / 128), 256, GSMEM>>>(
        xh, xl, wah, wal, qhp, qlp, khp, klp, vhp, vlp);

    // slot 5-6: selection scores + topk
    scores_kernel<<<dim3(BB, TT / 64), 256>>>(x, u, last);
    topk_kernel<<<BB * NH, 512>>>(last, idx);

    // slot 7: mma attention -> yh/yl
    attn_kernel<<<dim3(BB * NH, TT / 128), 128, ASMEM>>>(
        qhp, qlp, khp, klp, vhp, vlp, idx, yh, yl);

    // slot 8: out = y @ W_proj
    gemm_bf16x3<<<dim3(CC / 128, BB * TT / 128), 256, GSMEM>>>(yh, yl, wph, wpl, out, CC);
}

// round 13
// speedup vs baseline: 2.0092x; 1.2233x over previous
#include <cuda_runtime.h>
#include <cuda_bf16.h>
#include <math.h>
#include <stdint.h>

// Problem constants
#define BB 4
#define TT 1024
#define CC 1024
#define NH 16
#define HD 64
#define KKEEP 391
#define REC 64
#define NONREC (TT - REC)       // 960

// ---------------- scratch (device globals; no allocation allowed) ----------
__device__ float g_last[BB * NH * TT];
__device__ int   g_idx[BB * NH * KKEEP];
__device__ float g_qlast[BB * CC];
__device__ float g_u[BB * CC * NH];
__device__ __nv_bfloat16 g_xh[BB * TT * CC];
__device__ __nv_bfloat16 g_xl[BB * TT * CC];
__device__ __nv_bfloat16 g_wah[3 * CC * CC];         // W_attn^T hi/lo [3072][1024]
__device__ __nv_bfloat16 g_wal[3 * CC * CC];
__device__ __nv_bfloat16 g_wph[CC * CC];             // W_proj^T hi/lo
__device__ __nv_bfloat16 g_wpl[CC * CC];
__device__ __nv_bfloat16 g_yh[BB * TT * CC];
__device__ __nv_bfloat16 g_yl[BB * TT * CC];
// split QKV (written by gemm_qkv epilogue)
__device__ __nv_bfloat16 g_qh[BB * TT * CC];         // Q * 0.125, hi/lo
__device__ __nv_bfloat16 g_ql[BB * TT * CC];
__device__ __nv_bfloat16 g_kh[BB * TT * CC];
__device__ __nv_bfloat16 g_kl[BB * TT * CC];
__device__ __nv_bfloat16 g_vh[BB * TT * CC];
__device__ __nv_bfloat16 g_vl[BB * TT * CC];

// ---------------- helpers ---------------------------------------------------
__device__ __forceinline__ uint32_t smem_u32(const void* p) {
    uint32_t a;
    asm("{ .reg .u64 t; cvta.to.shared.u64 t, %1; cvt.u32.u64 %0, t; }" : "=r"(a) : "l"(p));
    return a;
}
__device__ __forceinline__ void cp_async16(uint32_t dst, const void* src) {
    asm volatile("cp.async.cg.shared.global [%0], [%1], 16;" :: "r"(dst), "l"(src));
}
__device__ __forceinline__ void cp_commit() {
    asm volatile("cp.async.commit_group;");
}
__device__ __forceinline__ void ldm_x4(uint32_t& r0, uint32_t& r1, uint32_t& r2, uint32_t& r3, uint32_t addr) {
    asm volatile("ldmatrix.sync.aligned.m8n8.x4.shared.b16 {%0,%1,%2,%3}, [%4];"
                 : "=r"(r0), "=r"(r1), "=r"(r2), "=r"(r3) : "r"(addr));
}
__device__ __forceinline__ void ldm_x2(uint32_t& r0, uint32_t& r1, uint32_t addr) {
    asm volatile("ldmatrix.sync.aligned.m8n8.x2.shared.b16 {%0,%1}, [%2];"
                 : "=r"(r0), "=r"(r1) : "r"(addr));
}
__device__ __forceinline__ void ldm_x4t(uint32_t* r, uint32_t addr) {
    asm volatile("ldmatrix.sync.aligned.m8n8.x4.trans.shared.b16 {%0,%1,%2,%3}, [%4];"
                 : "=r"(r[0]), "=r"(r[1]), "=r"(r[2]), "=r"(r[3]) : "r"(addr));
}
__device__ __forceinline__ void mma16816(float* d, const uint32_t* a, const uint32_t* b) {
    asm volatile(
        "mma.sync.aligned.m16n8k16.row.col.f32.bf16.bf16.f32 "
        "{%0,%1,%2,%3},{%4,%5,%6,%7},{%8,%9},{%0,%1,%2,%3};"
        : "+f"(d[0]), "+f"(d[1]), "+f"(d[2]), "+f"(d[3])
        : "r"(a[0]), "r"(a[1]), "r"(a[2]), "r"(a[3]), "r"(b[0]), "r"(b[1]));
}
__device__ __forceinline__ void split_bf16(float a, __nv_bfloat16& h, __nv_bfloat16& l) {
    h = __float2bfloat16(a);
    l = __float2bfloat16(a - __bfloat162float(h));
}
// split v0,v1 into hi/lo bf16x2 words
__device__ __forceinline__ void split_pair(float v0, float v1, uint32_t& wh, uint32_t& wl) {
    __nv_bfloat16 h0, l0, h1, l1;
    split_bf16(v0, h0, l0); split_bf16(v1, h1, l1);
    __nv_bfloat162 th(h0, h1), tl(l0, l1);
    wh = *(uint32_t*)&th; wl = *(uint32_t*)&tl;
}

// ---------------- merged prep: split x + transpose-split both weights -------
#define PREP_SPLIT 4096
#define PREP_WA (PREP_SPLIT + 3072)
#define PREP_TOTAL (PREP_WA + 1024)

__global__ __launch_bounds__(256) void prep_kernel(
    const float* __restrict__ x, const float* __restrict__ Wa, const float* __restrict__ Wp,
    __nv_bfloat16* __restrict__ xh, __nv_bfloat16* __restrict__ xl,
    __nv_bfloat16* __restrict__ wah, __nv_bfloat16* __restrict__ wal,
    __nv_bfloat16* __restrict__ wph, __nv_bfloat16* __restrict__ wpl)
{
    const int bid = blockIdx.x;
    if (bid < PREP_SPLIT) {
        int i = bid * 256 + threadIdx.x;
        float4 v = ((const float4*)x)[i];
        uint32_t h01, l01, h23, l23;
        split_pair(v.x, v.y, h01, l01);
        split_pair(v.z, v.w, h23, l23);
        ((uint32_t*)xh)[i * 2 + 0] = h01;
        ((uint32_t*)xh)[i * 2 + 1] = h23;
        ((uint32_t*)xl)[i * 2 + 0] = l01;
        ((uint32_t*)xl)[i * 2 + 1] = l23;
        return;
    }
    const float* in;
    __nv_bfloat16 *outh, *outl;
    int rows, cols, bx, by;
    if (bid < PREP_WA) {
        int id = bid - PREP_SPLIT;
        in = Wa; outh = wah; outl = wal; rows = CC; cols = 3 * CC;
        bx = (id % 96) * 32; by = (id / 96) * 32;
    } else {
        int id = bid - PREP_WA;
        in = Wp; outh = wph; outl = wpl; rows = CC; cols = CC;
        bx = (id % 32) * 32; by = (id / 32) * 32;
    }
    __shared__ float t[32][33];
    const int tx = threadIdx.x & 31, ty = threadIdx.x >> 5;
    int xcol = bx + tx;
    #pragma unroll
    for (int j = ty; j < 32; j += 8)
        t[j][tx] = in[(size_t)(by + j) * cols + xcol];
    __syncthreads();
    int xo = by + tx;
    #pragma unroll
    for (int j = ty; j < 32; j += 8) {
        float v = t[tx][j];
        __nv_bfloat16 h, l;
        split_bf16(v, h, l);
        outh[(size_t)(bx + j) * rows + xo] = h;
        outl[(size_t)(bx + j) * rows + xo] = l;
    }
}

// ---------------- mma.sync bf16 3-term GEMM core ----------------------------
#define GK 1024
#define BKC 32
#define ARR2 (128 * 64)
#define STG2 (4 * ARR2)
#define NSTG 3
#define GSMEM (NSTG * STG2)

__device__ __forceinline__ void gemm_load_stage(
    uint32_t sdst, const __nv_bfloat16* Ahb, const __nv_bfloat16* Alb,
    const __nv_bfloat16* Bhb, const __nv_bfloat16* Blb, int k0, int tid)
{
    #pragma unroll
    for (int it = 0; it < 2; it++) {
        int i = tid + it * 256;
        int r = i >> 2, c = i & 3;
        int cs = c ^ ((r >> 1) & 3);
        size_t go = (size_t)r * GK + k0 + c * 8;
        uint32_t d0 = sdst + (uint32_t)(r * 64 + cs * 16);
        cp_async16(d0,            Ahb + go);
        cp_async16(d0 + ARR2,     Alb + go);
        cp_async16(d0 + 2 * ARR2, Bhb + go);
        cp_async16(d0 + 3 * ARR2, Blb + go);
    }
    cp_commit();
}

#define GEMM_MAIN(acc, Ah, Al, Bh, Bl)                                          \
    extern __shared__ char dsm[];                                               \
    const uint32_t sb = smem_u32(dsm);                                          \
    const int tid = threadIdx.x;                                                \
    const int wid = tid >> 5;                                                   \
    const int lane = tid & 31;                                                  \
    const int wm = wid >> 2;                                                    \
    const int wn = wid & 3;                                                     \
    const int m0 = blockIdx.y * 128;                                            \
    const int n0 = blockIdx.x * 128;                                            \
    const __nv_bfloat16* Ahb = Ah + (size_t)m0 * GK;                            \
    const __nv_bfloat16* Alb = Al + (size_t)m0 * GK;                            \
    const __nv_bfloat16* Bhb = Bh + (size_t)n0 * GK;                            \
    const __nv_bfloat16* Blb = Bl + (size_t)n0 * GK;                            \
    float acc[4][4][4];                                                         \
    _Pragma("unroll")                                                           \
    for (int i = 0; i < 4; i++)                                                 \
        _Pragma("unroll")                                                       \
        for (int j = 0; j < 4; j++)                                             \
            _Pragma("unroll")                                                   \
            for (int r = 0; r < 4; r++) acc[i][j][r] = 0.f;                     \
    const int arow = wm * 64 + (lane & 15);                                     \
    const int achk = lane >> 4;                                                 \
    const uint32_t s_a = (uint32_t)((arow >> 1) & 3);                           \
    const int brow = wn * 32 + (lane & 7);                                      \
    const int bchk = (lane >> 3) & 1;                                           \
    const uint32_t s_b = (uint32_t)((brow >> 1) & 3);                           \
    gemm_load_stage(sb,        Ahb, Alb, Bhb, Blb, 0,   tid);                   \
    gemm_load_stage(sb + STG2, Ahb, Alb, Bhb, Blb, BKC, tid);                   \
    const int NCH = GK / BKC;                                                   \
    for (int ch = 0; ch < NCH; ch++) {                                          \
        if (ch + 1 < NCH) { asm volatile("cp.async.wait_group 1;"); }           \
        else              { asm volatile("cp.async.wait_group 0;"); }           \
        __syncthreads();                                                        \
        if (ch + 2 < NCH)                                                       \
            gemm_load_stage(sb + ((ch + 2) % NSTG) * STG2, Ahb, Alb, Bhb, Blb,  \
                            (ch + 2) * BKC, tid);                               \
        const uint32_t st = sb + (ch % NSTG) * STG2;                            \
        _Pragma("unroll")                                                       \
        for (int ks = 0; ks < 2; ks++) {                                        \
            const uint32_t kc = (uint32_t)(ks * 2);                             \
            uint32_t af[4][4], bf[4][2], bt[4][2];                              \
            _Pragma("unroll")                                                   \
            for (int mt = 0; mt < 4; mt++) {                                    \
                uint32_t ad = st + (uint32_t)((arow + mt * 16) * 64) + (((kc + achk) ^ s_a) << 4); \
                ldm_x4(af[mt][0], af[mt][1], af[mt][2], af[mt][3], ad);         \
            }                                                                   \
            _Pragma("unroll")                                                   \
            for (int nt = 0; nt < 4; nt++) {                                    \
                uint32_t bd = st + 2 * ARR2 + (uint32_t)((brow + nt * 8) * 64) + (((kc + bchk) ^ s_b) << 4); \
                ldm_x2(bf[nt][0], bf[nt][1], bd);                               \
            }                                                                   \
            _Pragma("unroll")                                                   \
            for (int mt = 0; mt < 4; mt++)                                      \
                _Pragma("unroll")                                               \
                for (int nt = 0; nt < 4; nt++) mma16816(acc[mt][nt], af[mt], bf[nt]); \
            _Pragma("unroll")                                                   \
            for (int nt = 0; nt < 4; nt++) {                                    \
                uint32_t bd = st + 3 * ARR2 + (uint32_t)((brow + nt * 8) * 64) + (((kc + bchk) ^ s_b) << 4); \
                ldm_x2(bt[nt][0], bt[nt][1], bd);                               \
            }                                                                   \
            _Pragma("unroll")                                                   \
            for (int mt = 0; mt < 4; mt++)                                      \
                _Pragma("unroll")                                               \
                for (int nt = 0; nt < 4; nt++) mma16816(acc[mt][nt], af[mt], bt[nt]); \
            _Pragma("unroll")                                                   \
            for (int mt = 0; mt < 4; mt++) {                                    \
                uint32_t ad = st + ARR2 + (uint32_t)((arow + mt * 16) * 64) + (((kc + achk) ^ s_a) << 4); \
                ldm_x4(af[mt][0], af[mt][1], af[mt][2], af[mt][3], ad);         \
            }                                                                   \
            _Pragma("unroll")                                                   \
            for (int mt = 0; mt < 4; mt++)                                      \
                _Pragma("unroll")                                               \
                for (int nt = 0; nt < 4; nt++) mma16816(acc[mt][nt], af[mt], bf[nt]); \
        }                                                                       \
        __syncthreads();                                                        \
    }

// GEMM2: fp32 C output
__global__ __launch_bounds__(256, 2) void gemm_bf16x3(
    const __nv_bfloat16* __restrict__ Ah, const __nv_bfloat16* __restrict__ Al,
    const __nv_bfloat16* __restrict__ Bh, const __nv_bfloat16* __restrict__ Bl,
    float* __restrict__ C, int N)
{
    GEMM_MAIN(acc, Ah, Al, Bh, Bl)
    const int mrow = m0 + wm * 64 + (lane >> 2);
    const int ncol = n0 + wn * 32 + (lane & 3) * 2;
    #pragma unroll
    for (int mt = 0; mt < 4; mt++)
        #pragma unroll
        for (int nt = 0; nt < 4; nt++) {
            float* c0 = C + (size_t)(mrow + mt * 16) * N + ncol + nt * 8;
            *(float2*)c0 = make_float2(acc[mt][nt][0], acc[mt][nt][1]);
            float* c1 = c0 + (size_t)8 * N;
            *(float2*)c1 = make_float2(acc[mt][nt][2], acc[mt][nt][3]);
        }
}

// GEMM1: N=3072 fixed; epilogue splits into q(scaled)/k/v bf16 hi/lo
__global__ __launch_bounds__(256, 2) void gemm_qkv(
    const __nv_bfloat16* __restrict__ Ah, const __nv_bfloat16* __restrict__ Al,
    const __nv_bfloat16* __restrict__ Bh, const __nv_bfloat16* __restrict__ Bl,
    __nv_bfloat16* __restrict__ qh, __nv_bfloat16* __restrict__ ql,
    __nv_bfloat16* __restrict__ kh, __nv_bfloat16* __restrict__ kl,
    __nv_bfloat16* __restrict__ vh, __nv_bfloat16* __restrict__ vl)
{
    GEMM_MAIN(acc, Ah, Al, Bh, Bl)
    const int region = n0 >> 10;
    __nv_bfloat16 *oh, *ol;
    float sc;
    if (region == 0)      { oh = qh; ol = ql; sc = 0.125f; }
    else if (region == 1) { oh = kh; ol = kl; sc = 1.f; }
    else                  { oh = vh; ol = vl; sc = 1.f; }
    const int mrow = m0 + wm * 64 + (lane >> 2);
    const int colr = (n0 & 1023) + wn * 32 + (lane & 3) * 2;
    #pragma unroll
    for (int mt = 0; mt < 4; mt++)
        #pragma unroll
        for (int nt = 0; nt < 4; nt++) {
            size_t o0 = (size_t)(mrow + mt * 16) * CC + colr + nt * 8;
            uint32_t wh, wl;
            split_pair(acc[mt][nt][0] * sc, acc[mt][nt][1] * sc, wh, wl);
            *(uint32_t*)(oh + o0) = wh;
            *(uint32_t*)(ol + o0) = wl;
            size_t o1 = o0 + (size_t)8 * CC;
            split_pair(acc[mt][nt][2] * sc, acc[mt][nt][3] * sc, wh, wl);
            *(uint32_t*)(oh + o1) = wh;
            *(uint32_t*)(ol + o1) = wl;
        }
}

// ---------------- fp32 selection-score path ---------------------------------
__global__ __launch_bounds__(64) void qlast_kernel(
    const float* __restrict__ x, const float* __restrict__ Wa,
    float* __restrict__ qlast)
{
    const int b = blockIdx.x >> 4, h = blockIdx.x & 15;
    __shared__ float xs[CC];
    for (int c = threadIdx.x; c < CC; c += 64)
        xs[c] = x[((size_t)b * TT + (TT - 1)) * CC + c];
    __syncthreads();
    const int col = h * HD + threadIdx.x;
    float s = 0.f;
    for (int c = 0; c < CC; c++) s += xs[c] * Wa[(size_t)c * (3 * CC) + col];
    qlast[(b * NH + h) * HD + threadIdx.x] = s;
}

__global__ __launch_bounds__(256) void uproj_kernel(
    const float* __restrict__ Wa, const float* __restrict__ qlast,
    float* __restrict__ u)
{
    const int b = blockIdx.x;
    const int c = blockIdx.y * 16 + (threadIdx.x >> 4);
    const int h = threadIdx.x & 15;
    __shared__ float qs[CC];
    for (int i = threadIdx.x; i < CC; i += 256) qs[i] = qlast[b * CC + i];
    __syncthreads();
    const float* wrow = Wa + (size_t)c * (3 * CC) + CC + h * HD;
    const float* qh = qs + h * HD;
    float s = 0.f;
    #pragma unroll
    for (int d = 0; d < HD; d++) s += wrow[d] * qh[d];
    u[((size_t)b * CC + c) * NH + h] = s;
}

// coalesced scores: block = 128 thr (32 t-rows x 4 head-groups), grid (BB, 32)
// x tile staged in smem (129-float row stride -> conflict-free scalar LDS).
#define SC_TR 32
#define SC_PAD 129

__global__ __launch_bounds__(128) void scores_kernel(
    const float* __restrict__ x, const float* __restrict__ u,
    float* __restrict__ last)
{
    const int b = blockIdx.x;
    const int t0 = blockIdx.y * SC_TR;
    const int tid = threadIdx.x;
    const int tloc = tid & 31;
    const int hg = tid >> 5;                 // 0..3 -> heads hg*4..hg*4+3

    __shared__ float xs[SC_TR][SC_PAD];
    __shared__ float us[128][NH];

    float4 acc = make_float4(0.f, 0.f, 0.f, 0.f);

    for (int c0 = 0; c0 < CC; c0 += 128) {
        __syncthreads();
        // load x tile [32 rows][128 cols] coalesced (float4 LDG, scalar STS)
        #pragma unroll
        for (int it = 0; it < 8; it++) {
            int flat = it * 128 + tid;       // 0..1023 float4s
            int r = flat >> 5;               // 32 float4 per row
            int c4 = flat & 31;
            float4 v = *(const float4*)(x + ((size_t)(b * TT + t0 + r)) * CC + c0 + c4 * 4);
            xs[r][c4 * 4 + 0] = v.x; xs[r][c4 * 4 + 1] = v.y;
            xs[r][c4 * 4 + 2] = v.z; xs[r][c4 * 4 + 3] = v.w;
        }
        // load u tile [128 c][16 h] coalesced
        #pragma unroll
        for (int it = 0; it < 4; it++) {
            int flat = it * 128 + tid;       // 0..511 float4s
            int ci = flat >> 2;
            int h4 = flat & 3;
            float4 v = *(const float4*)(u + ((size_t)(b * CC + c0 + ci)) * NH + h4 * 4);
            *(float4*)&us[ci][h4 * 4] = v;
        }
        __syncthreads();

        #pragma unroll 4
        for (int ci = 0; ci < 128; ci++) {
            float xv = xs[tloc][ci];
            float4 uu = *(const float4*)&us[ci][hg * 4];
            acc.x += xv * uu.x; acc.y += xv * uu.y;
            acc.z += xv * uu.z; acc.w += xv * uu.w;
        }
    }

    const int t = t0 + tloc;
    last[(b * NH + hg * 4 + 0) * TT + t] = acc.x * 0.125f;
    last[(b * NH + hg * 4 + 1) * TT + t] = acc.y * 0.125f;
    last[(b * NH + hg * 4 + 2) * TT + t] = acc.z * 0.125f;
    last[(b * NH + hg * 4 + 3) * TT + t] = acc.w * 0.125f;
}

// ---------------- top-k set selection via bitonic sort ---------------------
__global__ __launch_bounds__(512) void topk_kernel(const float* __restrict__ last,
                                                   int* __restrict__ idxout)
{
    __shared__ unsigned long long s[TT];
    const int bh = blockIdx.x;
    const int tid = threadIdx.x;

    for (int t = tid; t < TT; t += 512) {
        unsigned u;
        if (t >= NONREC) {
            u = 0xFFFFFFFFu;
        } else {
            u = __float_as_uint(last[bh * TT + t]);
            u = (u & 0x80000000u) ? ~u : (u | 0x80000000u);
        }
        s[t] = ((unsigned long long)u << 32) | (unsigned)t;
    }
    __syncthreads();

    for (int k = 2; k <= TT; k <<= 1) {
        for (int j = k >> 1; j > 0; j >>= 1) {
            for (int i = tid; i < TT; i += 512) {
                int ix = i ^ j;
                if (ix > i) {
                    bool desc = ((i & k) == 0);
                    unsigned long long a = s[i], b = s[ix];
                    bool sw = desc ? (a < b) : (a > b);
                    if (sw) { s[i] = b; s[ix] = a; }
                }
            }
            __syncthreads();
        }
    }
    for (int i = tid; i < KKEEP; i += 512)
        idxout[bh * KKEEP + i] = (int)(s[i] & 0xFFFFFFFFu);
}

// ---------------- mma-based pruned attention --------------------------------
#define ASMEM (32768 + 2 * 32768)        // 98304

__device__ __forceinline__ void attn_kv_prefetch(
    char* smp, uint32_t sb, uint32_t stgoff,
    const __nv_bfloat16* kh, const __nv_bfloat16* kl,
    const __nv_bfloat16* vh, const __nv_bfloat16* vl,
    const int* idxp, int b, int hoff, int c0, int cn, int tid)
{
    for (int i = tid; i < 64 * 8; i += 128) {
        int r = i >> 3, c = i & 7;
        uint32_t off = (uint32_t)(r * 128 + (((c ^ (r & 7))) << 4));
        if (r < cn) {
            int kt = idxp[c0 + r];
            size_t g = ((size_t)(b * TT + kt)) * CC + hoff + c * 8;
            cp_async16(sb + stgoff + off,         kh + g);
            cp_async16(sb + stgoff + 8192 + off,  kl + g);
            cp_async16(sb + stgoff + 16384 + off, vh + g);
            cp_async16(sb + stgoff + 24576 + off, vl + g);
        } else {
            uint4 z = make_uint4(0, 0, 0, 0);
            *(uint4*)(smp + stgoff + off) = z;
            *(uint4*)(smp + stgoff + 8192 + off) = z;
            *(uint4*)(smp + stgoff + 16384 + off) = z;
            *(uint4*)(smp + stgoff + 24576 + off) = z;
        }
    }
    cp_commit();
}

__global__ __launch_bounds__(128) void attn_kernel(
    const __nv_bfloat16* __restrict__ qh, const __nv_bfloat16* __restrict__ ql,
    const __nv_bfloat16* __restrict__ kh, const __nv_bfloat16* __restrict__ kl,
    const __nv_bfloat16* __restrict__ vh, const __nv_bfloat16* __restrict__ vl,
    const int* __restrict__ idx,
    __nv_bfloat16* __restrict__ yh, __nv_bfloat16* __restrict__ yl)
{
    extern __shared__ char asmem[];
    const uint32_t sb = smem_u32(asmem);
    const int tid = threadIdx.x;
    const int wq = tid >> 5;
    const int lane = tid & 31;
    const int bh = blockIdx.x;
    const int b = bh >> 4, h = bh & 15;
    const int qt0 = blockIdx.y * 128;
    const int hoff = h * HD;
    const int* idxp = idx + bh * KKEEP;

    for (int i = tid; i < 128 * 8; i += 128) {
        int r = i >> 3, c = i & 7;
        size_t g = ((size_t)(b * TT + qt0 + r)) * CC + hoff + c * 8;
        uint32_t off = (uint32_t)(r * 128 + (((c ^ (r & 7))) << 4));
        cp_async16(sb + off, qh + g);
        cp_async16(sb + 16384 + off, ql + g);
    }
    cp_commit();

    const int nch = (KKEEP + 63) / 64;   // 7
    attn_kv_prefetch(asmem, sb, 32768, kh, kl, vh, vl, idxp, b, hoff, 0, 64, tid);

    float o[2][8][4];
    #pragma unroll
    for (int mt = 0; mt < 2; mt++)
        #pragma unroll
        for (int dt = 0; dt < 8; dt++)
            #pragma unroll
            for (int r = 0; r < 4; r++) o[mt][dt][r] = 0.f;
    float la[4] = {0.f, 0.f, 0.f, 0.f};

    for (int ch = 0; ch < nch; ch++) {
        if (ch + 1 < nch) {
            int c1 = (ch + 1) * 64;
            attn_kv_prefetch(asmem, sb, 32768 + ((ch + 1) & 1) * 32768,
                             kh, kl, vh, vl, idxp, b, hoff, c1,
                             min(64, KKEEP - c1), tid);
            asm volatile("cp.async.wait_group 1;");
        } else {
            asm volatile("cp.async.wait_group 0;");
        }
        __syncthreads();

        const uint32_t stg = sb + 32768 + (uint32_t)((ch & 1) * 32768);

        #pragma unroll
        for (int mt = 0; mt < 2; mt++) {
            uint32_t ah[4][4], al[4][4];
            {
                int row = wq * 32 + mt * 16 + (lane & 15);
                #pragma unroll
                for (int kd = 0; kd < 4; kd++) {
                    int chv = kd * 2 + (lane >> 4);
                    uint32_t ad = (uint32_t)(row * 128 + (((chv ^ (row & 7))) << 4));
                    ldm_x4(ah[kd][0], ah[kd][1], ah[kd][2], ah[kd][3], sb + ad);
                    ldm_x4(al[kd][0], al[kd][1], al[kd][2], al[kd][3], sb + 16384 + ad);
                }
            }
            #pragma unroll
            for (int ntp = 0; ntp < 4; ntp++) {
                float s0[4] = {0.f, 0.f, 0.f, 0.f};
                float s1[4] = {0.f, 0.f, 0.f, 0.f};
                {
                    int rowe = ntp * 16 + (lane & 7);
                    int rowo = rowe + 8;
                    #pragma unroll
                    for (int kd = 0; kd < 4; kd++) {
                        int chv = kd * 2 + ((lane >> 3) & 1);
                        uint32_t ae = (uint32_t)(rowe * 128 + (((chv ^ (rowe & 7))) << 4));
                        uint32_t ao = (uint32_t)(rowo * 128 + (((chv ^ (rowo & 7))) << 4));
                        uint32_t bhe[2], ble[2], bho[2], blo2[2];
                        ldm_x2(bhe[0], bhe[1], stg + ae);
                        ldm_x2(ble[0], ble[1], stg + 8192 + ae);
                        ldm_x2(bho[0], bho[1], stg + ao);
                        ldm_x2(blo2[0], blo2[1], stg + 8192 + ao);
                        mma16816(s0, ah[kd], bhe);
                        mma16816(s0, ah[kd], ble);
                        mma16816(s0, al[kd], bhe);
                        mma16816(s1, ah[kd], bho);
                        mma16816(s1, ah[kd], blo2);
                        mma16816(s1, al[kd], bho);
                    }
                }
                const int kb = ch * 64 + ntp * 16 + 2 * (lane & 3);
                float p0 = (kb     < KKEEP) ? __expf(s0[0]) : 0.f;
                float p1 = (kb + 1 < KKEEP) ? __expf(s0[1]) : 0.f;
                float p2 = (kb     < KKEEP) ? __expf(s0[2]) : 0.f;
                float p3 = (kb + 1 < KKEEP) ? __expf(s0[3]) : 0.f;
                float p4 = (kb + 8 < KKEEP) ? __expf(s1[0]) : 0.f;
                float p5 = (kb + 9 < KKEEP) ? __expf(s1[1]) : 0.f;
                float p6 = (kb + 8 < KKEEP) ? __expf(s1[2]) : 0.f;
                float p7 = (kb + 9 < KKEEP) ? __expf(s1[3]) : 0.f;
                la[mt * 2 + 0] += (p0 + p1) + (p4 + p5);
                la[mt * 2 + 1] += (p2 + p3) + (p6 + p7);
                uint32_t phi[4], plo[4];
                {
                    float vs[8] = {p0, p1, p2, p3, p4, p5, p6, p7};
                    #pragma unroll
                    for (int j = 0; j < 4; j++) {
                        __nv_bfloat16 ha = __float2bfloat16(vs[2 * j]);
                        __nv_bfloat16 hb = __float2bfloat16(vs[2 * j + 1]);
                        __nv_bfloat162 th(ha, hb);
                        phi[j] = *(uint32_t*)&th;
                        __nv_bfloat162 tl(__float2bfloat16(vs[2 * j] - __bfloat162float(ha)),
                                          __float2bfloat16(vs[2 * j + 1] - __bfloat162float(hb)));
                        plo[j] = *(uint32_t*)&tl;
                    }
                }
                #pragma unroll
                for (int dp = 0; dp < 4; dp++) {
                    int g = lane >> 3;
                    int krow = ntp * 16 + ((g & 1) << 3) + (lane & 7);
                    int chv = dp * 2 + (g >> 1);
                    uint32_t av = (uint32_t)(krow * 128 + (((chv ^ (krow & 7))) << 4));
                    uint32_t vbh[4], vbl[4];
                    ldm_x4t(vbh, stg + 16384 + av);
                    ldm_x4t(vbl, stg + 24576 + av);
                    mma16816(o[mt][dp * 2],     phi, &vbh[0]);
                    mma16816(o[mt][dp * 2],     plo, &vbh[0]);
                    mma16816(o[mt][dp * 2],     phi, &vbl[0]);
                    mma16816(o[mt][dp * 2 + 1], phi, &vbh[2]);
                    mma16816(o[mt][dp * 2 + 1], plo, &vbh[2]);
                    mma16816(o[mt][dp * 2 + 1], phi, &vbl[2]);
                }
            }
        }
        __syncthreads();
    }

    #pragma unroll
    for (int j = 0; j < 4; j++) {
        la[j] += __shfl_xor_sync(0xFFFFFFFFu, la[j], 1);
        la[j] += __shfl_xor_sync(0xFFFFFFFFu, la[j], 2);
        la[j] = 1.f / la[j];
    }

    #pragma unroll
    for (int mt = 0; mt < 2; mt++) {
        const int row0 = qt0 + wq * 32 + mt * 16 + (lane >> 2);
        #pragma unroll
        for (int dt = 0; dt < 8; dt++) {
            const int col = dt * 8 + 2 * (lane & 3);
            size_t a0 = ((size_t)(b * TT + row0)) * CC + hoff + col;
            uint32_t wh, wl;
            split_pair(o[mt][dt][0] * la[mt * 2], o[mt][dt][1] * la[mt * 2], wh, wl);
            *(uint32_t*)(yh + a0) = wh;
            *(uint32_t*)(yl + a0) = wl;
            size_t a1 = a0 + (size_t)8 * CC;
            split_pair(o[mt][dt][2] * la[mt * 2 + 1], o[mt][dt][3] * la[mt * 2 + 1], wh, wl);
            *(uint32_t*)(yh + a1) = wh;
            *(uint32_t*)(yl + a1) = wl;
        }
    }
}

// ---------------- launch ----------------------------------------------------
extern "C" void kernel_launch(void* const* d_in, const int* in_sizes, int n_in,
                              void* d_out, int out_size)
{
    const float* x  = (const float*)d_in[0];   // [4,1024,1024]
    const float* Wa = (const float*)d_in[1];   // [1024,3072]
    const float* Wp = (const float*)d_in[2];   // [1024,1024]
    float* out = (float*)d_out;                // [4,1024,1024]

    void* p;
    cudaGetSymbolAddress(&p, g_last);  float* last  = (float*)p;
    cudaGetSymbolAddress(&p, g_idx);   int*   idx   = (int*)p;
    cudaGetSymbolAddress(&p, g_qlast); float* qlast = (float*)p;
    cudaGetSymbolAddress(&p, g_u);     float* u     = (float*)p;
    cudaGetSymbolAddress(&p, g_xh);   __nv_bfloat16* xh  = (__nv_bfloat16*)p;
    cudaGetSymbolAddress(&p, g_xl);   __nv_bfloat16* xl  = (__nv_bfloat16*)p;
    cudaGetSymbolAddress(&p, g_wah);  __nv_bfloat16* wah = (__nv_bfloat16*)p;
    cudaGetSymbolAddress(&p, g_wal);  __nv_bfloat16* wal = (__nv_bfloat16*)p;
    cudaGetSymbolAddress(&p, g_wph);  __nv_bfloat16* wph = (__nv_bfloat16*)p;
    cudaGetSymbolAddress(&p, g_wpl);  __nv_bfloat16* wpl = (__nv_bfloat16*)p;
    cudaGetSymbolAddress(&p, g_yh);   __nv_bfloat16* yh  = (__nv_bfloat16*)p;
    cudaGetSymbolAddress(&p, g_yl);   __nv_bfloat16* yl  = (__nv_bfloat16*)p;
    cudaGetSymbolAddress(&p, g_qh);   __nv_bfloat16* qhp = (__nv_bfloat16*)p;
    cudaGetSymbolAddress(&p, g_ql);   __nv_bfloat16* qlp = (__nv_bfloat16*)p;
    cudaGetSymbolAddress(&p, g_kh);   __nv_bfloat16* khp = (__nv_bfloat16*)p;
    cudaGetSymbolAddress(&p, g_kl);   __nv_bfloat16* klp = (__nv_bfloat16*)p;
    cudaGetSymbolAddress(&p, g_vh);   __nv_bfloat16* vhp = (__nv_bfloat16*)p;
    cudaGetSymbolAddress(&p, g_vl);   __nv_bfloat16* vlp = (__nv_bfloat16*)p;

    cudaFuncSetAttribute(gemm_bf16x3, cudaFuncAttributeMaxDynamicSharedMemorySize, GSMEM);
    cudaFuncSetAttribute(gemm_qkv, cudaFuncAttributeMaxDynamicSharedMemorySize, GSMEM);
    cudaFuncSetAttribute(attn_kernel, cudaFuncAttributeMaxDynamicSharedMemorySize, ASMEM);

    // slot 1-3
    qlast_kernel<<<BB * NH, 64>>>(x, Wa, qlast);
    uproj_kernel<<<dim3(BB, CC / 16), 256>>>(Wa, qlast, u);
    prep_kernel<<<PREP_TOTAL, 256>>>(x, Wa, Wp, xh, xl, wah, wal, wph, wpl);

    // slot 4 (profiled): coalesced scores
    scores_kernel<<<dim3(BB, TT / SC_TR), 128>>>(x, u, last);

    // slot 5: topk
    topk_kernel<<<BB * NH, 512>>>(last, idx);

    // slot 6: qkv GEMM with splitting epilogue
    gemm_qkv<<<dim3(3 * CC / 128, BB * TT / 128), 256, GSMEM>>>(
        xh, xl, wah, wal, qhp, qlp, khp, klp, vhp, vlp);

    // slot 7: mma attention -> yh/yl
    attn_kernel<<<dim3(BB * NH, TT / 128), 128, ASMEM>>>(
        qhp, qlp, khp, klp, vhp, vlp, idx, yh, yl);

    // slot 8: out = y @ W_proj
    gemm_bf16x3<<<dim3(CC / 128, BB * TT / 128), 256, GSMEM>>>(yh, yl, wph, wpl, out, CC);
}

// round 14
// speedup vs baseline: 2.4542x; 1.2214x over previous
#include <cuda_runtime.h>
#include <cuda_bf16.h>
#include <math.h>
#include <stdint.h>

// Problem constants
#define BB 4
#define TT 1024
#define CC 1024
#define NH 16
#define HD 64
#define KKEEP 391
#define REC 64
#define NONREC (TT - REC)       // 960

// ---------------- scratch (device globals; no allocation allowed) ----------
__device__ float g_last[BB * NH * TT];
__device__ int   g_idx[BB * NH * KKEEP];
__device__ float g_qlast[BB * CC];
__device__ float g_u[BB * CC * NH];
__device__ __nv_bfloat16 g_xh[BB * TT * CC];
__device__ __nv_bfloat16 g_xl[BB * TT * CC];
__device__ __nv_bfloat16 g_wah[3 * CC * CC];         // W_attn^T hi/lo [3072][1024]
__device__ __nv_bfloat16 g_wal[3 * CC * CC];
__device__ __nv_bfloat16 g_wph[CC * CC];             // W_proj^T hi/lo
__device__ __nv_bfloat16 g_wpl[CC * CC];
__device__ __nv_bfloat16 g_yh[BB * TT * CC];
__device__ __nv_bfloat16 g_yl[BB * TT * CC];
__device__ __nv_bfloat16 g_qh[BB * TT * CC];         // Q * 0.125, hi/lo
__device__ __nv_bfloat16 g_ql[BB * TT * CC];
__device__ __nv_bfloat16 g_kh[BB * TT * CC];
__device__ __nv_bfloat16 g_kl[BB * TT * CC];
__device__ __nv_bfloat16 g_vh[BB * TT * CC];
__device__ __nv_bfloat16 g_vl[BB * TT * CC];

// ---------------- helpers ---------------------------------------------------
__device__ __forceinline__ uint32_t smem_u32(const void* p) {
    uint32_t a;
    asm("{ .reg .u64 t; cvta.to.shared.u64 t, %1; cvt.u32.u64 %0, t; }" : "=r"(a) : "l"(p));
    return a;
}
__device__ __forceinline__ void cp_async16(uint32_t dst, const void* src) {
    asm volatile("cp.async.cg.shared.global [%0], [%1], 16;" :: "r"(dst), "l"(src));
}
__device__ __forceinline__ void cp_commit() {
    asm volatile("cp.async.commit_group;");
}
__device__ __forceinline__ void ldm_x4(uint32_t& r0, uint32_t& r1, uint32_t& r2, uint32_t& r3, uint32_t addr) {
    asm volatile("ldmatrix.sync.aligned.m8n8.x4.shared.b16 {%0,%1,%2,%3}, [%4];"
                 : "=r"(r0), "=r"(r1), "=r"(r2), "=r"(r3) : "r"(addr));
}
__device__ __forceinline__ void ldm_x2(uint32_t& r0, uint32_t& r1, uint32_t addr) {
    asm volatile("ldmatrix.sync.aligned.m8n8.x2.shared.b16 {%0,%1}, [%2];"
                 : "=r"(r0), "=r"(r1) : "r"(addr));
}
__device__ __forceinline__ void ldm_x4t(uint32_t* r, uint32_t addr) {
    asm volatile("ldmatrix.sync.aligned.m8n8.x4.trans.shared.b16 {%0,%1,%2,%3}, [%4];"
                 : "=r"(r[0]), "=r"(r[1]), "=r"(r[2]), "=r"(r[3]) : "r"(addr));
}
__device__ __forceinline__ void mma16816(float* d, const uint32_t* a, const uint32_t* b) {
    asm volatile(
        "mma.sync.aligned.m16n8k16.row.col.f32.bf16.bf16.f32 "
        "{%0,%1,%2,%3},{%4,%5,%6,%7},{%8,%9},{%0,%1,%2,%3};"
        : "+f"(d[0]), "+f"(d[1]), "+f"(d[2]), "+f"(d[3])
        : "r"(a[0]), "r"(a[1]), "r"(a[2]), "r"(a[3]), "r"(b[0]), "r"(b[1]));
}
__device__ __forceinline__ void split_bf16(float a, __nv_bfloat16& h, __nv_bfloat16& l) {
    h = __float2bfloat16(a);
    l = __float2bfloat16(a - __bfloat162float(h));
}
__device__ __forceinline__ void split_pair(float v0, float v1, uint32_t& wh, uint32_t& wl) {
    __nv_bfloat16 h0, l0, h1, l1;
    split_bf16(v0, h0, l0); split_bf16(v1, h1, l1);
    __nv_bfloat162 th(h0, h1), tl(l0, l1);
    wh = *(uint32_t*)&th; wl = *(uint32_t*)&tl;
}

// ---------------- merged prep: split x + transpose-split both weights -------
#define PREP_SPLIT 4096
#define PREP_WA (PREP_SPLIT + 3072)
#define PREP_TOTAL (PREP_WA + 1024)

__global__ __launch_bounds__(256) void prep_kernel(
    const float* __restrict__ x, const float* __restrict__ Wa, const float* __restrict__ Wp,
    __nv_bfloat16* __restrict__ xh, __nv_bfloat16* __restrict__ xl,
    __nv_bfloat16* __restrict__ wah, __nv_bfloat16* __restrict__ wal,
    __nv_bfloat16* __restrict__ wph, __nv_bfloat16* __restrict__ wpl)
{
    const int bid = blockIdx.x;
    if (bid < PREP_SPLIT) {
        int i = bid * 256 + threadIdx.x;
        float4 v = ((const float4*)x)[i];
        uint32_t h01, l01, h23, l23;
        split_pair(v.x, v.y, h01, l01);
        split_pair(v.z, v.w, h23, l23);
        ((uint32_t*)xh)[i * 2 + 0] = h01;
        ((uint32_t*)xh)[i * 2 + 1] = h23;
        ((uint32_t*)xl)[i * 2 + 0] = l01;
        ((uint32_t*)xl)[i * 2 + 1] = l23;
        return;
    }
    const float* in;
    __nv_bfloat16 *outh, *outl;
    int rows, cols, bx, by;
    if (bid < PREP_WA) {
        int id = bid - PREP_SPLIT;
        in = Wa; outh = wah; outl = wal; rows = CC; cols = 3 * CC;
        bx = (id % 96) * 32; by = (id / 96) * 32;
    } else {
        int id = bid - PREP_WA;
        in = Wp; outh = wph; outl = wpl; rows = CC; cols = CC;
        bx = (id % 32) * 32; by = (id / 32) * 32;
    }
    __shared__ float t[32][33];
    const int tx = threadIdx.x & 31, ty = threadIdx.x >> 5;
    int xcol = bx + tx;
    #pragma unroll
    for (int j = ty; j < 32; j += 8)
        t[j][tx] = in[(size_t)(by + j) * cols + xcol];
    __syncthreads();
    int xo = by + tx;
    #pragma unroll
    for (int j = ty; j < 32; j += 8) {
        float v = t[tx][j];
        __nv_bfloat16 h, l;
        split_bf16(v, h, l);
        outh[(size_t)(bx + j) * rows + xo] = h;
        outl[(size_t)(bx + j) * rows + xo] = l;
    }
}

// ---------------- mma.sync bf16 3-term GEMM, CTA 128x64, 3 CTAs/SM ----------
#define GK 1024
#define BKC 32
#define ARR_A 8192                 // 128 rows x 64B
#define ARR_B 4096                 // 64 rows x 64B
#define STG3 (2 * ARR_A + 2 * ARR_B)   // 24576
#define NSTG 3
#define GSMEM (NSTG * STG3)        // 73728

__device__ __forceinline__ void gemm_load_stage(
    uint32_t sdst, const __nv_bfloat16* Ahb, const __nv_bfloat16* Alb,
    const __nv_bfloat16* Bhb, const __nv_bfloat16* Blb, int k0, int tid)
{
    #pragma unroll
    for (int it = 0; it < 6; it++) {
        int i = tid + it * 256;            // 0..1535
        const __nv_bfloat16* src;
        uint32_t dst;
        if (i < 1024) {                    // A arrays (512 chunks each)
            int j = i & 511;
            int r = j >> 2, c = j & 3;
            int cs = c ^ ((r >> 1) & 3);
            src = (i < 512 ? Ahb : Alb) + (size_t)r * GK + k0 + c * 8;
            dst = sdst + (i < 512 ? 0u : (uint32_t)ARR_A) + (uint32_t)(r * 64 + cs * 16);
        } else {                           // B arrays (256 chunks each)
            int j = i & 255;
            int r = j >> 2, c = j & 3;
            int cs = c ^ ((r >> 1) & 3);
            src = (i < 1280 ? Bhb : Blb) + (size_t)r * GK + k0 + c * 8;
            dst = sdst + 2 * ARR_A + (i < 1280 ? 0u : (uint32_t)ARR_B) + (uint32_t)(r * 64 + cs * 16);
        }
        cp_async16(dst, src);
    }
    cp_commit();
}

// mainloop: 8 warps (4m x 2n), warp tile 32x32, acc[2][4][4]
#define GEMM_MAIN(acc, Ah, Al, Bh, Bl)                                          \
    extern __shared__ char dsm[];                                               \
    const uint32_t sb = smem_u32(dsm);                                          \
    const int tid = threadIdx.x;                                                \
    const int wid = tid >> 5;                                                   \
    const int lane = tid & 31;                                                  \
    const int wm = wid >> 1;                                                    \
    const int wn = wid & 1;                                                     \
    const int m0 = blockIdx.y * 128;                                            \
    const int n0 = blockIdx.x * 64;                                             \
    const __nv_bfloat16* Ahb = Ah + (size_t)m0 * GK;                            \
    const __nv_bfloat16* Alb = Al + (size_t)m0 * GK;                            \
    const __nv_bfloat16* Bhb = Bh + (size_t)n0 * GK;                            \
    const __nv_bfloat16* Blb = Bl + (size_t)n0 * GK;                            \
    float acc[2][4][4];                                                         \
    _Pragma("unroll")                                                           \
    for (int i = 0; i < 2; i++)                                                 \
        _Pragma("unroll")                                                       \
        for (int j = 0; j < 4; j++)                                             \
            _Pragma("unroll")                                                   \
            for (int r = 0; r < 4; r++) acc[i][j][r] = 0.f;                     \
    const int arow = wm * 32 + (lane & 15);                                     \
    const int achk = lane >> 4;                                                 \
    const uint32_t s_a = (uint32_t)((arow >> 1) & 3);                           \
    const int brow = wn * 32 + (lane & 7);                                      \
    const int bchk = (lane >> 3) & 1;                                           \
    const uint32_t s_b = (uint32_t)((brow >> 1) & 3);                           \
    gemm_load_stage(sb,        Ahb, Alb, Bhb, Blb, 0,   tid);                   \
    gemm_load_stage(sb + STG3, Ahb, Alb, Bhb, Blb, BKC, tid);                   \
    const int NCH = GK / BKC;                                                   \
    for (int ch = 0; ch < NCH; ch++) {                                          \
        if (ch + 1 < NCH) { asm volatile("cp.async.wait_group 1;"); }           \
        else              { asm volatile("cp.async.wait_group 0;"); }           \
        __syncthreads();                                                        \
        if (ch + 2 < NCH)                                                       \
            gemm_load_stage(sb + ((ch + 2) % NSTG) * STG3, Ahb, Alb, Bhb, Blb,  \
                            (ch + 2) * BKC, tid);                               \
        const uint32_t st = sb + (ch % NSTG) * STG3;                            \
        _Pragma("unroll")                                                       \
        for (int ks = 0; ks < 2; ks++) {                                        \
            const uint32_t kc = (uint32_t)(ks * 2);                             \
            uint32_t af[2][4], bf[4][2], bt[4][2];                              \
            _Pragma("unroll")                                                   \
            for (int mt = 0; mt < 2; mt++) {                                    \
                uint32_t ad = st + (uint32_t)((arow + mt * 16) * 64) + (((kc + achk) ^ s_a) << 4); \
                ldm_x4(af[mt][0], af[mt][1], af[mt][2], af[mt][3], ad);         \
            }                                                                   \
            _Pragma("unroll")                                                   \
            for (int nt = 0; nt < 4; nt++) {                                    \
                uint32_t bd = st + 2 * ARR_A + (uint32_t)((brow + nt * 8) * 64) + (((kc + bchk) ^ s_b) << 4); \
                ldm_x2(bf[nt][0], bf[nt][1], bd);                               \
            }                                                                   \
            _Pragma("unroll")                                                   \
            for (int mt = 0; mt < 2; mt++)                                      \
                _Pragma("unroll")                                               \
                for (int nt = 0; nt < 4; nt++) mma16816(acc[mt][nt], af[mt], bf[nt]); \
            _Pragma("unroll")                                                   \
            for (int nt = 0; nt < 4; nt++) {                                    \
                uint32_t bd = st + 2 * ARR_A + ARR_B + (uint32_t)((brow + nt * 8) * 64) + (((kc + bchk) ^ s_b) << 4); \
                ldm_x2(bt[nt][0], bt[nt][1], bd);                               \
            }                                                                   \
            _Pragma("unroll")                                                   \
            for (int mt = 0; mt < 2; mt++)                                      \
                _Pragma("unroll")                                               \
                for (int nt = 0; nt < 4; nt++) mma16816(acc[mt][nt], af[mt], bt[nt]); \
            _Pragma("unroll")                                                   \
            for (int mt = 0; mt < 2; mt++) {                                    \
                uint32_t ad = st + ARR_A + (uint32_t)((arow + mt * 16) * 64) + (((kc + achk) ^ s_a) << 4); \
                ldm_x4(af[mt][0], af[mt][1], af[mt][2], af[mt][3], ad);         \
            }                                                                   \
            _Pragma("unroll")                                                   \
            for (int mt = 0; mt < 2; mt++)                                      \
                _Pragma("unroll")                                               \
                for (int nt = 0; nt < 4; nt++) mma16816(acc[mt][nt], af[mt], bf[nt]); \
        }                                                                       \
        __syncthreads();                                                        \
    }

// GEMM2: fp32 C output
__global__ __launch_bounds__(256, 3) void gemm_bf16x3(
    const __nv_bfloat16* __restrict__ Ah, const __nv_bfloat16* __restrict__ Al,
    const __nv_bfloat16* __restrict__ Bh, const __nv_bfloat16* __restrict__ Bl,
    float* __restrict__ C, int N)
{
    GEMM_MAIN(acc, Ah, Al, Bh, Bl)
    const int mrow = m0 + wm * 32 + (lane >> 2);
    const int ncol = n0 + wn * 32 + (lane & 3) * 2;
    #pragma unroll
    for (int mt = 0; mt < 2; mt++)
        #pragma unroll
        for (int nt = 0; nt < 4; nt++) {
            float* c0 = C + (size_t)(mrow + mt * 16) * N + ncol + nt * 8;
            *(float2*)c0 = make_float2(acc[mt][nt][0], acc[mt][nt][1]);
            float* c1 = c0 + (size_t)8 * N;
            *(float2*)c1 = make_float2(acc[mt][nt][2], acc[mt][nt][3]);
        }
}

// GEMM1: N=3072 fixed; epilogue splits into q(scaled)/k/v bf16 hi/lo
__global__ __launch_bounds__(256, 3) void gemm_qkv(
    const __nv_bfloat16* __restrict__ Ah, const __nv_bfloat16* __restrict__ Al,
    const __nv_bfloat16* __restrict__ Bh, const __nv_bfloat16* __restrict__ Bl,
    __nv_bfloat16* __restrict__ qh, __nv_bfloat16* __restrict__ ql,
    __nv_bfloat16* __restrict__ kh, __nv_bfloat16* __restrict__ kl,
    __nv_bfloat16* __restrict__ vh, __nv_bfloat16* __restrict__ vl)
{
    GEMM_MAIN(acc, Ah, Al, Bh, Bl)
    const int region = n0 >> 10;
    __nv_bfloat16 *oh, *ol;
    float sc;
    if (region == 0)      { oh = qh; ol = ql; sc = 0.125f; }
    else if (region == 1) { oh = kh; ol = kl; sc = 1.f; }
    else                  { oh = vh; ol = vl; sc = 1.f; }
    const int mrow = m0 + wm * 32 + (lane >> 2);
    const int colr = (n0 & 1023) + wn * 32 + (lane & 3) * 2;
    #pragma unroll
    for (int mt = 0; mt < 2; mt++)
        #pragma unroll
        for (int nt = 0; nt < 4; nt++) {
            size_t o0 = (size_t)(mrow + mt * 16) * CC + colr + nt * 8;
            uint32_t wh, wl;
            split_pair(acc[mt][nt][0] * sc, acc[mt][nt][1] * sc, wh, wl);
            *(uint32_t*)(oh + o0) = wh;
            *(uint32_t*)(ol + o0) = wl;
            size_t o1 = o0 + (size_t)8 * CC;
            split_pair(acc[mt][nt][2] * sc, acc[mt][nt][3] * sc, wh, wl);
            *(uint32_t*)(oh + o1) = wh;
            *(uint32_t*)(ol + o1) = wl;
        }
}

// ---------------- fp32 selection-score path ---------------------------------
__global__ __launch_bounds__(256) void qlast_kernel(
    const float* __restrict__ x, const float* __restrict__ Wa,
    float* __restrict__ qlast)
{
    const int b = blockIdx.x >> 4, h = blockIdx.x & 15;
    const int tid = threadIdx.x;
    __shared__ float xs[CC];
    __shared__ float red[4][64];
    for (int c = tid; c < CC; c += 256)
        xs[c] = x[((size_t)b * TT + (TT - 1)) * CC + c];
    __syncthreads();
    const int col = h * HD + (tid & 63);
    const int q = tid >> 6;              // 0..3 c-range
    float s = 0.f;
    #pragma unroll 4
    for (int c = q * 256; c < q * 256 + 256; c++)
        s += xs[c] * Wa[(size_t)c * (3 * CC) + col];
    red[q][tid & 63] = s;
    __syncthreads();
    if (tid < 64)
        qlast[(b * NH + h) * HD + tid] = red[0][tid] + red[1][tid] + red[2][tid] + red[3][tid];
}

__global__ __launch_bounds__(256) void uproj_kernel(
    const float* __restrict__ Wa, const float* __restrict__ qlast,
    float* __restrict__ u)
{
    const int b = blockIdx.x;
    const int c = blockIdx.y * 16 + (threadIdx.x >> 4);
    const int h = threadIdx.x & 15;
    __shared__ float qs[CC];
    for (int i = threadIdx.x; i < CC; i += 256) qs[i] = qlast[b * CC + i];
    __syncthreads();
    const float* wrow = Wa + (size_t)c * (3 * CC) + CC + h * HD;
    const float* qh = qs + h * HD;
    float s = 0.f;
    #pragma unroll
    for (int d = 0; d < HD; d++) s += wrow[d] * qh[d];
    u[((size_t)b * CC + c) * NH + h] = s;
}

// coalesced scores: block = 128 thr (32 t-rows x 4 head-groups), grid (BB, 32)
#define SC_TR 32
#define SC_PAD 129

__global__ __launch_bounds__(128) void scores_kernel(
    const float* __restrict__ x, const float* __restrict__ u,
    float* __restrict__ last)
{
    const int b = blockIdx.x;
    const int t0 = blockIdx.y * SC_TR;
    const int tid = threadIdx.x;
    const int tloc = tid & 31;
    const int hg = tid >> 5;

    __shared__ float xs[SC_TR][SC_PAD];
    __shared__ float us[128][NH];

    float4 acc = make_float4(0.f, 0.f, 0.f, 0.f);

    for (int c0 = 0; c0 < CC; c0 += 128) {
        __syncthreads();
        #pragma unroll
        for (int it = 0; it < 8; it++) {
            int flat = it * 128 + tid;
            int r = flat >> 5;
            int c4 = flat & 31;
            float4 v = *(const float4*)(x + ((size_t)(b * TT + t0 + r)) * CC + c0 + c4 * 4);
            xs[r][c4 * 4 + 0] = v.x; xs[r][c4 * 4 + 1] = v.y;
            xs[r][c4 * 4 + 2] = v.z; xs[r][c4 * 4 + 3] = v.w;
        }
        #pragma unroll
        for (int it = 0; it < 4; it++) {
            int flat = it * 128 + tid;
            int ci = flat >> 2;
            int h4 = flat & 3;
            float4 v = *(const float4*)(u + ((size_t)(b * CC + c0 + ci)) * NH + h4 * 4);
            *(float4*)&us[ci][h4 * 4] = v;
        }
        __syncthreads();

        #pragma unroll 4
        for (int ci = 0; ci < 128; ci++) {
            float xv = xs[tloc][ci];
            float4 uu = *(const float4*)&us[ci][hg * 4];
            acc.x += xv * uu.x; acc.y += xv * uu.y;
            acc.z += xv * uu.z; acc.w += xv * uu.w;
        }
    }

    const int t = t0 + tloc;
    last[(b * NH + hg * 4 + 0) * TT + t] = acc.x * 0.125f;
    last[(b * NH + hg * 4 + 1) * TT + t] = acc.y * 0.125f;
    last[(b * NH + hg * 4 + 2) * TT + t] = acc.z * 0.125f;
    last[(b * NH + hg * 4 + 3) * TT + t] = acc.w * 0.125f;
}

// ---------------- top-k set selection via bitonic sort ---------------------
__global__ __launch_bounds__(512) void topk_kernel(const float* __restrict__ last,
                                                   int* __restrict__ idxout)
{
    __shared__ unsigned long long s[TT];
    const int bh = blockIdx.x;
    const int tid = threadIdx.x;

    for (int t = tid; t < TT; t += 512) {
        unsigned u;
        if (t >= NONREC) {
            u = 0xFFFFFFFFu;
        } else {
            u = __float_as_uint(last[bh * TT + t]);
            u = (u & 0x80000000u) ? ~u : (u | 0x80000000u);
        }
        s[t] = ((unsigned long long)u << 32) | (unsigned)t;
    }
    __syncthreads();

    for (int k = 2; k <= TT; k <<= 1) {
        for (int j = k >> 1; j > 0; j >>= 1) {
            for (int i = tid; i < TT; i += 512) {
                int ix = i ^ j;
                if (ix > i) {
                    bool desc = ((i & k) == 0);
                    unsigned long long a = s[i], b = s[ix];
                    bool sw = desc ? (a < b) : (a > b);
                    if (sw) { s[i] = b; s[ix] = a; }
                }
            }
            __syncthreads();
        }
    }
    for (int i = tid; i < KKEEP; i += 512)
        idxout[bh * KKEEP + i] = (int)(s[i] & 0xFFFFFFFFu);
}

// ---------------- mma-based pruned attention --------------------------------
#define ASMEM (32768 + 2 * 32768)        // 98304

__device__ __forceinline__ void attn_kv_prefetch(
    char* smp, uint32_t sb, uint32_t stgoff,
    const __nv_bfloat16* kh, const __nv_bfloat16* kl,
    const __nv_bfloat16* vh, const __nv_bfloat16* vl,
    const int* idxp, int b, int hoff, int c0, int cn, int tid)
{
    for (int i = tid; i < 64 * 8; i += 128) {
        int r = i >> 3, c = i & 7;
        uint32_t off = (uint32_t)(r * 128 + (((c ^ (r & 7))) << 4));
        if (r < cn) {
            int kt = idxp[c0 + r];
            size_t g = ((size_t)(b * TT + kt)) * CC + hoff + c * 8;
            cp_async16(sb + stgoff + off,         kh + g);
            cp_async16(sb + stgoff + 8192 + off,  kl + g);
            cp_async16(sb + stgoff + 16384 + off, vh + g);
            cp_async16(sb + stgoff + 24576 + off, vl + g);
        } else {
            uint4 z = make_uint4(0, 0, 0, 0);
            *(uint4*)(smp + stgoff + off) = z;
            *(uint4*)(smp + stgoff + 8192 + off) = z;
            *(uint4*)(smp + stgoff + 16384 + off) = z;
            *(uint4*)(smp + stgoff + 24576 + off) = z;
        }
    }
    cp_commit();
}

__global__ __launch_bounds__(128) void attn_kernel(
    const __nv_bfloat16* __restrict__ qh, const __nv_bfloat16* __restrict__ ql,
    const __nv_bfloat16* __restrict__ kh, const __nv_bfloat16* __restrict__ kl,
    const __nv_bfloat16* __restrict__ vh, const __nv_bfloat16* __restrict__ vl,
    const int* __restrict__ idx,
    __nv_bfloat16* __restrict__ yh, __nv_bfloat16* __restrict__ yl)
{
    extern __shared__ char asmem[];
    const uint32_t sb = smem_u32(asmem);
    const int tid = threadIdx.x;
    const int wq = tid >> 5;
    const int lane = tid & 31;
    const int bh = blockIdx.x;
    const int b = bh >> 4, h = bh & 15;
    const int qt0 = blockIdx.y * 128;
    const int hoff = h * HD;
    const int* idxp = idx + bh * KKEEP;

    for (int i = tid; i < 128 * 8; i += 128) {
        int r = i >> 3, c = i & 7;
        size_t g = ((size_t)(b * TT + qt0 + r)) * CC + hoff + c * 8;
        uint32_t off = (uint32_t)(r * 128 + (((c ^ (r & 7))) << 4));
        cp_async16(sb + off, qh + g);
        cp_async16(sb + 16384 + off, ql + g);
    }
    cp_commit();

    const int nch = (KKEEP + 63) / 64;   // 7
    attn_kv_prefetch(asmem, sb, 32768, kh, kl, vh, vl, idxp, b, hoff, 0, 64, tid);

    float o[2][8][4];
    #pragma unroll
    for (int mt = 0; mt < 2; mt++)
        #pragma unroll
        for (int dt = 0; dt < 8; dt++)
            #pragma unroll
            for (int r = 0; r < 4; r++) o[mt][dt][r] = 0.f;
    float la[4] = {0.f, 0.f, 0.f, 0.f};

    for (int ch = 0; ch < nch; ch++) {
        if (ch + 1 < nch) {
            int c1 = (ch + 1) * 64;
            attn_kv_prefetch(asmem, sb, 32768 + ((ch + 1) & 1) * 32768,
                             kh, kl, vh, vl, idxp, b, hoff, c1,
                             min(64, KKEEP - c1), tid);
            asm volatile("cp.async.wait_group 1;");
        } else {
            asm volatile("cp.async.wait_group 0;");
        }
        __syncthreads();

        const uint32_t stg = sb + 32768 + (uint32_t)((ch & 1) * 32768);

        #pragma unroll
        for (int mt = 0; mt < 2; mt++) {
            uint32_t ah[4][4], al[4][4];
            {
                int row = wq * 32 + mt * 16 + (lane & 15);
                #pragma unroll
                for (int kd = 0; kd < 4; kd++) {
                    int chv = kd * 2 + (lane >> 4);
                    uint32_t ad = (uint32_t)(row * 128 + (((chv ^ (row & 7))) << 4));
                    ldm_x4(ah[kd][0], ah[kd][1], ah[kd][2], ah[kd][3], sb + ad);
                    ldm_x4(al[kd][0], al[kd][1], al[kd][2], al[kd][3], sb + 16384 + ad);
                }
            }
            #pragma unroll
            for (int ntp = 0; ntp < 4; ntp++) {
                float s0[4] = {0.f, 0.f, 0.f, 0.f};
                float s1[4] = {0.f, 0.f, 0.f, 0.f};
                {
                    int rowe = ntp * 16 + (lane & 7);
                    int rowo = rowe + 8;
                    #pragma unroll
                    for (int kd = 0; kd < 4; kd++) {
                        int chv = kd * 2 + ((lane >> 3) & 1);
                        uint32_t ae = (uint32_t)(rowe * 128 + (((chv ^ (rowe & 7))) << 4));
                        uint32_t ao = (uint32_t)(rowo * 128 + (((chv ^ (rowo & 7))) << 4));
                        uint32_t bhe[2], ble[2], bho[2], blo2[2];
                        ldm_x2(bhe[0], bhe[1], stg + ae);
                        ldm_x2(ble[0], ble[1], stg + 8192 + ae);
                        ldm_x2(bho[0], bho[1], stg + ao);
                        ldm_x2(blo2[0], blo2[1], stg + 8192 + ao);
                        mma16816(s0, ah[kd], bhe);
                        mma16816(s0, ah[kd], ble);
                        mma16816(s0, al[kd], bhe);
                        mma16816(s1, ah[kd], bho);
                        mma16816(s1, ah[kd], blo2);
                        mma16816(s1, al[kd], bho);
                    }
                }
                const int kb = ch * 64 + ntp * 16 + 2 * (lane & 3);
                float p0 = (kb     < KKEEP) ? __expf(s0[0]) : 0.f;
                float p1 = (kb + 1 < KKEEP) ? __expf(s0[1]) : 0.f;
                float p2 = (kb     < KKEEP) ? __expf(s0[2]) : 0.f;
                float p3 = (kb + 1 < KKEEP) ? __expf(s0[3]) : 0.f;
                float p4 = (kb + 8 < KKEEP) ? __expf(s1[0]) : 0.f;
                float p5 = (kb + 9 < KKEEP) ? __expf(s1[1]) : 0.f;
                float p6 = (kb + 8 < KKEEP) ? __expf(s1[2]) : 0.f;
                float p7 = (kb + 9 < KKEEP) ? __expf(s1[3]) : 0.f;
                la[mt * 2 + 0] += (p0 + p1) + (p4 + p5);
                la[mt * 2 + 1] += (p2 + p3) + (p6 + p7);
                uint32_t phi[4], plo[4];
                {
                    float vs[8] = {p0, p1, p2, p3, p4, p5, p6, p7};
                    #pragma unroll
                    for (int j = 0; j < 4; j++) {
                        __nv_bfloat16 ha = __float2bfloat16(vs[2 * j]);
                        __nv_bfloat16 hb = __float2bfloat16(vs[2 * j + 1]);
                        __nv_bfloat162 th(ha, hb);
                        phi[j] = *(uint32_t*)&th;
                        __nv_bfloat162 tl(__float2bfloat16(vs[2 * j] - __bfloat162float(ha)),
                                          __float2bfloat16(vs[2 * j + 1] - __bfloat162float(hb)));
                        plo[j] = *(uint32_t*)&tl;
                    }
                }
                #pragma unroll
                for (int dp = 0; dp < 4; dp++) {
                    int g = lane >> 3;
                    int krow = ntp * 16 + ((g & 1) << 3) + (lane & 7);
                    int chv = dp * 2 + (g >> 1);
                    uint32_t av = (uint32_t)(krow * 128 + (((chv ^ (krow & 7))) << 4));
                    uint32_t vbh[4], vbl[4];
                    ldm_x4t(vbh, stg + 16384 + av);
                    ldm_x4t(vbl, stg + 24576 + av);
                    mma16816(o[mt][dp * 2],     phi, &vbh[0]);
                    mma16816(o[mt][dp * 2],     plo, &vbh[0]);
                    mma16816(o[mt][dp * 2],     phi, &vbl[0]);
                    mma16816(o[mt][dp * 2 + 1], phi, &vbh[2]);
                    mma16816(o[mt][dp * 2 + 1], plo, &vbh[2]);
                    mma16816(o[mt][dp * 2 + 1], phi, &vbl[2]);
                }
            }
        }
        __syncthreads();
    }

    #pragma unroll
    for (int j = 0; j < 4; j++) {
        la[j] += __shfl_xor_sync(0xFFFFFFFFu, la[j], 1);
        la[j] += __shfl_xor_sync(0xFFFFFFFFu, la[j], 2);
        la[j] = 1.f / la[j];
    }

    #pragma unroll
    for (int mt = 0; mt < 2; mt++) {
        const int row0 = qt0 + wq * 32 + mt * 16 + (lane >> 2);
        #pragma unroll
        for (int dt = 0; dt < 8; dt++) {
            const int col = dt * 8 + 2 * (lane & 3);
            size_t a0 = ((size_t)(b * TT + row0)) * CC + hoff + col;
            uint32_t wh, wl;
            split_pair(o[mt][dt][0] * la[mt * 2], o[mt][dt][1] * la[mt * 2], wh, wl);
            *(uint32_t*)(yh + a0) = wh;
            *(uint32_t*)(yl + a0) = wl;
            size_t a1 = a0 + (size_t)8 * CC;
            split_pair(o[mt][dt][2] * la[mt * 2 + 1], o[mt][dt][3] * la[mt * 2 + 1], wh, wl);
            *(uint32_t*)(yh + a1) = wh;
            *(uint32_t*)(yl + a1) = wl;
        }
    }
}

// ---------------- launch ----------------------------------------------------
extern "C" void kernel_launch(void* const* d_in, const int* in_sizes, int n_in,
                              void* d_out, int out_size)
{
    const float* x  = (const float*)d_in[0];   // [4,1024,1024]
    const float* Wa = (const float*)d_in[1];   // [1024,3072]
    const float* Wp = (const float*)d_in[2];   // [1024,1024]
    float* out = (float*)d_out;                // [4,1024,1024]

    void* p;
    cudaGetSymbolAddress(&p, g_last);  float* last  = (float*)p;
    cudaGetSymbolAddress(&p, g_idx);   int*   idx   = (int*)p;
    cudaGetSymbolAddress(&p, g_qlast); float* qlast = (float*)p;
    cudaGetSymbolAddress(&p, g_u);     float* u     = (float*)p;
    cudaGetSymbolAddress(&p, g_xh);   __nv_bfloat16* xh  = (__nv_bfloat16*)p;
    cudaGetSymbolAddress(&p, g_xl);   __nv_bfloat16* xl  = (__nv_bfloat16*)p;
    cudaGetSymbolAddress(&p, g_wah);  __nv_bfloat16* wah = (__nv_bfloat16*)p;
    cudaGetSymbolAddress(&p, g_wal);  __nv_bfloat16* wal = (__nv_bfloat16*)p;
    cudaGetSymbolAddress(&p, g_wph);  __nv_bfloat16* wph = (__nv_bfloat16*)p;
    cudaGetSymbolAddress(&p, g_wpl);  __nv_bfloat16* wpl = (__nv_bfloat16*)p;
    cudaGetSymbolAddress(&p, g_yh);   __nv_bfloat16* yh  = (__nv_bfloat16*)p;
    cudaGetSymbolAddress(&p, g_yl);   __nv_bfloat16* yl  = (__nv_bfloat16*)p;
    cudaGetSymbolAddress(&p, g_qh);   __nv_bfloat16* qhp = (__nv_bfloat16*)p;
    cudaGetSymbolAddress(&p, g_ql);   __nv_bfloat16* qlp = (__nv_bfloat16*)p;
    cudaGetSymbolAddress(&p, g_kh);   __nv_bfloat16* khp = (__nv_bfloat16*)p;
    cudaGetSymbolAddress(&p, g_kl);   __nv_bfloat16* klp = (__nv_bfloat16*)p;
    cudaGetSymbolAddress(&p, g_vh);   __nv_bfloat16* vhp = (__nv_bfloat16*)p;
    cudaGetSymbolAddress(&p, g_vl);   __nv_bfloat16* vlp = (__nv_bfloat16*)p;

    cudaFuncSetAttribute(gemm_bf16x3, cudaFuncAttributeMaxDynamicSharedMemorySize, GSMEM);
    cudaFuncSetAttribute(gemm_qkv, cudaFuncAttributeMaxDynamicSharedMemorySize, GSMEM);
    cudaFuncSetAttribute(attn_kernel, cudaFuncAttributeMaxDynamicSharedMemorySize, ASMEM);

    // slot 1-3
    qlast_kernel<<<BB * NH, 256>>>(x, Wa, qlast);
    uproj_kernel<<<dim3(BB, CC / 16), 256>>>(Wa, qlast, u);
    prep_kernel<<<PREP_TOTAL, 256>>>(x, Wa, Wp, xh, xl, wah, wal, wph, wpl);

    // slot 4 (profiled): qkv GEMM, 128x64 tiles, 3 CTAs/SM
    gemm_qkv<<<dim3(3 * CC / 64, BB * TT / 128), 256, GSMEM>>>(
        xh, xl, wah, wal, qhp, qlp, khp, klp, vhp, vlp);

    // slot 5-6: selection scores + topk
    scores_kernel<<<dim3(BB, TT / SC_TR), 128>>>(x, u, last);
    topk_kernel<<<BB * NH, 512>>>(last, idx);

    // slot 7: mma attention -> yh/yl
    attn_kernel<<<dim3(BB * NH, TT / 128), 128, ASMEM>>>(
        qhp, qlp, khp, klp, vhp, vlp, idx, yh, yl);

    // slot 8: out = y @ W_proj
    gemm_bf16x3<<<dim3(CC / 64, BB * TT / 128), 256, GSMEM>>>(yh, yl, wph, wpl, out, CC);
}

// round 16
// speedup vs baseline: 2.5148x; 1.0247x over previous
#include <cuda_runtime.h>
#include <cuda_bf16.h>
#include <math.h>
#include <stdint.h>

// Problem constants
#define BB 4
#define TT 1024
#define CC 1024
#define NH 16
#define HD 64
#define KKEEP 391
#define REC 64
#define NONREC (TT - REC)       // 960

// ---------------- scratch (device globals; no allocation allowed) ----------
__device__ float g_last[BB * NH * TT];
__device__ int   g_idx[BB * NH * KKEEP];
__device__ float g_qlast[BB * CC];
__device__ float g_u[BB * CC * NH];
__device__ __nv_bfloat16 g_xh[BB * TT * CC];
__device__ __nv_bfloat16 g_xl[BB * TT * CC];
__device__ __nv_bfloat16 g_wah[3 * CC * CC];         // W_attn^T hi/lo [3072][1024]
__device__ __nv_bfloat16 g_wal[3 * CC * CC];
__device__ __nv_bfloat16 g_wph[CC * CC];             // W_proj^T hi/lo
__device__ __nv_bfloat16 g_wpl[CC * CC];
__device__ __nv_bfloat16 g_yh[BB * TT * CC];
__device__ __nv_bfloat16 g_yl[BB * TT * CC];
__device__ __nv_bfloat16 g_qh[BB * TT * CC];         // Q * 0.125, hi/lo
__device__ __nv_bfloat16 g_ql[BB * TT * CC];
__device__ __nv_bfloat16 g_kh[BB * TT * CC];
__device__ __nv_bfloat16 g_kl[BB * TT * CC];
__device__ __nv_bfloat16 g_vh[BB * TT * CC];
__device__ __nv_bfloat16 g_vl[BB * TT * CC];

// ---------------- helpers ---------------------------------------------------
__device__ __forceinline__ uint32_t smem_u32(const void* p) {
    uint32_t a;
    asm("{ .reg .u64 t; cvta.to.shared.u64 t, %1; cvt.u32.u64 %0, t; }" : "=r"(a) : "l"(p));
    return a;
}
__device__ __forceinline__ void cp_async16(uint32_t dst, const void* src) {
    asm volatile("cp.async.cg.shared.global [%0], [%1], 16;" :: "r"(dst), "l"(src));
}
__device__ __forceinline__ void cp_commit() {
    asm volatile("cp.async.commit_group;");
}
__device__ __forceinline__ void ldm_x4(uint32_t& r0, uint32_t& r1, uint32_t& r2, uint32_t& r3, uint32_t addr) {
    asm volatile("ldmatrix.sync.aligned.m8n8.x4.shared.b16 {%0,%1,%2,%3}, [%4];"
                 : "=r"(r0), "=r"(r1), "=r"(r2), "=r"(r3) : "r"(addr));
}
__device__ __forceinline__ void ldm_x4t(uint32_t* r, uint32_t addr) {
    asm volatile("ldmatrix.sync.aligned.m8n8.x4.trans.shared.b16 {%0,%1,%2,%3}, [%4];"
                 : "=r"(r[0]), "=r"(r[1]), "=r"(r[2]), "=r"(r[3]) : "r"(addr));
}
__device__ __forceinline__ void mma16816(float* d, const uint32_t* a, const uint32_t* b) {
    asm volatile(
        "mma.sync.aligned.m16n8k16.row.col.f32.bf16.bf16.f32 "
        "{%0,%1,%2,%3},{%4,%5,%6,%7},{%8,%9},{%0,%1,%2,%3};"
        : "+f"(d[0]), "+f"(d[1]), "+f"(d[2]), "+f"(d[3])
        : "r"(a[0]), "r"(a[1]), "r"(a[2]), "r"(a[3]), "r"(b[0]), "r"(b[1]));
}
__device__ __forceinline__ void split_bf16(float a, __nv_bfloat16& h, __nv_bfloat16& l) {
    h = __float2bfloat16(a);
    l = __float2bfloat16(a - __bfloat162float(h));
}
__device__ __forceinline__ void split_pair(float v0, float v1, uint32_t& wh, uint32_t& wl) {
    __nv_bfloat16 h0, l0, h1, l1;
    split_bf16(v0, h0, l0); split_bf16(v1, h1, l1);
    __nv_bfloat162 th(h0, h1), tl(l0, l1);
    wh = *(uint32_t*)&th; wl = *(uint32_t*)&tl;
}

// ---------------- merged prep: split x + transpose-split both weights -------
#define PREP_SPLIT 4096
#define PREP_WA (PREP_SPLIT + 3072)
#define PREP_TOTAL (PREP_WA + 1024)

__global__ __launch_bounds__(256) void prep_kernel(
    const float* __restrict__ x, const float* __restrict__ Wa, const float* __restrict__ Wp,
    __nv_bfloat16* __restrict__ xh, __nv_bfloat16* __restrict__ xl,
    __nv_bfloat16* __restrict__ wah, __nv_bfloat16* __restrict__ wal,
    __nv_bfloat16* __restrict__ wph, __nv_bfloat16* __restrict__ wpl)
{
    const int bid = blockIdx.x;
    if (bid < PREP_SPLIT) {
        int i = bid * 256 + threadIdx.x;
        float4 v = ((const float4*)x)[i];
        uint32_t h01, l01, h23, l23;
        split_pair(v.x, v.y, h01, l01);
        split_pair(v.z, v.w, h23, l23);
        ((uint32_t*)xh)[i * 2 + 0] = h01;
        ((uint32_t*)xh)[i * 2 + 1] = h23;
        ((uint32_t*)xl)[i * 2 + 0] = l01;
        ((uint32_t*)xl)[i * 2 + 1] = l23;
        return;
    }
    const float* in;
    __nv_bfloat16 *outh, *outl;
    int rows, cols, bx, by;
    if (bid < PREP_WA) {
        int id = bid - PREP_SPLIT;
        in = Wa; outh = wah; outl = wal; rows = CC; cols = 3 * CC;
        bx = (id % 96) * 32; by = (id / 96) * 32;
    } else {
        int id = bid - PREP_WA;
        in = Wp; outh = wph; outl = wpl; rows = CC; cols = CC;
        bx = (id % 32) * 32; by = (id / 32) * 32;
    }
    __shared__ float t[32][33];
    const int tx = threadIdx.x & 31, ty = threadIdx.x >> 5;
    int xcol = bx + tx;
    #pragma unroll
    for (int j = ty; j < 32; j += 8)
        t[j][tx] = in[(size_t)(by + j) * cols + xcol];
    __syncthreads();
    int xo = by + tx;
    #pragma unroll
    for (int j = ty; j < 32; j += 8) {
        float v = t[tx][j];
        __nv_bfloat16 h, l;
        split_bf16(v, h, l);
        outh[(size_t)(bx + j) * rows + xo] = h;
        outl[(size_t)(bx + j) * rows + xo] = l;
    }
}

// ---------------- mma.sync bf16 3-term GEMM, CTA 128x64, 3 CTAs/SM ----------
#define GK 1024
#define BKC 32
#define ARR_A 8192                 // 128 rows x 64B
#define ARR_B 4096                 // 64 rows x 64B
#define STG3 (2 * ARR_A + 2 * ARR_B)   // 24576
#define NSTG 3
#define GSMEM (NSTG * STG3)        // 73728

__device__ __forceinline__ void gemm_load_stage(
    uint32_t sdst, const __nv_bfloat16* Ahb, const __nv_bfloat16* Alb,
    const __nv_bfloat16* Bhb, const __nv_bfloat16* Blb, int k0, int tid)
{
    #pragma unroll
    for (int it = 0; it < 6; it++) {
        int i = tid + it * 256;            // 0..1535
        const __nv_bfloat16* src;
        uint32_t dst;
        if (i < 1024) {                    // A arrays (512 chunks each)
            int j = i & 511;
            int r = j >> 2, c = j & 3;
            int cs = c ^ ((r >> 1) & 3);
            src = (i < 512 ? Ahb : Alb) + (size_t)r * GK + k0 + c * 8;
            dst = sdst + (i < 512 ? 0u : (uint32_t)ARR_A) + (uint32_t)(r * 64 + cs * 16);
        } else {                           // B arrays (256 chunks each)
            int j = i & 255;
            int r = j >> 2, c = j & 3;
            int cs = c ^ ((r >> 1) & 3);
            src = (i < 1280 ? Bhb : Blb) + (size_t)r * GK + k0 + c * 8;
            dst = sdst + 2 * ARR_A + (i < 1280 ? 0u : (uint32_t)ARR_B) + (uint32_t)(r * 64 + cs * 16);
        }
        cp_async16(dst, src);
    }
    cp_commit();
}

// mainloop: 8 warps (4m x 2n), warp tile 32x32, acc[2][4][4]
// B fragments loaded pairwise with ldmatrix.x4 (rows n, n+8 in one instr).
#define GEMM_MAIN(acc, Ah, Al, Bh, Bl)                                          \
    extern __shared__ char dsm[];                                               \
    const uint32_t sb = smem_u32(dsm);                                          \
    const int tid = threadIdx.x;                                                \
    const int wid = tid >> 5;                                                   \
    const int lane = tid & 31;                                                  \
    const int wm = wid >> 1;                                                    \
    const int wn = wid & 1;                                                     \
    const int m0 = blockIdx.y * 128;                                            \
    const int n0 = blockIdx.x * 64;                                             \
    const __nv_bfloat16* Ahb = Ah + (size_t)m0 * GK;                            \
    const __nv_bfloat16* Alb = Al + (size_t)m0 * GK;                            \
    const __nv_bfloat16* Bhb = Bh + (size_t)n0 * GK;                            \
    const __nv_bfloat16* Blb = Bl + (size_t)n0 * GK;                            \
    float acc[2][4][4];                                                         \
    _Pragma("unroll")                                                           \
    for (int i = 0; i < 2; i++)                                                 \
        _Pragma("unroll")                                                       \
        for (int j = 0; j < 4; j++)                                             \
            _Pragma("unroll")                                                   \
            for (int r = 0; r < 4; r++) acc[i][j][r] = 0.f;                     \
    const int arow = wm * 32 + (lane & 15);                                     \
    const int achk = lane >> 4;                                                 \
    const uint32_t s_a = (uint32_t)((arow >> 1) & 3);                           \
    const int brow2 = wn * 32 + (lane & 7) + ((lane >> 4) << 3);                \
    const int bchk = (lane >> 3) & 1;                                           \
    gemm_load_stage(sb,        Ahb, Alb, Bhb, Blb, 0,   tid);                   \
    gemm_load_stage(sb + STG3, Ahb, Alb, Bhb, Blb, BKC, tid);                   \
    const int NCH = GK / BKC;                                                   \
    for (int ch = 0; ch < NCH; ch++) {                                          \
        if (ch + 1 < NCH) { asm volatile("cp.async.wait_group 1;"); }           \
        else              { asm volatile("cp.async.wait_group 0;"); }           \
        __syncthreads();                                                        \
        if (ch + 2 < NCH)                                                       \
            gemm_load_stage(sb + ((ch + 2) % NSTG) * STG3, Ahb, Alb, Bhb, Blb,  \
                            (ch + 2) * BKC, tid);                               \
        const uint32_t st = sb + (ch % NSTG) * STG3;                            \
        _Pragma("unroll")                                                       \
        for (int ks = 0; ks < 2; ks++) {                                        \
            const uint32_t kc = (uint32_t)(ks * 2);                             \
            uint32_t af[2][4], bf[4][2], bt[4][2];                              \
            _Pragma("unroll")                                                   \
            for (int mt = 0; mt < 2; mt++) {                                    \
                uint32_t ad = st + (uint32_t)((arow + mt * 16) * 64) + (((kc + achk) ^ s_a) << 4); \
                ldm_x4(af[mt][0], af[mt][1], af[mt][2], af[mt][3], ad);         \
            }                                                                   \
            _Pragma("unroll")                                                   \
            for (int np = 0; np < 2; np++) {                                    \
                int rr = brow2 + np * 16;                                       \
                uint32_t bd = st + 2 * ARR_A + (uint32_t)(rr * 64) + (((kc + bchk) ^ ((rr >> 1) & 3)) << 4); \
                ldm_x4(bf[np * 2][0], bf[np * 2][1], bf[np * 2 + 1][0], bf[np * 2 + 1][1], bd); \
            }                                                                   \
            _Pragma("unroll")                                                   \
            for (int mt = 0; mt < 2; mt++)                                      \
                _Pragma("unroll")                                               \
                for (int nt = 0; nt < 4; nt++) mma16816(acc[mt][nt], af[mt], bf[nt]); \
            _Pragma("unroll")                                                   \
            for (int np = 0; np < 2; np++) {                                    \
                int rr = brow2 + np * 16;                                       \
                uint32_t bd = st + 2 * ARR_A + ARR_B + (uint32_t)(rr * 64) + (((kc + bchk) ^ ((rr >> 1) & 3)) << 4); \
                ldm_x4(bt[np * 2][0], bt[np * 2][1], bt[np * 2 + 1][0], bt[np * 2 + 1][1], bd); \
            }                                                                   \
            _Pragma("unroll")                                                   \
            for (int mt = 0; mt < 2; mt++)                                      \
                _Pragma("unroll")                                               \
                for (int nt = 0; nt < 4; nt++) mma16816(acc[mt][nt], af[mt], bt[nt]); \
            _Pragma("unroll")                                                   \
            for (int mt = 0; mt < 2; mt++) {                                    \
                uint32_t ad = st + ARR_A + (uint32_t)((arow + mt * 16) * 64) + (((kc + achk) ^ s_a) << 4); \
                ldm_x4(af[mt][0], af[mt][1], af[mt][2], af[mt][3], ad);         \
            }                                                                   \
            _Pragma("unroll")                                                   \
            for (int mt = 0; mt < 2; mt++)                                      \
                _Pragma("unroll")                                               \
                for (int nt = 0; nt < 4; nt++) mma16816(acc[mt][nt], af[mt], bf[nt]); \
        }                                                                       \
        __syncthreads();                                                        \
    }

// GEMM2: fp32 C output
__global__ __launch_bounds__(256, 3) void gemm_bf16x3(
    const __nv_bfloat16* __restrict__ Ah, const __nv_bfloat16* __restrict__ Al,
    const __nv_bfloat16* __restrict__ Bh, const __nv_bfloat16* __restrict__ Bl,
    float* __restrict__ C, int N)
{
    GEMM_MAIN(acc, Ah, Al, Bh, Bl)
    const int mrow = m0 + wm * 32 + (lane >> 2);
    const int ncol = n0 + wn * 32 + (lane & 3) * 2;
    #pragma unroll
    for (int mt = 0; mt < 2; mt++)
        #pragma unroll
        for (int nt = 0; nt < 4; nt++) {
            float* c0 = C + (size_t)(mrow + mt * 16) * N + ncol + nt * 8;
            *(float2*)c0 = make_float2(acc[mt][nt][0], acc[mt][nt][1]);
            float* c1 = c0 + (size_t)8 * N;
            *(float2*)c1 = make_float2(acc[mt][nt][2], acc[mt][nt][3]);
        }
}

// GEMM1: N=3072 fixed; epilogue splits into q(scaled)/k/v bf16 hi/lo
__global__ __launch_bounds__(256, 3) void gemm_qkv(
    const __nv_bfloat16* __restrict__ Ah, const __nv_bfloat16* __restrict__ Al,
    const __nv_bfloat16* __restrict__ Bh, const __nv_bfloat16* __restrict__ Bl,
    __nv_bfloat16* __restrict__ qh, __nv_bfloat16* __restrict__ ql,
    __nv_bfloat16* __restrict__ kh, __nv_bfloat16* __restrict__ kl,
    __nv_bfloat16* __restrict__ vh, __nv_bfloat16* __restrict__ vl)
{
    GEMM_MAIN(acc, Ah, Al, Bh, Bl)
    const int region = n0 >> 10;
    __nv_bfloat16 *oh, *ol;
    float sc;
    if (region == 0)      { oh = qh; ol = ql; sc = 0.125f; }
    else if (region == 1) { oh = kh; ol = kl; sc = 1.f; }
    else                  { oh = vh; ol = vl; sc = 1.f; }
    const int mrow = m0 + wm * 32 + (lane >> 2);
    const int colr = (n0 & 1023) + wn * 32 + (lane & 3) * 2;
    #pragma unroll
    for (int mt = 0; mt < 2; mt++)
        #pragma unroll
        for (int nt = 0; nt < 4; nt++) {
            size_t o0 = (size_t)(mrow + mt * 16) * CC + colr + nt * 8;
            uint32_t wh, wl;
            split_pair(acc[mt][nt][0] * sc, acc[mt][nt][1] * sc, wh, wl);
            *(uint32_t*)(oh + o0) = wh;
            *(uint32_t*)(ol + o0) = wl;
            size_t o1 = o0 + (size_t)8 * CC;
            split_pair(acc[mt][nt][2] * sc, acc[mt][nt][3] * sc, wh, wl);
            *(uint32_t*)(oh + o1) = wh;
            *(uint32_t*)(ol + o1) = wl;
        }
}

// ---------------- fp32 selection-score path ---------------------------------
__global__ __launch_bounds__(256) void qlast_kernel(
    const float* __restrict__ x, const float* __restrict__ Wa,
    float* __restrict__ qlast)
{
    const int b = blockIdx.x >> 4, h = blockIdx.x & 15;
    const int tid = threadIdx.x;
    __shared__ float xs[CC];
    __shared__ float red[4][64];
    for (int c = tid; c < CC; c += 256)
        xs[c] = x[((size_t)b * TT + (TT - 1)) * CC + c];
    __syncthreads();
    const int col = h * HD + (tid & 63);
    const int q = tid >> 6;
    float s = 0.f;
    #pragma unroll 4
    for (int c = q * 256; c < q * 256 + 256; c++)
        s += xs[c] * Wa[(size_t)c * (3 * CC) + col];
    red[q][tid & 63] = s;
    __syncthreads();
    if (tid < 64)
        qlast[(b * NH + h) * HD + tid] = red[0][tid] + red[1][tid] + red[2][tid] + red[3][tid];
}

__global__ __launch_bounds__(256) void uproj_kernel(
    const float* __restrict__ Wa, const float* __restrict__ qlast,
    float* __restrict__ u)
{
    const int b = blockIdx.x;
    const int c = blockIdx.y * 16 + (threadIdx.x >> 4);
    const int h = threadIdx.x & 15;
    __shared__ float qs[CC];
    for (int i = threadIdx.x; i < CC; i += 256) qs[i] = qlast[b * CC + i];
    __syncthreads();
    const float* wrow = Wa + (size_t)c * (3 * CC) + CC + h * HD;
    const float* qh = qs + h * HD;
    float s = 0.f;
    #pragma unroll
    for (int d = 0; d < HD; d++) s += wrow[d] * qh[d];
    u[((size_t)b * CC + c) * NH + h] = s;
}

#define SC_TR 32
#define SC_PAD 129

__global__ __launch_bounds__(128) void scores_kernel(
    const float* __restrict__ x, const float* __restrict__ u,
    float* __restrict__ last)
{
    const int b = blockIdx.x;
    const int t0 = blockIdx.y * SC_TR;
    const int tid = threadIdx.x;
    const int tloc = tid & 31;
    const int hg = tid >> 5;

    __shared__ float xs[SC_TR][SC_PAD];
    __shared__ float us[128][NH];

    float4 acc = make_float4(0.f, 0.f, 0.f, 0.f);

    for (int c0 = 0; c0 < CC; c0 += 128) {
        __syncthreads();
        #pragma unroll
        for (int it = 0; it < 8; it++) {
            int flat = it * 128 + tid;
            int r = flat >> 5;
            int c4 = flat & 31;
            float4 v = *(const float4*)(x + ((size_t)(b * TT + t0 + r)) * CC + c0 + c4 * 4);
            xs[r][c4 * 4 + 0] = v.x; xs[r][c4 * 4 + 1] = v.y;
            xs[r][c4 * 4 + 2] = v.z; xs[r][c4 * 4 + 3] = v.w;
        }
        #pragma unroll
        for (int it = 0; it < 4; it++) {
            int flat = it * 128 + tid;
            int ci = flat >> 2;
            int h4 = flat & 3;
            float4 v = *(const float4*)(u + ((size_t)(b * CC + c0 + ci)) * NH + h4 * 4);
            *(float4*)&us[ci][h4 * 4] = v;
        }
        __syncthreads();

        #pragma unroll 4
        for (int ci = 0; ci < 128; ci++) {
            float xv = xs[tloc][ci];
            float4 uu = *(const float4*)&us[ci][hg * 4];
            acc.x += xv * uu.x; acc.y += xv * uu.y;
            acc.z += xv * uu.z; acc.w += xv * uu.w;
        }
    }

    const int t = t0 + tloc;
    last[(b * NH + hg * 4 + 0) * TT + t] = acc.x * 0.125f;
    last[(b * NH + hg * 4 + 1) * TT + t] = acc.y * 0.125f;
    last[(b * NH + hg * 4 + 2) * TT + t] = acc.z * 0.125f;
    last[(b * NH + hg * 4 + 3) * TT + t] = acc.w * 0.125f;
}

// ---------------- top-k set selection via bitonic sort ---------------------
__global__ __launch_bounds__(512) void topk_kernel(const float* __restrict__ last,
                                                   int* __restrict__ idxout)
{
    __shared__ unsigned long long s[TT];
    const int bh = blockIdx.x;
    const int tid = threadIdx.x;

    for (int t = tid; t < TT; t += 512) {
        unsigned u;
        if (t >= NONREC) {
            u = 0xFFFFFFFFu;
        } else {
            u = __float_as_uint(last[bh * TT + t]);
            u = (u & 0x80000000u) ? ~u : (u | 0x80000000u);
        }
        s[t] = ((unsigned long long)u << 32) | (unsigned)t;
    }
    __syncthreads();

    for (int k = 2; k <= TT; k <<= 1) {
        for (int j = k >> 1; j > 0; j >>= 1) {
            for (int i = tid; i < TT; i += 512) {
                int ix = i ^ j;
                if (ix > i) {
                    bool desc = ((i & k) == 0);
                    unsigned long long a = s[i], b = s[ix];
                    bool sw = desc ? (a < b) : (a > b);
                    if (sw) { s[i] = b; s[ix] = a; }
                }
            }
            __syncthreads();
        }
    }
    for (int i = tid; i < KKEEP; i += 512)
        idxout[bh * KKEEP + i] = (int)(s[i] & 0xFFFFFFFFu);
}

// ---------------- mma-based pruned attention --------------------------------
#define ASMEM (32768 + 2 * 32768)        // 98304

__device__ __forceinline__ void attn_kv_prefetch(
    char* smp, uint32_t sb, uint32_t stgoff,
    const __nv_bfloat16* kh, const __nv_bfloat16* kl,
    const __nv_bfloat16* vh, const __nv_bfloat16* vl,
    const int* idxp, int b, int hoff, int c0, int cn, int tid)
{
    for (int i = tid; i < 64 * 8; i += 128) {
        int r = i >> 3, c = i & 7;
        uint32_t off = (uint32_t)(r * 128 + (((c ^ (r & 7))) << 4));
        if (r < cn) {
            int kt = idxp[c0 + r];
            size_t g = ((size_t)(b * TT + kt)) * CC + hoff + c * 8;
            cp_async16(sb + stgoff + off,         kh + g);
            cp_async16(sb + stgoff + 8192 + off,  kl + g);
            cp_async16(sb + stgoff + 16384 + off, vh + g);
            cp_async16(sb + stgoff + 24576 + off, vl + g);
        } else {
            uint4 z = make_uint4(0, 0, 0, 0);
            *(uint4*)(smp + stgoff + off) = z;
            *(uint4*)(smp + stgoff + 8192 + off) = z;
            *(uint4*)(smp + stgoff + 16384 + off) = z;
            *(uint4*)(smp + stgoff + 24576 + off) = z;
        }
    }
    cp_commit();
}

__global__ __launch_bounds__(128) void attn_kernel(
    const __nv_bfloat16* __restrict__ qh, const __nv_bfloat16* __restrict__ ql,
    const __nv_bfloat16* __restrict__ kh, const __nv_bfloat16* __restrict__ kl,
    const __nv_bfloat16* __restrict__ vh, const __nv_bfloat16* __restrict__ vl,
    const int* __restrict__ idx,
    __nv_bfloat16* __restrict__ yh, __nv_bfloat16* __restrict__ yl)
{
    extern __shared__ char asmem[];
    const uint32_t sb = smem_u32(asmem);
    const int tid = threadIdx.x;
    const int wq = tid >> 5;
    const int lane = tid & 31;
    const int bh = blockIdx.x;
    const int b = bh >> 4, h = bh & 15;
    const int qt0 = blockIdx.y * 128;
    const int hoff = h * HD;
    const int* idxp = idx + bh * KKEEP;

    for (int i = tid; i < 128 * 8; i += 128) {
        int r = i >> 3, c = i & 7;
        size_t g = ((size_t)(b * TT + qt0 + r)) * CC + hoff + c * 8;
        uint32_t off = (uint32_t)(r * 128 + (((c ^ (r & 7))) << 4));
        cp_async16(sb + off, qh + g);
        cp_async16(sb + 16384 + off, ql + g);
    }
    cp_commit();

    const int nch = (KKEEP + 63) / 64;   // 7
    attn_kv_prefetch(asmem, sb, 32768, kh, kl, vh, vl, idxp, b, hoff, 0, 64, tid);

    float o[2][8][4];
    #pragma unroll
    for (int mt = 0; mt < 2; mt++)
        #pragma unroll
        for (int dt = 0; dt < 8; dt++)
            #pragma unroll
            for (int r = 0; r < 4; r++) o[mt][dt][r] = 0.f;
    float la[4] = {0.f, 0.f, 0.f, 0.f};

    for (int ch = 0; ch < nch; ch++) {
        if (ch + 1 < nch) {
            int c1 = (ch + 1) * 64;
            attn_kv_prefetch(asmem, sb, 32768 + ((ch + 1) & 1) * 32768,
                             kh, kl, vh, vl, idxp, b, hoff, c1,
                             min(64, KKEEP - c1), tid);
            asm volatile("cp.async.wait_group 1;");
        } else {
            asm volatile("cp.async.wait_group 0;");
        }
        __syncthreads();

        const uint32_t stg = sb + 32768 + (uint32_t)((ch & 1) * 32768);

        #pragma unroll
        for (int mt = 0; mt < 2; mt++) {
            uint32_t ah[4][4], al[4][4];
            {
                int row = wq * 32 + mt * 16 + (lane & 15);
                #pragma unroll
                for (int kd = 0; kd < 4; kd++) {
                    int chv = kd * 2 + (lane >> 4);
                    uint32_t ad = (uint32_t)(row * 128 + (((chv ^ (row & 7))) << 4));
                    ldm_x4(ah[kd][0], ah[kd][1], ah[kd][2], ah[kd][3], sb + ad);
                    ldm_x4(al[kd][0], al[kd][1], al[kd][2], al[kd][3], sb + 16384 + ad);
                }
            }
            #pragma unroll
            for (int ntp = 0; ntp < 4; ntp++) {
                float s0[4] = {0.f, 0.f, 0.f, 0.f};
                float s1[4] = {0.f, 0.f, 0.f, 0.f};
                {
                    // paired K fragments: one x4 covers rows (n, n+8)
                    int rr = ntp * 16 + (lane & 7) + ((lane >> 4) << 3);
                    #pragma unroll
                    for (int kd = 0; kd < 4; kd++) {
                        int chv = kd * 2 + ((lane >> 3) & 1);
                        uint32_t ad = (uint32_t)(rr * 128 + (((chv ^ (rr & 7))) << 4));
                        uint32_t bh4[4], bl4[4];
                        ldm_x4(bh4[0], bh4[1], bh4[2], bh4[3], stg + ad);
                        ldm_x4(bl4[0], bl4[1], bl4[2], bl4[3], stg + 8192 + ad);
                        mma16816(s0, ah[kd], &bh4[0]);
                        mma16816(s0, ah[kd], &bl4[0]);
                        mma16816(s0, al[kd], &bh4[0]);
                        mma16816(s1, ah[kd], &bh4[2]);
                        mma16816(s1, ah[kd], &bl4[2]);
                        mma16816(s1, al[kd], &bh4[2]);
                    }
                }
                const int kb = ch * 64 + ntp * 16 + 2 * (lane & 3);
                float p0 = (kb     < KKEEP) ? __expf(s0[0]) : 0.f;
                float p1 = (kb + 1 < KKEEP) ? __expf(s0[1]) : 0.f;
                float p2 = (kb     < KKEEP) ? __expf(s0[2]) : 0.f;
                float p3 = (kb + 1 < KKEEP) ? __expf(s0[3]) : 0.f;
                float p4 = (kb + 8 < KKEEP) ? __expf(s1[0]) : 0.f;
                float p5 = (kb + 9 < KKEEP) ? __expf(s1[1]) : 0.f;
                float p6 = (kb + 8 < KKEEP) ? __expf(s1[2]) : 0.f;
                float p7 = (kb + 9 < KKEEP) ? __expf(s1[3]) : 0.f;
                la[mt * 2 + 0] += (p0 + p1) + (p4 + p5);
                la[mt * 2 + 1] += (p2 + p3) + (p6 + p7);
                uint32_t phi[4], plo[4];
                {
                    float vs[8] = {p0, p1, p2, p3, p4, p5, p6, p7};
                    #pragma unroll
                    for (int j = 0; j < 4; j++) {
                        __nv_bfloat16 ha = __float2bfloat16(vs[2 * j]);
                        __nv_bfloat16 hb = __float2bfloat16(vs[2 * j + 1]);
                        __nv_bfloat162 th(ha, hb);
                        phi[j] = *(uint32_t*)&th;
                        __nv_bfloat162 tl(__float2bfloat16(vs[2 * j] - __bfloat162float(ha)),
                                          __float2bfloat16(vs[2 * j + 1] - __bfloat162float(hb)));
                        plo[j] = *(uint32_t*)&tl;
                    }
                }
                #pragma unroll
                for (int dp = 0; dp < 4; dp++) {
                    int g = lane >> 3;
                    int krow = ntp * 16 + ((g & 1) << 3) + (lane & 7);
                    int chv = dp * 2 + (g >> 1);
                    uint32_t av = (uint32_t)(krow * 128 + (((chv ^ (krow & 7))) << 4));
                    uint32_t vbh[4], vbl[4];
                    ldm_x4t(vbh, stg + 16384 + av);
                    ldm_x4t(vbl, stg + 24576 + av);
                    mma16816(o[mt][dp * 2],     phi, &vbh[0]);
                    mma16816(o[mt][dp * 2],     plo, &vbh[0]);
                    mma16816(o[mt][dp * 2],     phi, &vbl[0]);
                    mma16816(o[mt][dp * 2 + 1], phi, &vbh[2]);
                    mma16816(o[mt][dp * 2 + 1], plo, &vbh[2]);
                    mma16816(o[mt][dp * 2 + 1], phi, &vbl[2]);
                }
            }
        }
        __syncthreads();
    }

    #pragma unroll
    for (int j = 0; j < 4; j++) {
        la[j] += __shfl_xor_sync(0xFFFFFFFFu, la[j], 1);
        la[j] += __shfl_xor_sync(0xFFFFFFFFu, la[j], 2);
        la[j] = 1.f / la[j];
    }

    #pragma unroll
    for (int mt = 0; mt < 2; mt++) {
        const int row0 = qt0 + wq * 32 + mt * 16 + (lane >> 2);
        #pragma unroll
        for (int dt = 0; dt < 8; dt++) {
            const int col = dt * 8 + 2 * (lane & 3);
            size_t a0 = ((size_t)(b * TT + row0)) * CC + hoff + col;
            uint32_t wh, wl;
            split_pair(o[mt][dt][0] * la[mt * 2], o[mt][dt][1] * la[mt * 2], wh, wl);
            *(uint32_t*)(yh + a0) = wh;
            *(uint32_t*)(yl + a0) = wl;
            size_t a1 = a0 + (size_t)8 * CC;
            split_pair(o[mt][dt][2] * la[mt * 2 + 1], o[mt][dt][3] * la[mt * 2 + 1], wh, wl);
            *(uint32_t*)(yh + a1) = wh;
            *(uint32_t*)(yl + a1) = wl;
        }
    }
}

// ---------------- launch ----------------------------------------------------
extern "C" void kernel_launch(void* const* d_in, const int* in_sizes, int n_in,
                              void* d_out, int out_size)
{
    const float* x  = (const float*)d_in[0];   // [4,1024,1024]
    const float* Wa = (const float*)d_in[1];   // [1024,3072]
    const float* Wp = (const float*)d_in[2];   // [1024,1024]
    float* out = (float*)d_out;                // [4,1024,1024]

    void* p;
    cudaGetSymbolAddress(&p, g_last);  float* last  = (float*)p;
    cudaGetSymbolAddress(&p, g_idx);   int*   idx   = (int*)p;
    cudaGetSymbolAddress(&p, g_qlast); float* qlast = (float*)p;
    cudaGetSymbolAddress(&p, g_u);     float* u     = (float*)p;
    cudaGetSymbolAddress(&p, g_xh);   __nv_bfloat16* xh  = (__nv_bfloat16*)p;
    cudaGetSymbolAddress(&p, g_xl);   __nv_bfloat16* xl  = (__nv_bfloat16*)p;
    cudaGetSymbolAddress(&p, g_wah);  __nv_bfloat16* wah = (__nv_bfloat16*)p;
    cudaGetSymbolAddress(&p, g_wal);  __nv_bfloat16* wal = (__nv_bfloat16*)p;
    cudaGetSymbolAddress(&p, g_wph);  __nv_bfloat16* wph = (__nv_bfloat16*)p;
    cudaGetSymbolAddress(&p, g_wpl);  __nv_bfloat16* wpl = (__nv_bfloat16*)p;
    cudaGetSymbolAddress(&p, g_yh);   __nv_bfloat16* yh  = (__nv_bfloat16*)p;
    cudaGetSymbolAddress(&p, g_yl);   __nv_bfloat16* yl  = (__nv_bfloat16*)p;
    cudaGetSymbolAddress(&p, g_qh);   __nv_bfloat16* qhp = (__nv_bfloat16*)p;
    cudaGetSymbolAddress(&p, g_ql);   __nv_bfloat16* qlp = (__nv_bfloat16*)p;
    cudaGetSymbolAddress(&p, g_kh);   __nv_bfloat16* khp = (__nv_bfloat16*)p;
    cudaGetSymbolAddress(&p, g_kl);   __nv_bfloat16* klp = (__nv_bfloat16*)p;
    cudaGetSymbolAddress(&p, g_vh);   __nv_bfloat16* vhp = (__nv_bfloat16*)p;
    cudaGetSymbolAddress(&p, g_vl);   __nv_bfloat16* vlp = (__nv_bfloat16*)p;

    cudaFuncSetAttribute(gemm_bf16x3, cudaFuncAttributeMaxDynamicSharedMemorySize, GSMEM);
    cudaFuncSetAttribute(gemm_qkv, cudaFuncAttributeMaxDynamicSharedMemorySize, GSMEM);
    cudaFuncSetAttribute(attn_kernel, cudaFuncAttributeMaxDynamicSharedMemorySize, ASMEM);

    // slot 1-3
    qlast_kernel<<<BB * NH, 256>>>(x, Wa, qlast);
    uproj_kernel<<<dim3(BB, CC / 16), 256>>>(Wa, qlast, u);
    prep_kernel<<<PREP_TOTAL, 256>>>(x, Wa, Wp, xh, xl, wah, wal, wph, wpl);

    // slot 4 (profiled): qkv GEMM, paired-B ldmatrix.x4
    gemm_qkv<<<dim3(3 * CC / 64, BB * TT / 128), 256, GSMEM>>>(
        xh, xl, wah, wal, qhp, qlp, khp, klp, vhp, vlp);

    // slot 5-6: selection scores + topk
    scores_kernel<<<dim3(BB, TT / SC_TR), 128>>>(x, u, last);
    topk_kernel<<<BB * NH, 512>>>(last, idx);

    // slot 7: mma attention -> yh/yl
    attn_kernel<<<dim3(BB * NH, TT / 128), 128, ASMEM>>>(
        qhp, qlp, khp, klp, vhp, vlp, idx, yh, yl);

    // slot 8: out = y @ W_proj
    gemm_bf16x3<<<dim3(CC / 64, BB * TT / 128), 256, GSMEM>>>(yh, yl, wph, wpl, out, CC);
}

// round 17
// speedup vs baseline: 2.6700x; 1.0617x over previous
#include <cuda_runtime.h>
#include <cuda_bf16.h>
#include <math.h>
#include <stdint.h>

// Problem constants
#define BB 4
#define TT 1024
#define CC 1024
#define NH 16
#define HD 64
#define KKEEP 391
#define REC 64
#define NONREC (TT - REC)       // 960

// ---------------- scratch (device globals; no allocation allowed) ----------
__device__ float g_last[BB * NH * TT];
__device__ int   g_idx[BB * NH * KKEEP];
__device__ float g_qlast[BB * CC];
__device__ float g_u[BB * CC * NH];
__device__ __nv_bfloat16 g_xh[BB * TT * CC];
__device__ __nv_bfloat16 g_xl[BB * TT * CC];
__device__ __nv_bfloat16 g_wah[3 * CC * CC];         // W_attn^T hi/lo [3072][1024]
__device__ __nv_bfloat16 g_wal[3 * CC * CC];
__device__ __nv_bfloat16 g_wph[CC * CC];             // W_proj^T hi/lo
__device__ __nv_bfloat16 g_wpl[CC * CC];
__device__ __nv_bfloat16 g_yh[BB * TT * CC];
__device__ __nv_bfloat16 g_yl[BB * TT * CC];
__device__ __nv_bfloat16 g_qh[BB * TT * CC];         // Q * 0.125, hi/lo
__device__ __nv_bfloat16 g_ql[BB * TT * CC];
__device__ __nv_bfloat16 g_kh[BB * TT * CC];
__device__ __nv_bfloat16 g_kl[BB * TT * CC];
__device__ __nv_bfloat16 g_vh[BB * TT * CC];
__device__ __nv_bfloat16 g_vl[BB * TT * CC];

// ---------------- helpers ---------------------------------------------------
__device__ __forceinline__ uint32_t smem_u32(const void* p) {
    uint32_t a;
    asm("{ .reg .u64 t; cvta.to.shared.u64 t, %1; cvt.u32.u64 %0, t; }" : "=r"(a) : "l"(p));
    return a;
}
__device__ __forceinline__ void cp_async16(uint32_t dst, const void* src) {
    asm volatile("cp.async.cg.shared.global [%0], [%1], 16;" :: "r"(dst), "l"(src));
}
__device__ __forceinline__ void cp_commit() {
    asm volatile("cp.async.commit_group;");
}
__device__ __forceinline__ void ldm_x4(uint32_t& r0, uint32_t& r1, uint32_t& r2, uint32_t& r3, uint32_t addr) {
    asm volatile("ldmatrix.sync.aligned.m8n8.x4.shared.b16 {%0,%1,%2,%3}, [%4];"
                 : "=r"(r0), "=r"(r1), "=r"(r2), "=r"(r3) : "r"(addr));
}
__device__ __forceinline__ void ldm_x4t(uint32_t* r, uint32_t addr) {
    asm volatile("ldmatrix.sync.aligned.m8n8.x4.trans.shared.b16 {%0,%1,%2,%3}, [%4];"
                 : "=r"(r[0]), "=r"(r[1]), "=r"(r[2]), "=r"(r[3]) : "r"(addr));
}
__device__ __forceinline__ void mma16816(float* d, const uint32_t* a, const uint32_t* b) {
    asm volatile(
        "mma.sync.aligned.m16n8k16.row.col.f32.bf16.bf16.f32 "
        "{%0,%1,%2,%3},{%4,%5,%6,%7},{%8,%9},{%0,%1,%2,%3};"
        : "+f"(d[0]), "+f"(d[1]), "+f"(d[2]), "+f"(d[3])
        : "r"(a[0]), "r"(a[1]), "r"(a[2]), "r"(a[3]), "r"(b[0]), "r"(b[1]));
}
__device__ __forceinline__ void split_bf16(float a, __nv_bfloat16& h, __nv_bfloat16& l) {
    h = __float2bfloat16(a);
    l = __float2bfloat16(a - __bfloat162float(h));
}
__device__ __forceinline__ void split_pair(float v0, float v1, uint32_t& wh, uint32_t& wl) {
    __nv_bfloat16 h0, l0, h1, l1;
    split_bf16(v0, h0, l0); split_bf16(v1, h1, l1);
    __nv_bfloat162 th(h0, h1), tl(l0, l1);
    wh = *(uint32_t*)&th; wl = *(uint32_t*)&tl;
}

// ---------------- merged prep: split x + transpose-split both weights -------
#define PREP_SPLIT 4096
#define PREP_WA (PREP_SPLIT + 3072)
#define PREP_TOTAL (PREP_WA + 1024)

__global__ __launch_bounds__(256) void prep_kernel(
    const float* __restrict__ x, const float* __restrict__ Wa, const float* __restrict__ Wp,
    __nv_bfloat16* __restrict__ xh, __nv_bfloat16* __restrict__ xl,
    __nv_bfloat16* __restrict__ wah, __nv_bfloat16* __restrict__ wal,
    __nv_bfloat16* __restrict__ wph, __nv_bfloat16* __restrict__ wpl)
{
    const int bid = blockIdx.x;
    if (bid < PREP_SPLIT) {
        int i = bid * 256 + threadIdx.x;
        float4 v = ((const float4*)x)[i];
        uint32_t h01, l01, h23, l23;
        split_pair(v.x, v.y, h01, l01);
        split_pair(v.z, v.w, h23, l23);
        ((uint32_t*)xh)[i * 2 + 0] = h01;
        ((uint32_t*)xh)[i * 2 + 1] = h23;
        ((uint32_t*)xl)[i * 2 + 0] = l01;
        ((uint32_t*)xl)[i * 2 + 1] = l23;
        return;
    }
    const float* in;
    __nv_bfloat16 *outh, *outl;
    int rows, cols, bx, by;
    if (bid < PREP_WA) {
        int id = bid - PREP_SPLIT;
        in = Wa; outh = wah; outl = wal; rows = CC; cols = 3 * CC;
        bx = (id % 96) * 32; by = (id / 96) * 32;
    } else {
        int id = bid - PREP_WA;
        in = Wp; outh = wph; outl = wpl; rows = CC; cols = CC;
        bx = (id % 32) * 32; by = (id / 32) * 32;
    }
    __shared__ float t[32][33];
    const int tx = threadIdx.x & 31, ty = threadIdx.x >> 5;
    int xcol = bx + tx;
    #pragma unroll
    for (int j = ty; j < 32; j += 8)
        t[j][tx] = in[(size_t)(by + j) * cols + xcol];
    __syncthreads();
    int xo = by + tx;
    #pragma unroll
    for (int j = ty; j < 32; j += 8) {
        float v = t[tx][j];
        __nv_bfloat16 h, l;
        split_bf16(v, h, l);
        outh[(size_t)(bx + j) * rows + xo] = h;
        outl[(size_t)(bx + j) * rows + xo] = l;
    }
}

// ---------------- mma.sync bf16 3-term GEMM, CTA 128x64, 3 CTAs/SM ----------
#define GK 1024
#define BKC 32
#define ARR_A 8192                 // 128 rows x 64B
#define ARR_B 4096                 // 64 rows x 64B
#define STG3 (2 * ARR_A + 2 * ARR_B)   // 24576
#define NSTG 3
#define GSMEM (NSTG * STG3)        // 73728

__device__ __forceinline__ void gemm_load_stage(
    uint32_t sdst, const __nv_bfloat16* Ahb, const __nv_bfloat16* Alb,
    const __nv_bfloat16* Bhb, const __nv_bfloat16* Blb, int k0, int tid)
{
    #pragma unroll
    for (int it = 0; it < 6; it++) {
        int i = tid + it * 256;            // 0..1535
        const __nv_bfloat16* src;
        uint32_t dst;
        if (i < 1024) {                    // A arrays (512 chunks each)
            int j = i & 511;
            int r = j >> 2, c = j & 3;
            int cs = c ^ ((r >> 1) & 3);
            src = (i < 512 ? Ahb : Alb) + (size_t)r * GK + k0 + c * 8;
            dst = sdst + (i < 512 ? 0u : (uint32_t)ARR_A) + (uint32_t)(r * 64 + cs * 16);
        } else {                           // B arrays (256 chunks each)
            int j = i & 255;
            int r = j >> 2, c = j & 3;
            int cs = c ^ ((r >> 1) & 3);
            src = (i < 1280 ? Bhb : Blb) + (size_t)r * GK + k0 + c * 8;
            dst = sdst + 2 * ARR_A + (i < 1280 ? 0u : (uint32_t)ARR_B) + (uint32_t)(r * 64 + cs * 16);
        }
        cp_async16(dst, src);
    }
    cp_commit();
}

// mainloop: 8 warps (4m x 2n), warp tile 32x32, acc[2][4][4]
// B fragments loaded pairwise with ldmatrix.x4 (rows n, n+8 in one instr).
#define GEMM_MAIN(acc, Ah, Al, Bh, Bl)                                          \
    extern __shared__ char dsm[];                                               \
    const uint32_t sb = smem_u32(dsm);                                          \
    const int tid = threadIdx.x;                                                \
    const int wid = tid >> 5;                                                   \
    const int lane = tid & 31;                                                  \
    const int wm = wid >> 1;                                                    \
    const int wn = wid & 1;                                                     \
    const int m0 = blockIdx.y * 128;                                            \
    const int n0 = blockIdx.x * 64;                                             \
    const __nv_bfloat16* Ahb = Ah + (size_t)m0 * GK;                            \
    const __nv_bfloat16* Alb = Al + (size_t)m0 * GK;                            \
    const __nv_bfloat16* Bhb = Bh + (size_t)n0 * GK;                            \
    const __nv_bfloat16* Blb = Bl + (size_t)n0 * GK;                            \
    float acc[2][4][4];                                                         \
    _Pragma("unroll")                                                           \
    for (int i = 0; i < 2; i++)                                                 \
        _Pragma("unroll")                                                       \
        for (int j = 0; j < 4; j++)                                             \
            _Pragma("unroll")                                                   \
            for (int r = 0; r < 4; r++) acc[i][j][r] = 0.f;                     \
    const int arow = wm * 32 + (lane & 15);                                     \
    const int achk = lane >> 4;                                                 \
    const uint32_t s_a = (uint32_t)((arow >> 1) & 3);                           \
    const int brow2 = wn * 32 + (lane & 7) + ((lane >> 4) << 3);                \
    const int bchk = (lane >> 3) & 1;                                           \
    gemm_load_stage(sb,        Ahb, Alb, Bhb, Blb, 0,   tid);                   \
    gemm_load_stage(sb + STG3, Ahb, Alb, Bhb, Blb, BKC, tid);                   \
    const int NCH = GK / BKC;                                                   \
    for (int ch = 0; ch < NCH; ch++) {                                          \
        if (ch + 1 < NCH) { asm volatile("cp.async.wait_group 1;"); }           \
        else              { asm volatile("cp.async.wait_group 0;"); }           \
        __syncthreads();                                                        \
        if (ch + 2 < NCH)                                                       \
            gemm_load_stage(sb + ((ch + 2) % NSTG) * STG3, Ahb, Alb, Bhb, Blb,  \
                            (ch + 2) * BKC, tid);                               \
        const uint32_t st = sb + (ch % NSTG) * STG3;                            \
        _Pragma("unroll")                                                       \
        for (int ks = 0; ks < 2; ks++) {                                        \
            const uint32_t kc = (uint32_t)(ks * 2);                             \
            uint32_t af[2][4], bf[4][2], bt[4][2];                              \
            _Pragma("unroll")                                                   \
            for (int mt = 0; mt < 2; mt++) {                                    \
                uint32_t ad = st + (uint32_t)((arow + mt * 16) * 64) + (((kc + achk) ^ s_a) << 4); \
                ldm_x4(af[mt][0], af[mt][1], af[mt][2], af[mt][3], ad);         \
            }                                                                   \
            _Pragma("unroll")                                                   \
            for (int np = 0; np < 2; np++) {                                    \
                int rr = brow2 + np * 16;                                       \
                uint32_t bd = st + 2 * ARR_A + (uint32_t)(rr * 64) + (((kc + bchk) ^ ((rr >> 1) & 3)) << 4); \
                ldm_x4(bf[np * 2][0], bf[np * 2][1], bf[np * 2 + 1][0], bf[np * 2 + 1][1], bd); \
            }                                                                   \
            _Pragma("unroll")                                                   \
            for (int mt = 0; mt < 2; mt++)                                      \
                _Pragma("unroll")                                               \
                for (int nt = 0; nt < 4; nt++) mma16816(acc[mt][nt], af[mt], bf[nt]); \
            _Pragma("unroll")                                                   \
            for (int np = 0; np < 2; np++) {                                    \
                int rr = brow2 + np * 16;                                       \
                uint32_t bd = st + 2 * ARR_A + ARR_B + (uint32_t)(rr * 64) + (((kc + bchk) ^ ((rr >> 1) & 3)) << 4); \
                ldm_x4(bt[np * 2][0], bt[np * 2][1], bt[np * 2 + 1][0], bt[np * 2 + 1][1], bd); \
            }                                                                   \
            _Pragma("unroll")                                                   \
            for (int mt = 0; mt < 2; mt++)                                      \
                _Pragma("unroll")                                               \
                for (int nt = 0; nt < 4; nt++) mma16816(acc[mt][nt], af[mt], bt[nt]); \
            _Pragma("unroll")                                                   \
            for (int mt = 0; mt < 2; mt++) {                                    \
                uint32_t ad = st + ARR_A + (uint32_t)((arow + mt * 16) * 64) + (((kc + achk) ^ s_a) << 4); \
                ldm_x4(af[mt][0], af[mt][1], af[mt][2], af[mt][3], ad);         \
            }                                                                   \
            _Pragma("unroll")                                                   \
            for (int mt = 0; mt < 2; mt++)                                      \
                _Pragma("unroll")                                               \
                for (int nt = 0; nt < 4; nt++) mma16816(acc[mt][nt], af[mt], bf[nt]); \
        }                                                                       \
        __syncthreads();                                                        \
    }

// GEMM2: fp32 C output
__global__ __launch_bounds__(256, 3) void gemm_bf16x3(
    const __nv_bfloat16* __restrict__ Ah, const __nv_bfloat16* __restrict__ Al,
    const __nv_bfloat16* __restrict__ Bh, const __nv_bfloat16* __restrict__ Bl,
    float* __restrict__ C, int N)
{
    GEMM_MAIN(acc, Ah, Al, Bh, Bl)
    const int mrow = m0 + wm * 32 + (lane >> 2);
    const int ncol = n0 + wn * 32 + (lane & 3) * 2;
    #pragma unroll
    for (int mt = 0; mt < 2; mt++)
        #pragma unroll
        for (int nt = 0; nt < 4; nt++) {
            float* c0 = C + (size_t)(mrow + mt * 16) * N + ncol + nt * 8;
            *(float2*)c0 = make_float2(acc[mt][nt][0], acc[mt][nt][1]);
            float* c1 = c0 + (size_t)8 * N;
            *(float2*)c1 = make_float2(acc[mt][nt][2], acc[mt][nt][3]);
        }
}

// GEMM1: N=3072 fixed; epilogue splits into q(scaled)/k/v bf16 hi/lo
__global__ __launch_bounds__(256, 3) void gemm_qkv(
    const __nv_bfloat16* __restrict__ Ah, const __nv_bfloat16* __restrict__ Al,
    const __nv_bfloat16* __restrict__ Bh, const __nv_bfloat16* __restrict__ Bl,
    __nv_bfloat16* __restrict__ qh, __nv_bfloat16* __restrict__ ql,
    __nv_bfloat16* __restrict__ kh, __nv_bfloat16* __restrict__ kl,
    __nv_bfloat16* __restrict__ vh, __nv_bfloat16* __restrict__ vl)
{
    GEMM_MAIN(acc, Ah, Al, Bh, Bl)
    const int region = n0 >> 10;
    __nv_bfloat16 *oh, *ol;
    float sc;
    if (region == 0)      { oh = qh; ol = ql; sc = 0.125f; }
    else if (region == 1) { oh = kh; ol = kl; sc = 1.f; }
    else                  { oh = vh; ol = vl; sc = 1.f; }
    const int mrow = m0 + wm * 32 + (lane >> 2);
    const int colr = (n0 & 1023) + wn * 32 + (lane & 3) * 2;
    #pragma unroll
    for (int mt = 0; mt < 2; mt++)
        #pragma unroll
        for (int nt = 0; nt < 4; nt++) {
            size_t o0 = (size_t)(mrow + mt * 16) * CC + colr + nt * 8;
            uint32_t wh, wl;
            split_pair(acc[mt][nt][0] * sc, acc[mt][nt][1] * sc, wh, wl);
            *(uint32_t*)(oh + o0) = wh;
            *(uint32_t*)(ol + o0) = wl;
            size_t o1 = o0 + (size_t)8 * CC;
            split_pair(acc[mt][nt][2] * sc, acc[mt][nt][3] * sc, wh, wl);
            *(uint32_t*)(oh + o1) = wh;
            *(uint32_t*)(ol + o1) = wl;
        }
}

// ---------------- fp32 selection-score path ---------------------------------
__global__ __launch_bounds__(256) void qlast_kernel(
    const float* __restrict__ x, const float* __restrict__ Wa,
    float* __restrict__ qlast)
{
    const int b = blockIdx.x >> 4, h = blockIdx.x & 15;
    const int tid = threadIdx.x;
    __shared__ float xs[CC];
    __shared__ float red[4][64];
    for (int c = tid; c < CC; c += 256)
        xs[c] = x[((size_t)b * TT + (TT - 1)) * CC + c];
    __syncthreads();
    const int col = h * HD + (tid & 63);
    const int q = tid >> 6;
    float s = 0.f;
    #pragma unroll 4
    for (int c = q * 256; c < q * 256 + 256; c++)
        s += xs[c] * Wa[(size_t)c * (3 * CC) + col];
    red[q][tid & 63] = s;
    __syncthreads();
    if (tid < 64)
        qlast[(b * NH + h) * HD + tid] = red[0][tid] + red[1][tid] + red[2][tid] + red[3][tid];
}

__global__ __launch_bounds__(256) void uproj_kernel(
    const float* __restrict__ Wa, const float* __restrict__ qlast,
    float* __restrict__ u)
{
    const int b = blockIdx.x;
    const int c = blockIdx.y * 16 + (threadIdx.x >> 4);
    const int h = threadIdx.x & 15;
    __shared__ float qs[CC];
    for (int i = threadIdx.x; i < CC; i += 256) qs[i] = qlast[b * CC + i];
    __syncthreads();
    const float* wrow = Wa + (size_t)c * (3 * CC) + CC + h * HD;
    const float* qh = qs + h * HD;
    float s = 0.f;
    #pragma unroll
    for (int d = 0; d < HD; d++) s += wrow[d] * qh[d];
    u[((size_t)b * CC + c) * NH + h] = s;
}

#define SC_TR 32
#define SC_PAD 129

__global__ __launch_bounds__(128) void scores_kernel(
    const float* __restrict__ x, const float* __restrict__ u,
    float* __restrict__ last)
{
    const int b = blockIdx.x;
    const int t0 = blockIdx.y * SC_TR;
    const int tid = threadIdx.x;
    const int tloc = tid & 31;
    const int hg = tid >> 5;

    __shared__ float xs[SC_TR][SC_PAD];
    __shared__ float us[128][NH];

    float4 acc = make_float4(0.f, 0.f, 0.f, 0.f);

    for (int c0 = 0; c0 < CC; c0 += 128) {
        __syncthreads();
        #pragma unroll
        for (int it = 0; it < 8; it++) {
            int flat = it * 128 + tid;
            int r = flat >> 5;
            int c4 = flat & 31;
            float4 v = *(const float4*)(x + ((size_t)(b * TT + t0 + r)) * CC + c0 + c4 * 4);
            xs[r][c4 * 4 + 0] = v.x; xs[r][c4 * 4 + 1] = v.y;
            xs[r][c4 * 4 + 2] = v.z; xs[r][c4 * 4 + 3] = v.w;
        }
        #pragma unroll
        for (int it = 0; it < 4; it++) {
            int flat = it * 128 + tid;
            int ci = flat >> 2;
            int h4 = flat & 3;
            float4 v = *(const float4*)(u + ((size_t)(b * CC + c0 + ci)) * NH + h4 * 4);
            *(float4*)&us[ci][h4 * 4] = v;
        }
        __syncthreads();

        #pragma unroll 4
        for (int ci = 0; ci < 128; ci++) {
            float xv = xs[tloc][ci];
            float4 uu = *(const float4*)&us[ci][hg * 4];
            acc.x += xv * uu.x; acc.y += xv * uu.y;
            acc.z += xv * uu.z; acc.w += xv * uu.w;
        }
    }

    const int t = t0 + tloc;
    last[(b * NH + hg * 4 + 0) * TT + t] = acc.x * 0.125f;
    last[(b * NH + hg * 4 + 1) * TT + t] = acc.y * 0.125f;
    last[(b * NH + hg * 4 + 2) * TT + t] = acc.z * 0.125f;
    last[(b * NH + hg * 4 + 3) * TT + t] = acc.w * 0.125f;
}

// ---------------- top-k set selection via bitonic sort ---------------------
__global__ __launch_bounds__(512) void topk_kernel(const float* __restrict__ last,
                                                   int* __restrict__ idxout)
{
    __shared__ unsigned long long s[TT];
    const int bh = blockIdx.x;
    const int tid = threadIdx.x;

    for (int t = tid; t < TT; t += 512) {
        unsigned u;
        if (t >= NONREC) {
            u = 0xFFFFFFFFu;
        } else {
            u = __float_as_uint(last[bh * TT + t]);
            u = (u & 0x80000000u) ? ~u : (u | 0x80000000u);
        }
        s[t] = ((unsigned long long)u << 32) | (unsigned)t;
    }
    __syncthreads();

    for (int k = 2; k <= TT; k <<= 1) {
        for (int j = k >> 1; j > 0; j >>= 1) {
            for (int i = tid; i < TT; i += 512) {
                int ix = i ^ j;
                if (ix > i) {
                    bool desc = ((i & k) == 0);
                    unsigned long long a = s[i], b = s[ix];
                    bool sw = desc ? (a < b) : (a > b);
                    if (sw) { s[i] = b; s[ix] = a; }
                }
            }
            __syncthreads();
        }
    }
    for (int i = tid; i < KKEEP; i += 512)
        idxout[bh * KKEEP + i] = (int)(s[i] & 0xFFFFFFFFu);
}

// ---------------- mma-based pruned attention --------------------------------
#define ASMEM (32768 + 2 * 32768)        // 98304

__device__ __forceinline__ void attn_kv_prefetch(
    char* smp, uint32_t sb, uint32_t stgoff,
    const __nv_bfloat16* kh, const __nv_bfloat16* kl,
    const __nv_bfloat16* vh, const __nv_bfloat16* vl,
    const int* idxp, int b, int hoff, int c0, int cn, int tid)
{
    for (int i = tid; i < 64 * 8; i += 128) {
        int r = i >> 3, c = i & 7;
        uint32_t off = (uint32_t)(r * 128 + (((c ^ (r & 7))) << 4));
        if (r < cn) {
            int kt = idxp[c0 + r];
            size_t g = ((size_t)(b * TT + kt)) * CC + hoff + c * 8;
            cp_async16(sb + stgoff + off,         kh + g);
            cp_async16(sb + stgoff + 8192 + off,  kl + g);
            cp_async16(sb + stgoff + 16384 + off, vh + g);
            cp_async16(sb + stgoff + 24576 + off, vl + g);
        } else {
            uint4 z = make_uint4(0, 0, 0, 0);
            *(uint4*)(smp + stgoff + off) = z;
            *(uint4*)(smp + stgoff + 8192 + off) = z;
            *(uint4*)(smp + stgoff + 16384 + off) = z;
            *(uint4*)(smp + stgoff + 24576 + off) = z;
        }
    }
    cp_commit();
}

__global__ __launch_bounds__(128) void attn_kernel(
    const __nv_bfloat16* __restrict__ qh, const __nv_bfloat16* __restrict__ ql,
    const __nv_bfloat16* __restrict__ kh, const __nv_bfloat16* __restrict__ kl,
    const __nv_bfloat16* __restrict__ vh, const __nv_bfloat16* __restrict__ vl,
    const int* __restrict__ idx,
    __nv_bfloat16* __restrict__ yh, __nv_bfloat16* __restrict__ yl)
{
    extern __shared__ char asmem[];
    const uint32_t sb = smem_u32(asmem);
    const int tid = threadIdx.x;
    const int wq = tid >> 5;
    const int lane = tid & 31;
    const int bh = blockIdx.x;
    const int b = bh >> 4, h = bh & 15;
    const int qt0 = blockIdx.y * 128;
    const int hoff = h * HD;
    const int* idxp = idx + bh * KKEEP;

    for (int i = tid; i < 128 * 8; i += 128) {
        int r = i >> 3, c = i & 7;
        size_t g = ((size_t)(b * TT + qt0 + r)) * CC + hoff + c * 8;
        uint32_t off = (uint32_t)(r * 128 + (((c ^ (r & 7))) << 4));
        cp_async16(sb + off, qh + g);
        cp_async16(sb + 16384 + off, ql + g);
    }
    cp_commit();

    const int nch = (KKEEP + 63) / 64;   // 7
    attn_kv_prefetch(asmem, sb, 32768, kh, kl, vh, vl, idxp, b, hoff, 0, 64, tid);

    float o[2][8][4];
    #pragma unroll
    for (int mt = 0; mt < 2; mt++)
        #pragma unroll
        for (int dt = 0; dt < 8; dt++)
            #pragma unroll
            for (int r = 0; r < 4; r++) o[mt][dt][r] = 0.f;
    float la[4] = {0.f, 0.f, 0.f, 0.f};

    for (int ch = 0; ch < nch; ch++) {
        if (ch + 1 < nch) {
            int c1 = (ch + 1) * 64;
            attn_kv_prefetch(asmem, sb, 32768 + ((ch + 1) & 1) * 32768,
                             kh, kl, vh, vl, idxp, b, hoff, c1,
                             min(64, KKEEP - c1), tid);
            asm volatile("cp.async.wait_group 1;");
        } else {
            asm volatile("cp.async.wait_group 0;");
        }
        __syncthreads();

        const uint32_t stg = sb + 32768 + (uint32_t)((ch & 1) * 32768);

        #pragma unroll
        for (int mt = 0; mt < 2; mt++) {
            uint32_t ah[4][4], al[4][4];
            {
                int row = wq * 32 + mt * 16 + (lane & 15);
                #pragma unroll
                for (int kd = 0; kd < 4; kd++) {
                    int chv = kd * 2 + (lane >> 4);
                    uint32_t ad = (uint32_t)(row * 128 + (((chv ^ (row & 7))) << 4));
                    ldm_x4(ah[kd][0], ah[kd][1], ah[kd][2], ah[kd][3], sb + ad);
                    ldm_x4(al[kd][0], al[kd][1], al[kd][2], al[kd][3], sb + 16384 + ad);
                }
            }
            #pragma unroll
            for (int ntp = 0; ntp < 4; ntp++) {
                float s0[4] = {0.f, 0.f, 0.f, 0.f};
                float s1[4] = {0.f, 0.f, 0.f, 0.f};
                {
                    int rr = ntp * 16 + (lane & 7) + ((lane >> 4) << 3);
                    #pragma unroll
                    for (int kd = 0; kd < 4; kd++) {
                        int chv = kd * 2 + ((lane >> 3) & 1);
                        uint32_t ad = (uint32_t)(rr * 128 + (((chv ^ (rr & 7))) << 4));
                        uint32_t bh4[4], bl4[4];
                        ldm_x4(bh4[0], bh4[1], bh4[2], bh4[3], stg + ad);
                        ldm_x4(bl4[0], bl4[1], bl4[2], bl4[3], stg + 8192 + ad);
                        mma16816(s0, ah[kd], &bh4[0]);
                        mma16816(s0, ah[kd], &bl4[0]);
                        mma16816(s0, al[kd], &bh4[0]);
                        mma16816(s1, ah[kd], &bh4[2]);
                        mma16816(s1, ah[kd], &bl4[2]);
                        mma16816(s1, al[kd], &bh4[2]);
                    }
                }
                const int kb = ch * 64 + ntp * 16 + 2 * (lane & 3);
                float p0 = (kb     < KKEEP) ? __expf(s0[0]) : 0.f;
                float p1 = (kb + 1 < KKEEP) ? __expf(s0[1]) : 0.f;
                float p2 = (kb     < KKEEP) ? __expf(s0[2]) : 0.f;
                float p3 = (kb + 1 < KKEEP) ? __expf(s0[3]) : 0.f;
                float p4 = (kb + 8 < KKEEP) ? __expf(s1[0]) : 0.f;
                float p5 = (kb + 9 < KKEEP) ? __expf(s1[1]) : 0.f;
                float p6 = (kb + 8 < KKEEP) ? __expf(s1[2]) : 0.f;
                float p7 = (kb + 9 < KKEEP) ? __expf(s1[3]) : 0.f;
                la[mt * 2 + 0] += (p0 + p1) + (p4 + p5);
                la[mt * 2 + 1] += (p2 + p3) + (p6 + p7);
                uint32_t phi[4], plo[4];
                {
                    float vs[8] = {p0, p1, p2, p3, p4, p5, p6, p7};
                    #pragma unroll
                    for (int j = 0; j < 4; j++) {
                        __nv_bfloat16 ha = __float2bfloat16(vs[2 * j]);
                        __nv_bfloat16 hb = __float2bfloat16(vs[2 * j + 1]);
                        __nv_bfloat162 th(ha, hb);
                        phi[j] = *(uint32_t*)&th;
                        __nv_bfloat162 tl(__float2bfloat16(vs[2 * j] - __bfloat162float(ha)),
                                          __float2bfloat16(vs[2 * j + 1] - __bfloat162float(hb)));
                        plo[j] = *(uint32_t*)&tl;
                    }
                }
                #pragma unroll
                for (int dp = 0; dp < 4; dp++) {
                    int g = lane >> 3;
                    int krow = ntp * 16 + ((g & 1) << 3) + (lane & 7);
                    int chv = dp * 2 + (g >> 1);
                    uint32_t av = (uint32_t)(krow * 128 + (((chv ^ (krow & 7))) << 4));
                    uint32_t vbh[4], vbl[4];
                    ldm_x4t(vbh, stg + 16384 + av);
                    ldm_x4t(vbl, stg + 24576 + av);
                    mma16816(o[mt][dp * 2],     phi, &vbh[0]);
                    mma16816(o[mt][dp * 2],     plo, &vbh[0]);
                    mma16816(o[mt][dp * 2],     phi, &vbl[0]);
                    mma16816(o[mt][dp * 2 + 1], phi, &vbh[2]);
                    mma16816(o[mt][dp * 2 + 1], plo, &vbh[2]);
                    mma16816(o[mt][dp * 2 + 1], phi, &vbl[2]);
                }
            }
        }
        __syncthreads();
    }

    #pragma unroll
    for (int j = 0; j < 4; j++) {
        la[j] += __shfl_xor_sync(0xFFFFFFFFu, la[j], 1);
        la[j] += __shfl_xor_sync(0xFFFFFFFFu, la[j], 2);
        la[j] = 1.f / la[j];
    }

    #pragma unroll
    for (int mt = 0; mt < 2; mt++) {
        const int row0 = qt0 + wq * 32 + mt * 16 + (lane >> 2);
        #pragma unroll
        for (int dt = 0; dt < 8; dt++) {
            const int col = dt * 8 + 2 * (lane & 3);
            size_t a0 = ((size_t)(b * TT + row0)) * CC + hoff + col;
            uint32_t wh, wl;
            split_pair(o[mt][dt][0] * la[mt * 2], o[mt][dt][1] * la[mt * 2], wh, wl);
            *(uint32_t*)(yh + a0) = wh;
            *(uint32_t*)(yl + a0) = wl;
            size_t a1 = a0 + (size_t)8 * CC;
            split_pair(o[mt][dt][2] * la[mt * 2 + 1], o[mt][dt][3] * la[mt * 2 + 1], wh, wl);
            *(uint32_t*)(yh + a1) = wh;
            *(uint32_t*)(yl + a1) = wl;
        }
    }
}

// ---------------- launch ----------------------------------------------------
extern "C" void kernel_launch(void* const* d_in, const int* in_sizes, int n_in,
                              void* d_out, int out_size)
{
    const float* x  = (const float*)d_in[0];   // [4,1024,1024]
    const float* Wa = (const float*)d_in[1];   // [1024,3072]
    const float* Wp = (const float*)d_in[2];   // [1024,1024]
    float* out = (float*)d_out;                // [4,1024,1024]

    void* p;
    cudaGetSymbolAddress(&p, g_last);  float* last  = (float*)p;
    cudaGetSymbolAddress(&p, g_idx);   int*   idx   = (int*)p;
    cudaGetSymbolAddress(&p, g_qlast); float* qlast = (float*)p;
    cudaGetSymbolAddress(&p, g_u);     float* u     = (float*)p;
    cudaGetSymbolAddress(&p, g_xh);   __nv_bfloat16* xh  = (__nv_bfloat16*)p;
    cudaGetSymbolAddress(&p, g_xl);   __nv_bfloat16* xl  = (__nv_bfloat16*)p;
    cudaGetSymbolAddress(&p, g_wah);  __nv_bfloat16* wah = (__nv_bfloat16*)p;
    cudaGetSymbolAddress(&p, g_wal);  __nv_bfloat16* wal = (__nv_bfloat16*)p;
    cudaGetSymbolAddress(&p, g_wph);  __nv_bfloat16* wph = (__nv_bfloat16*)p;
    cudaGetSymbolAddress(&p, g_wpl);  __nv_bfloat16* wpl = (__nv_bfloat16*)p;
    cudaGetSymbolAddress(&p, g_yh);   __nv_bfloat16* yh  = (__nv_bfloat16*)p;
    cudaGetSymbolAddress(&p, g_yl);   __nv_bfloat16* yl  = (__nv_bfloat16*)p;
    cudaGetSymbolAddress(&p, g_qh);   __nv_bfloat16* qhp = (__nv_bfloat16*)p;
    cudaGetSymbolAddress(&p, g_ql);   __nv_bfloat16* qlp = (__nv_bfloat16*)p;
    cudaGetSymbolAddress(&p, g_kh);   __nv_bfloat16* khp = (__nv_bfloat16*)p;
    cudaGetSymbolAddress(&p, g_kl);   __nv_bfloat16* klp = (__nv_bfloat16*)p;
    cudaGetSymbolAddress(&p, g_vh);   __nv_bfloat16* vhp = (__nv_bfloat16*)p;
    cudaGetSymbolAddress(&p, g_vl);   __nv_bfloat16* vlp = (__nv_bfloat16*)p;

    cudaFuncSetAttribute(gemm_bf16x3, cudaFuncAttributeMaxDynamicSharedMemorySize, GSMEM);
    cudaFuncSetAttribute(gemm_qkv, cudaFuncAttributeMaxDynamicSharedMemorySize, GSMEM);
    cudaFuncSetAttribute(attn_kernel, cudaFuncAttributeMaxDynamicSharedMemorySize, ASMEM);

    // fork a side stream for the independent score path (capture-safe
    // fork/join via events; no device memory is allocated by these calls)
    cudaStream_t s2;
    cudaStreamCreateWithFlags(&s2, cudaStreamNonBlocking);
    cudaEvent_t eFork, eJoin;
    cudaEventCreateWithFlags(&eFork, cudaEventDisableTiming);
    cudaEventCreateWithFlags(&eJoin, cudaEventDisableTiming);

    cudaEventRecord(eFork, 0);
    cudaStreamWaitEvent(s2, eFork, 0);

    // side stream: fp32 selection-score chain (independent of prep/gemm)
    qlast_kernel<<<BB * NH, 256, 0, s2>>>(x, Wa, qlast);
    uproj_kernel<<<dim3(BB, CC / 16), 256, 0, s2>>>(Wa, qlast, u);
    scores_kernel<<<dim3(BB, TT / SC_TR), 128, 0, s2>>>(x, u, last);
    topk_kernel<<<BB * NH, 512, 0, s2>>>(last, idx);
    cudaEventRecord(eJoin, s2);

    // main stream: prep -> qkv GEMM
    prep_kernel<<<PREP_TOTAL, 256>>>(x, Wa, Wp, xh, xl, wah, wal, wph, wpl);
    gemm_qkv<<<dim3(3 * CC / 64, BB * TT / 128), 256, GSMEM>>>(
        xh, xl, wah, wal, qhp, qlp, khp, klp, vhp, vlp);

    // join: attn needs idx from the side stream
    cudaStreamWaitEvent(0, eJoin, 0);
    attn_kernel<<<dim3(BB * NH, TT / 128), 128, ASMEM>>>(
        qhp, qlp, khp, klp, vhp, vlp, idx, yh, yl);

    // out = y @ W_proj
    gemm_bf16x3<<<dim3(CC / 64, BB * TT / 128), 256, GSMEM>>>(yh, yl, wph, wpl, out, CC);
}